// round 8
// baseline (speedup 1.0000x reference)
#include <cuda_runtime.h>
#include <math.h>
#include <stdint.h>

#define CH    96
#define HH    192
#define WWI   192
#define HW    (HH*WWI)        // 36864
#define BATCH 4
#define NWIN_PER 576          // 24*24 windows per image
#define NWIN  (BATCH*NWIN_PER)
#define NTOK  64
#define NHEAD 6
#define HDIM  16
#define QS    100             // row stride for 64-row fp32 tiles
#define HS    196             // FFN hidden stride

// 56.6 MB each — static device scratch (no allocations allowed)
__device__ float g_imgA[BATCH*HW*CH];
__device__ float g_imgB[BATCH*HW*CH];
// pre-split tf32 (hi,lo) weights: sa1_wqkv | sa1_wproj | sa2_wqkv | sa2_wproj
//                                | ff1_w1 | ff1_w2 | ff2_w1 | ff2_w2
#define WS_SA1_QKV   0
#define WS_SA1_PROJ  27648
#define WS_SA2_QKV   36864
#define WS_SA2_PROJ  64512
#define WS_FF1_W1    73728
#define WS_FF1_W2    92160
#define WS_FF2_W1    110592
#define WS_FF2_W2    129024
__device__ float2 g_wsplit[147456];

// ---------------------------------------------------------------------------
// FMA-only exp. Valid for x <= 0 (softmax-shifted logits); clamps at -80.
// ---------------------------------------------------------------------------
__device__ __forceinline__ float fexp(float x) {
    x = fmaxf(x, -80.0f);
    const float L2E = 1.4426950408889634f;
    float t = fmaf(x, L2E, 12582912.0f);
    float n = t - 12582912.0f;
    float f = fmaf(x, L2E, -n);
    float p = 1.5403530393381608e-4f;
    p = fmaf(p, f, 1.3333558146428443e-3f);
    p = fmaf(p, f, 9.6181291076284772e-3f);
    p = fmaf(p, f, 5.5504108664821580e-2f);
    p = fmaf(p, f, 2.4022650695910072e-1f);
    p = fmaf(p, f, 6.9314718055994531e-1f);
    p = fmaf(p, f, 1.0f);
    int e = (int)n;
    float s = __int_as_float((127 + e) << 23);
    return p * s;
}

// ---------------------------------------------------------------------------
// tf32 MMA helpers (3xTF32 split for near-fp32 accuracy)
// ---------------------------------------------------------------------------
__device__ __forceinline__ uint32_t f2tf(float x) {
    uint32_t r; asm("cvt.rna.tf32.f32 %0, %1;" : "=r"(r) : "f"(x)); return r;
}
__device__ __forceinline__ void tfsplit(float x, uint32_t& h, uint32_t& l) {
    h = f2tf(x);
    l = f2tf(x - __uint_as_float(h));
}
__device__ __forceinline__ void mma_m16n8k8(float4& d,
    uint32_t a0, uint32_t a1, uint32_t a2, uint32_t a3,
    uint32_t b0, uint32_t b1)
{
    asm volatile("mma.sync.aligned.m16n8k8.row.col.f32.tf32.tf32.f32 "
                 "{%0,%1,%2,%3},{%4,%5,%6,%7},{%8,%9},{%0,%1,%2,%3};"
                 : "+f"(d.x), "+f"(d.y), "+f"(d.z), "+f"(d.w)
                 : "r"(a0), "r"(a1), "r"(a2), "r"(a3), "r"(b0), "r"(b1));
}

// weight pre-split kernel: x -> (tf32_hi, tf32_lo)
__global__ void split_weights_kernel(const float* __restrict__ src,
                                     float2* __restrict__ dst, int n) {
    int i = blockIdx.x * 256 + threadIdx.x;
    if (i < n) {
        float x = src[i];
        float hf = __uint_as_float(f2tf(x));
        float lf = __uint_as_float(f2tf(x - hf));
        dst[i] = make_float2(hf, lf);
    }
}

// C = A(64 x K, smem, row stride lda) @ B(K x N, pre-split gmem, stride ldb)
// warp computes one 16-row m-tile x NT 8-col n-tiles. mg=lane>>2, mt=lane&3.
template<int NT, int KSTEPS>
__device__ __forceinline__ void mma_gemm(
    float4* acc, const float* A, int lda, int m0,
    const float2* __restrict__ B, int ldb, int n0, int mg, int mt)
{
    #pragma unroll 2
    for (int ks = 0; ks < KSTEPS; ks++) {
        const int k0 = ks * 8;
        uint32_t ah[4], al[4];
        tfsplit(A[(m0 + mg) * lda + k0 + mt],         ah[0], al[0]);
        tfsplit(A[(m0 + mg + 8) * lda + k0 + mt],     ah[1], al[1]);
        tfsplit(A[(m0 + mg) * lda + k0 + mt + 4],     ah[2], al[2]);
        tfsplit(A[(m0 + mg + 8) * lda + k0 + mt + 4], ah[3], al[3]);
        #pragma unroll
        for (int j = 0; j < NT; j++) {
            float2 w0 = __ldg(&B[(k0 + mt) * ldb + n0 + j * 8 + mg]);
            float2 w1 = __ldg(&B[(k0 + mt + 4) * ldb + n0 + j * 8 + mg]);
            uint32_t bh0 = __float_as_uint(w0.x), bl0 = __float_as_uint(w0.y);
            uint32_t bh1 = __float_as_uint(w1.x), bl1 = __float_as_uint(w1.y);
            mma_m16n8k8(acc[j], ah[0], ah[1], ah[2], ah[3], bh0, bh1);
            mma_m16n8k8(acc[j], ah[0], ah[1], ah[2], ah[3], bl0, bl1);
            mma_m16n8k8(acc[j], al[0], al[1], al[2], al[3], bh0, bh1);
        }
    }
}

// ---------------------------------------------------------------------------
// Transposes: [B,C,H,W] <-> [B,HW,C]
// ---------------------------------------------------------------------------
__global__ void transpose_in_kernel(const float* __restrict__ x, float* __restrict__ img) {
    __shared__ float tile[32][33];
    int b = blockIdx.z;
    int hw0 = blockIdx.x * 32, c0 = blockIdx.y * 32;
    const float* src = x + (size_t)b * CH * HW;
    float* dst = img + (size_t)b * HW * CH;
    #pragma unroll
    for (int i = threadIdx.y; i < 32; i += 8)
        tile[i][threadIdx.x] = src[(size_t)(c0 + i) * HW + hw0 + threadIdx.x];
    __syncthreads();
    #pragma unroll
    for (int i = threadIdx.y; i < 32; i += 8)
        dst[(size_t)(hw0 + i) * CH + c0 + threadIdx.x] = tile[threadIdx.x][i];
}

__global__ void transpose_out_kernel(const float* __restrict__ img, float* __restrict__ x) {
    __shared__ float tile[32][33];
    int b = blockIdx.z;
    int hw0 = blockIdx.x * 32, c0 = blockIdx.y * 32;
    const float* src = img + (size_t)b * HW * CH;
    float* dst = x + (size_t)b * CH * HW;
    #pragma unroll
    for (int i = threadIdx.y; i < 32; i += 8)
        tile[i][threadIdx.x] = src[(size_t)(hw0 + i) * CH + c0 + threadIdx.x];
    __syncthreads();
    #pragma unroll
    for (int i = threadIdx.y; i < 32; i += 8)
        dst[(size_t)(c0 + i) * HW + hw0 + threadIdx.x] = tile[threadIdx.x][i];
}

// ---------------------------------------------------------------------------
// Fused window attention: GEMMs on tensor cores (3xTF32, pre-split weights),
// heads SIMT.
// smem floats: Xs/Qb/Kb/Vb/Ob 5*6400 | S 2*64*68 | Tb 1360 | stats 128 |
//              Cnt 64  = 42,256 floats = 169,024 B
// ---------------------------------------------------------------------------
#define ATTN_SMEM (42256 * 4)

template<int SHIFTED>
__global__ void __launch_bounds__(512, 1) attn_kernel(
    const float* __restrict__ in, float* __restrict__ out,
    const float2* __restrict__ wqkv2, const float* __restrict__ bqkv,
    const float* __restrict__ table, const float2* __restrict__ wproj2,
    const float* __restrict__ bproj, const float* __restrict__ gam,
    const float* __restrict__ beta)
{
    extern __shared__ float sm[];
    float* Xs    = sm;                 // 64 x QS
    float* Qb    = Xs + 64*QS;         // 64 x QS (later reused as Y)
    float* Kb    = Qb + 64*QS;
    float* Vb    = Kb + 64*QS;
    float* Ob    = Vb + 64*QS;
    float* S     = Ob + 64*QS;         // 2 x 64 x 68
    float* Tb    = S + 2*64*68;        // 1360 (1350 used)
    float* stats = Tb + 1360;          // 128
    int*   Cnt   = (int*)(stats + 128);// 64

    const int tid = threadIdx.x;
    const int wid = blockIdx.x;
    const int b  = wid / NWIN_PER;
    const int wl = wid - b * NWIN_PER;
    const int wr = wl / 24, wc = wl - (wl / 24) * 24;
    const float* src = in  + (size_t)b * HW * CH;
    float*       dst = out + (size_t)b * HW * CH;

    // ---- gather window tokens + stage table + region ids ----
    for (int idx = tid; idx < NTOK * CH; idx += 512) {
        int t = idx / CH, c = idx - t * CH;
        int r = t >> 3, cl = t & 7;
        int h = wr * 8 + r, w = wc * 8 + cl;
        if (SHIFTED) { h += 4; if (h >= HH) h -= HH; w += 4; if (w >= WWI) w -= WWI; }
        Xs[t * QS + c] = src[(h * WWI + w) * CH + c];
    }
    for (int idx = tid; idx < 1350; idx += 512) Tb[idx] = table[idx];
    if (SHIFTED && tid < 64) {
        int ri = tid >> 3, ci = tid & 7;
        Cnt[tid] = ((wr == 23) ? (ri < 4 ? 1 : 2) : 0) * 3
                 + ((wc == 23) ? (ci < 4 ? 1 : 2) : 0);
    }
    __syncthreads();

    const int wg = tid >> 5, tx = tid & 31;   // 16 warps
    const int mg = tx >> 2, mt = tx & 3;      // mma lane coords
    const int m0 = (wg & 3) * 16;             // m-tile
    const int nch = wg >> 2;                  // n-chunk

    // ---- QKV GEMM: 64x288x96 via mma; warp covers 16 rows x 72 cols ----
    {
        float4 acc[9];
        #pragma unroll
        for (int j = 0; j < 9; j++) {
            int c = nch * 72 + j * 8 + 2 * mt;
            float b0 = __ldg(&bqkv[c]), b1 = __ldg(&bqkv[c + 1]);
            acc[j].x = b0; acc[j].y = b1; acc[j].z = b0; acc[j].w = b1;
        }
        mma_gemm<9, 12>(acc, Xs, QS, m0, wqkv2, 288, nch * 72, mg, mt);
        #pragma unroll
        for (int j = 0; j < 9; j++) {
            int c = nch * 72 + j * 8 + 2 * mt;
            int rA = m0 + mg, rB = rA + 8;
            float v[4] = {acc[j].x, acc[j].y, acc[j].z, acc[j].w};
            int   rr[4] = {rA, rA, rB, rB};
            int   cc[4] = {c, c + 1, c, c + 1};
            #pragma unroll
            for (int e = 0; e < 4; e++) {
                int col = cc[e];
                if (col < 96)       Qb[rr[e] * QS + col]         = v[e];
                else if (col < 192) Kb[rr[e] * QS + (col - 96)]  = v[e];
                else                Vb[rr[e] * QS + (col - 192)] = v[e];
            }
        }
    }
    __syncthreads();

    // ---- heads: 2 in flight (warps 0-7 -> head 2it, warps 8-15 -> 2it+1) ----
    const int hg   = wg >> 3;          // head group
    const int rowg = wg & 7;
    const int i0   = rowg * 8;
    int cni[8], cj0 = 0, cj1 = 0;
    if (SHIFTED) {
        cj0 = Cnt[tx]; cj1 = Cnt[tx + 32];
        #pragma unroll
        for (int r = 0; r < 8; r++) cni[r] = Cnt[i0 + r];
    }
    for (int it = 0; it < 3; it++) {
        const int hd = it * 2 + hg;
        float* Sg = S + hg * 64 * 68;

        float sc[8][2];
        #pragma unroll
        for (int r = 0; r < 8; r++) { sc[r][0] = 0.f; sc[r][1] = 0.f; }
        #pragma unroll
        for (int d4 = 0; d4 < 4; d4++) {
            float4 k0 = *(const float4*)&Kb[tx * QS + hd * 16 + d4 * 4];
            float4 k1 = *(const float4*)&Kb[(tx + 32) * QS + hd * 16 + d4 * 4];
            #pragma unroll
            for (int r = 0; r < 8; r++) {
                float4 q = *(const float4*)&Qb[(i0 + r) * QS + hd * 16 + d4 * 4];
                sc[r][0] = fmaf(q.x, k0.x, fmaf(q.y, k0.y, fmaf(q.z, k0.z, fmaf(q.w, k0.w, sc[r][0]))));
                sc[r][1] = fmaf(q.x, k1.x, fmaf(q.y, k1.y, fmaf(q.z, k1.z, fmaf(q.w, k1.w, sc[r][1]))));
            }
        }
        #pragma unroll
        for (int r = 0; r < 8; r++) {
            int i = i0 + r;
            int ri = i >> 3, ci = i & 7;
            float v[2];
            #pragma unroll
            for (int cj = 0; cj < 2; cj++) {
                int j = tx + 32 * cj;
                int rj = j >> 3, cjj = j & 7;
                int ridx = (ri - rj + 7) * 15 + (ci - cjj + 7);
                float bias = Tb[ridx * 6 + hd];
                if (SHIFTED) {
                    int cjv = cj ? cj1 : cj0;
                    if (cni[r] != cjv) bias -= 100.f;
                }
                v[cj] = fmaf(sc[r][cj], 0.25f, bias);
            }
            float mx = fmaxf(v[0], v[1]);
            #pragma unroll
            for (int o = 16; o > 0; o >>= 1) mx = fmaxf(mx, __shfl_xor_sync(0xffffffffu, mx, o));
            float e0 = fexp(v[0] - mx), e1 = fexp(v[1] - mx);
            float ssum = e0 + e1;
            #pragma unroll
            for (int o = 16; o > 0; o >>= 1) ssum += __shfl_xor_sync(0xffffffffu, ssum, o);
            float inv = 1.0f / ssum;
            Sg[i * 68 + tx]      = e0 * inv;
            Sg[i * 68 + tx + 32] = e1 * inv;
        }
        __syncthreads();

        // attn @ V : thread = (row, d4 group) within its head's 256 threads
        {
            int gtid = tid & 255;
            int d4   = gtid & 3;
            int row  = gtid >> 2;
            float4 o = make_float4(0.f, 0.f, 0.f, 0.f);
            #pragma unroll 4
            for (int j4 = 0; j4 < 16; j4++) {
                float4 s4 = *(const float4*)&Sg[row * 68 + j4 * 4];
                #pragma unroll
                for (int jj = 0; jj < 4; jj++) {
                    float sj = (jj == 0) ? s4.x : (jj == 1) ? s4.y : (jj == 2) ? s4.z : s4.w;
                    float4 v4 = *(const float4*)&Vb[(j4 * 4 + jj) * QS + hd * 16 + d4 * 4];
                    o.x = fmaf(sj, v4.x, o.x);
                    o.y = fmaf(sj, v4.y, o.y);
                    o.z = fmaf(sj, v4.z, o.z);
                    o.w = fmaf(sj, v4.w, o.w);
                }
            }
            *(float4*)&Ob[row * QS + hd * 16 + d4 * 4] = o;
        }
        __syncthreads();
    }

    // ---- proj GEMM 64x96x96 via mma + residual ----
    float* Y = Qb;  // reuse
    {
        float4 acc[3];
        #pragma unroll
        for (int j = 0; j < 3; j++) {
            int c = nch * 24 + j * 8 + 2 * mt;
            float b0 = __ldg(&bproj[c]), b1 = __ldg(&bproj[c + 1]);
            acc[j].x = b0; acc[j].y = b1; acc[j].z = b0; acc[j].w = b1;
        }
        mma_gemm<3, 12>(acc, Ob, QS, m0, wproj2, 96, nch * 24, mg, mt);
        #pragma unroll
        for (int j = 0; j < 3; j++) {
            int c = nch * 24 + j * 8 + 2 * mt;
            int rA = m0 + mg, rB = rA + 8;
            Y[rA * QS + c]     = acc[j].x + Xs[rA * QS + c];
            Y[rA * QS + c + 1] = acc[j].y + Xs[rA * QS + c + 1];
            Y[rB * QS + c]     = acc[j].z + Xs[rB * QS + c];
            Y[rB * QS + c + 1] = acc[j].w + Xs[rB * QS + c + 1];
        }
    }
    __syncthreads();

    // ---- LayerNorm: 8 threads per row, single pass ----
    {
        int row = tid >> 3, l8 = tid & 7;
        float s = 0.f, s2 = 0.f;
        #pragma unroll
        for (int q = 0; q < 3; q++) {
            float4 y = *(const float4*)&Y[row * QS + l8 * 12 + q * 4];
            s += (y.x + y.y) + (y.z + y.w);
            s2 = fmaf(y.x, y.x, fmaf(y.y, y.y, fmaf(y.z, y.z, fmaf(y.w, y.w, s2))));
        }
        #pragma unroll
        for (int o = 4; o > 0; o >>= 1) {
            s  += __shfl_xor_sync(0xffffffffu, s,  o);
            s2 += __shfl_xor_sync(0xffffffffu, s2, o);
        }
        if (l8 == 0) {
            float mean = s * (1.0f / 96.0f);
            float var  = fmaf(-mean, mean, s2 * (1.0f / 96.0f));
            stats[row]      = mean;
            stats[64 + row] = rsqrtf(var + 1e-5f);
        }
    }
    __syncthreads();

    // ---- scatter (same coords as gather: roll cancels) ----
    for (int idx = tid; idx < NTOK * CH; idx += 512) {
        int t = idx / CH, c = idx - t * CH;
        int r = t >> 3, cl = t & 7;
        int h = wr * 8 + r, w = wc * 8 + cl;
        if (SHIFTED) { h += 4; if (h >= HH) h -= HH; w += 4; if (w >= WWI) w -= WWI; }
        float yv = (Y[t * QS + c] - stats[t]) * stats[64 + t];
        dst[(h * WWI + w) * CH + c] = fmaf(yv, gam[c], beta[c]);
    }
}

// ---------------------------------------------------------------------------
// Fused FFN: both GEMMs on tensor cores (3xTF32, pre-split weights).
// smem floats: Xs 64x100 | H1 64x196 | Y 64x100 | stats 128 = 25,472
// ---------------------------------------------------------------------------
#define FFN_SMEM (25472 * 4)

__global__ void __launch_bounds__(512, 1) ffn_kernel(
    const float* __restrict__ in, float* __restrict__ out,
    const float2* __restrict__ w12, const float* __restrict__ b1,
    const float2* __restrict__ w22, const float* __restrict__ b2,
    const float* __restrict__ gam, const float* __restrict__ beta)
{
    extern __shared__ float sm[];
    float* Xs    = sm;                  // 64 x QS
    float* H1    = Xs + 64*QS;          // 64 x HS
    float* Y     = H1 + 64*HS;          // 64 x QS
    float* stats = Y + 64*QS;

    const int tid = threadIdx.x;
    const size_t t0 = (size_t)blockIdx.x * 64;
    const float* src = in + t0 * CH;
    float*       dst = out + t0 * CH;

    for (int idx = tid; idx < 6144; idx += 512) {
        int t = idx / CH, c = idx - t * CH;
        Xs[t * QS + c] = src[idx];
    }
    __syncthreads();

    const int wg = tid >> 5, tx = tid & 31;
    const int mg = tx >> 2, mt = tx & 3;
    const int m0 = (wg & 3) * 16;
    const int nch = wg >> 2;

    // GEMM1: 64x192x96 + GELU -> H1
    {
        float4 acc[6];
        #pragma unroll
        for (int j = 0; j < 6; j++) {
            int c = nch * 48 + j * 8 + 2 * mt;
            float v0 = __ldg(&b1[c]), v1 = __ldg(&b1[c + 1]);
            acc[j].x = v0; acc[j].y = v1; acc[j].z = v0; acc[j].w = v1;
        }
        mma_gemm<6, 12>(acc, Xs, QS, m0, w12, 192, nch * 48, mg, mt);
        #pragma unroll
        for (int j = 0; j < 6; j++) {
            int c = nch * 48 + j * 8 + 2 * mt;
            int rA = m0 + mg, rB = rA + 8;
            float v[4] = {acc[j].x, acc[j].y, acc[j].z, acc[j].w};
            int   rr[4] = {rA, rA, rB, rB};
            int   cc[4] = {c, c + 1, c, c + 1};
            #pragma unroll
            for (int e = 0; e < 4; e++) {
                float x = v[e];
                H1[rr[e] * HS + cc[e]] = 0.5f * x * (1.0f + erff(x * 0.70710678118654752f));
            }
        }
    }
    __syncthreads();

    // GEMM2: 64x96x192 + residual -> Y
    {
        float4 acc[3];
        #pragma unroll
        for (int j = 0; j < 3; j++) {
            int c = nch * 24 + j * 8 + 2 * mt;
            float v0 = __ldg(&b2[c]), v1 = __ldg(&b2[c + 1]);
            acc[j].x = v0; acc[j].y = v1; acc[j].z = v0; acc[j].w = v1;
        }
        mma_gemm<3, 24>(acc, H1, HS, m0, w22, 96, nch * 24, mg, mt);
        #pragma unroll
        for (int j = 0; j < 3; j++) {
            int c = nch * 24 + j * 8 + 2 * mt;
            int rA = m0 + mg, rB = rA + 8;
            Y[rA * QS + c]     = acc[j].x + Xs[rA * QS + c];
            Y[rA * QS + c + 1] = acc[j].y + Xs[rA * QS + c + 1];
            Y[rB * QS + c]     = acc[j].z + Xs[rB * QS + c];
            Y[rB * QS + c + 1] = acc[j].w + Xs[rB * QS + c + 1];
        }
    }
    __syncthreads();

    // LayerNorm: 8 threads per row, single pass
    {
        int row = tid >> 3, l8 = tid & 7;
        float s = 0.f, s2 = 0.f;
        #pragma unroll
        for (int q = 0; q < 3; q++) {
            float4 y = *(const float4*)&Y[row * QS + l8 * 12 + q * 4];
            s += (y.x + y.y) + (y.z + y.w);
            s2 = fmaf(y.x, y.x, fmaf(y.y, y.y, fmaf(y.z, y.z, fmaf(y.w, y.w, s2))));
        }
        #pragma unroll
        for (int o = 4; o > 0; o >>= 1) {
            s  += __shfl_xor_sync(0xffffffffu, s,  o);
            s2 += __shfl_xor_sync(0xffffffffu, s2, o);
        }
        if (l8 == 0) {
            float mean = s * (1.0f / 96.0f);
            float var  = fmaf(-mean, mean, s2 * (1.0f / 96.0f));
            stats[row]      = mean;
            stats[64 + row] = rsqrtf(var + 1e-5f);
        }
    }
    __syncthreads();

    for (int idx = tid; idx < 6144; idx += 512) {
        int t = idx / CH, c = idx - t * CH;
        float yv = (Y[t * QS + c] - stats[t]) * stats[64 + t];
        dst[idx] = fmaf(yv, gam[c], beta[c]);
    }
}

// ---------------------------------------------------------------------------
// Input order (setup_inputs dict order):
//   0: x | 1..7: sa1 | 8..14: sa2 | 15..20: ff1 | 21..26: ff2
// ---------------------------------------------------------------------------
extern "C" void kernel_launch(void* const* d_in, const int* in_sizes, int n_in,
                              void* d_out, int out_size) {
    const float* x = (const float*)d_in[0];
    float *imgA, *imgB;
    float2* ws;
    cudaGetSymbolAddress((void**)&imgA, g_imgA);
    cudaGetSymbolAddress((void**)&imgB, g_imgB);
    cudaGetSymbolAddress((void**)&ws,   g_wsplit);

    cudaFuncSetAttribute(attn_kernel<0>, cudaFuncAttributeMaxDynamicSharedMemorySize, ATTN_SMEM);
    cudaFuncSetAttribute(attn_kernel<1>, cudaFuncAttributeMaxDynamicSharedMemorySize, ATTN_SMEM);
    cudaFuncSetAttribute(ffn_kernel,     cudaFuncAttributeMaxDynamicSharedMemorySize, FFN_SMEM);

    // pre-split weights into tf32 (hi,lo)
    split_weights_kernel<<<(27648+255)/256, 256>>>((const float*)d_in[1],  ws + WS_SA1_QKV,  27648);
    split_weights_kernel<<<(9216 +255)/256, 256>>>((const float*)d_in[4],  ws + WS_SA1_PROJ, 9216);
    split_weights_kernel<<<(27648+255)/256, 256>>>((const float*)d_in[8],  ws + WS_SA2_QKV,  27648);
    split_weights_kernel<<<(9216 +255)/256, 256>>>((const float*)d_in[11], ws + WS_SA2_PROJ, 9216);
    split_weights_kernel<<<(18432+255)/256, 256>>>((const float*)d_in[15], ws + WS_FF1_W1,   18432);
    split_weights_kernel<<<(18432+255)/256, 256>>>((const float*)d_in[17], ws + WS_FF1_W2,   18432);
    split_weights_kernel<<<(18432+255)/256, 256>>>((const float*)d_in[21], ws + WS_FF2_W1,   18432);
    split_weights_kernel<<<(18432+255)/256, 256>>>((const float*)d_in[23], ws + WS_FF2_W2,   18432);

    dim3 tb(32, 8);
    dim3 tg(HW / 32, CH / 32, BATCH);

    transpose_in_kernel<<<tg, tb>>>(x, imgA);

    attn_kernel<0><<<NWIN, 512, ATTN_SMEM>>>(
        imgA, imgB,
        ws + WS_SA1_QKV, (const float*)d_in[2], (const float*)d_in[3],
        ws + WS_SA1_PROJ, (const float*)d_in[5], (const float*)d_in[6],
        (const float*)d_in[7]);

    ffn_kernel<<<NWIN, 512, FFN_SMEM>>>(
        imgB, imgA,
        ws + WS_FF1_W1, (const float*)d_in[16], ws + WS_FF1_W2,
        (const float*)d_in[18], (const float*)d_in[19], (const float*)d_in[20]);

    attn_kernel<1><<<NWIN, 512, ATTN_SMEM>>>(
        imgA, imgB,
        ws + WS_SA2_QKV, (const float*)d_in[9], (const float*)d_in[10],
        ws + WS_SA2_PROJ, (const float*)d_in[12], (const float*)d_in[13],
        (const float*)d_in[14]);

    ffn_kernel<<<NWIN, 512, FFN_SMEM>>>(
        imgB, imgA,
        ws + WS_FF2_W1, (const float*)d_in[22], ws + WS_FF2_W2,
        (const float*)d_in[24], (const float*)d_in[25], (const float*)d_in[26]);

    transpose_out_kernel<<<tg, tb>>>(imgA, (float*)d_out);
}

// round 9
// speedup vs baseline: 1.0042x; 1.0042x over previous
#include <cuda_runtime.h>
#include <math.h>
#include <stdint.h>

#define CH    96
#define HH    192
#define WWI   192
#define HW    (HH*WWI)        // 36864
#define BATCH 4
#define NWIN_PER 576          // 24*24 windows per image
#define NWIN  (BATCH*NWIN_PER)
#define NTOK  64
#define NHEAD 6
#define HDIM  16
#define QS    100             // row stride for 64-row fp32 tiles
#define HS    196             // FFN hidden stride

// 56.6 MB each — static device scratch (no allocations allowed)
__device__ float g_imgA[BATCH*HW*CH];
__device__ float g_imgB[BATCH*HW*CH];
// pre-split tf32 weights, TWO-PLANE layout: [hi0..hiN-1 | lo0..loN-1] per matrix
#define WS_SA1_QKV   0            // 27648*2
#define WS_SA1_PROJ  55296        // 9216*2
#define WS_SA2_QKV   73728        // 27648*2
#define WS_SA2_PROJ  129024       // 9216*2
#define WS_FF1_W1    147456       // 18432*2
#define WS_FF1_W2    184320       // 18432*2
#define WS_FF2_W1    221184       // 18432*2
#define WS_FF2_W2    258048       // 18432*2
__device__ float g_wsplit[294912];

// ---------------------------------------------------------------------------
// FMA-only exp. Valid for x <= 0 (softmax-shifted logits); clamps at -80.
// ---------------------------------------------------------------------------
__device__ __forceinline__ float fexp(float x) {
    x = fmaxf(x, -80.0f);
    const float L2E = 1.4426950408889634f;
    float t = fmaf(x, L2E, 12582912.0f);
    float n = t - 12582912.0f;
    float f = fmaf(x, L2E, -n);
    float p = 1.5403530393381608e-4f;
    p = fmaf(p, f, 1.3333558146428443e-3f);
    p = fmaf(p, f, 9.6181291076284772e-3f);
    p = fmaf(p, f, 5.5504108664821580e-2f);
    p = fmaf(p, f, 2.4022650695910072e-1f);
    p = fmaf(p, f, 6.9314718055994531e-1f);
    p = fmaf(p, f, 1.0f);
    int e = (int)n;
    float s = __int_as_float((127 + e) << 23);
    return p * s;
}

// ---------------------------------------------------------------------------
// tf32 MMA helpers (3xTF32 split for near-fp32 accuracy)
// ---------------------------------------------------------------------------
__device__ __forceinline__ uint32_t f2tf(float x) {
    uint32_t r; asm("cvt.rna.tf32.f32 %0, %1;" : "=r"(r) : "f"(x)); return r;
}
__device__ __forceinline__ void tfsplit(float x, uint32_t& h, uint32_t& l) {
    h = f2tf(x);
    l = f2tf(x - __uint_as_float(h));
}
__device__ __forceinline__ void mma_m16n8k8(float4& d,
    uint32_t a0, uint32_t a1, uint32_t a2, uint32_t a3,
    uint32_t b0, uint32_t b1)
{
    asm volatile("mma.sync.aligned.m16n8k8.row.col.f32.tf32.tf32.f32 "
                 "{%0,%1,%2,%3},{%4,%5,%6,%7},{%8,%9},{%0,%1,%2,%3};"
                 : "+f"(d.x), "+f"(d.y), "+f"(d.z), "+f"(d.w)
                 : "r"(a0), "r"(a1), "r"(a2), "r"(a3), "r"(b0), "r"(b1));
}

// weight pre-split kernel: x -> hi plane [0..n), lo plane [n..2n)
__global__ void split_weights_kernel(const float* __restrict__ src,
                                     float* __restrict__ dst, int n) {
    int i = blockIdx.x * 256 + threadIdx.x;
    if (i < n) {
        float x = src[i];
        float hf = __uint_as_float(f2tf(x));
        float lf = __uint_as_float(f2tf(x - hf));
        dst[i]     = hf;
        dst[i + n] = lf;
    }
}

// C = A(64 x K, smem, row stride lda) @ B(K x N, two-plane split gmem, stride ldb)
// Bh = hi plane base, Bh + plane = lo plane. warp: 16-row m-tile x NT 8-col n-tiles.
template<int NT, int KSTEPS>
__device__ __forceinline__ void mma_gemm(
    float4* acc, const float* A, int lda, int m0,
    const float* __restrict__ Bh, int plane, int ldb, int n0, int mg, int mt)
{
    const float* __restrict__ Bl = Bh + plane;
    #pragma unroll 2
    for (int ks = 0; ks < KSTEPS; ks++) {
        const int k0 = ks * 8;
        uint32_t ah[4], al[4];
        tfsplit(A[(m0 + mg) * lda + k0 + mt],         ah[0], al[0]);
        tfsplit(A[(m0 + mg + 8) * lda + k0 + mt],     ah[1], al[1]);
        tfsplit(A[(m0 + mg) * lda + k0 + mt + 4],     ah[2], al[2]);
        tfsplit(A[(m0 + mg + 8) * lda + k0 + mt + 4], ah[3], al[3]);
        #pragma unroll
        for (int j = 0; j < NT; j++) {
            int o0 = (k0 + mt) * ldb + n0 + j * 8 + mg;
            int o1 = (k0 + mt + 4) * ldb + n0 + j * 8 + mg;
            uint32_t bh0 = __float_as_uint(__ldg(Bh + o0));
            uint32_t bh1 = __float_as_uint(__ldg(Bh + o1));
            uint32_t bl0 = __float_as_uint(__ldg(Bl + o0));
            uint32_t bl1 = __float_as_uint(__ldg(Bl + o1));
            mma_m16n8k8(acc[j], ah[0], ah[1], ah[2], ah[3], bh0, bh1);
            mma_m16n8k8(acc[j], ah[0], ah[1], ah[2], ah[3], bl0, bl1);
            mma_m16n8k8(acc[j], al[0], al[1], al[2], al[3], bh0, bh1);
        }
    }
}

// ---------------------------------------------------------------------------
// Transposes: [B,C,H,W] <-> [B,HW,C]
// ---------------------------------------------------------------------------
__global__ void transpose_in_kernel(const float* __restrict__ x, float* __restrict__ img) {
    __shared__ float tile[32][33];
    int b = blockIdx.z;
    int hw0 = blockIdx.x * 32, c0 = blockIdx.y * 32;
    const float* src = x + (size_t)b * CH * HW;
    float* dst = img + (size_t)b * HW * CH;
    #pragma unroll
    for (int i = threadIdx.y; i < 32; i += 8)
        tile[i][threadIdx.x] = src[(size_t)(c0 + i) * HW + hw0 + threadIdx.x];
    __syncthreads();
    #pragma unroll
    for (int i = threadIdx.y; i < 32; i += 8)
        dst[(size_t)(hw0 + i) * CH + c0 + threadIdx.x] = tile[threadIdx.x][i];
}

__global__ void transpose_out_kernel(const float* __restrict__ img, float* __restrict__ x) {
    __shared__ float tile[32][33];
    int b = blockIdx.z;
    int hw0 = blockIdx.x * 32, c0 = blockIdx.y * 32;
    const float* src = img + (size_t)b * HW * CH;
    float* dst = x + (size_t)b * CH * HW;
    #pragma unroll
    for (int i = threadIdx.y; i < 32; i += 8)
        tile[i][threadIdx.x] = src[(size_t)(hw0 + i) * CH + c0 + threadIdx.x];
    __syncthreads();
    #pragma unroll
    for (int i = threadIdx.y; i < 32; i += 8)
        dst[(size_t)(c0 + i) * HW + hw0 + threadIdx.x] = tile[threadIdx.x][i];
}

// ---------------------------------------------------------------------------
// Fused window attention: GEMMs on tensor cores (3xTF32, two-plane weights),
// heads SIMT.
// smem floats: Xs/Qb/Kb/Vb/Ob 5*6400 | S 2*64*68 | Tb 1360 | stats 128 |
//              Cnt 64  = 42,256 floats = 169,024 B
// ---------------------------------------------------------------------------
#define ATTN_SMEM (42256 * 4)

template<int SHIFTED>
__global__ void __launch_bounds__(512, 1) attn_kernel(
    const float* __restrict__ in, float* __restrict__ out,
    const float* __restrict__ wqkv2, const float* __restrict__ bqkv,
    const float* __restrict__ table, const float* __restrict__ wproj2,
    const float* __restrict__ bproj, const float* __restrict__ gam,
    const float* __restrict__ beta)
{
    extern __shared__ float sm[];
    float* Xs    = sm;                 // 64 x QS
    float* Qb    = Xs + 64*QS;         // 64 x QS (later reused as Y)
    float* Kb    = Qb + 64*QS;
    float* Vb    = Kb + 64*QS;
    float* Ob    = Vb + 64*QS;
    float* S     = Ob + 64*QS;         // 2 x 64 x 68
    float* Tb    = S + 2*64*68;        // 1360 (1350 used)
    float* stats = Tb + 1360;          // 128
    int*   Cnt   = (int*)(stats + 128);// 64

    const int tid = threadIdx.x;
    const int wid = blockIdx.x;
    const int b  = wid / NWIN_PER;
    const int wl = wid - b * NWIN_PER;
    const int wr = wl / 24, wc = wl - (wl / 24) * 24;
    const float* src = in  + (size_t)b * HW * CH;
    float*       dst = out + (size_t)b * HW * CH;

    // ---- gather window tokens + stage table + region ids ----
    for (int idx = tid; idx < NTOK * CH; idx += 512) {
        int t = idx / CH, c = idx - t * CH;
        int r = t >> 3, cl = t & 7;
        int h = wr * 8 + r, w = wc * 8 + cl;
        if (SHIFTED) { h += 4; if (h >= HH) h -= HH; w += 4; if (w >= WWI) w -= WWI; }
        Xs[t * QS + c] = src[(h * WWI + w) * CH + c];
    }
    for (int idx = tid; idx < 1350; idx += 512) Tb[idx] = table[idx];
    if (SHIFTED && tid < 64) {
        int ri = tid >> 3, ci = tid & 7;
        Cnt[tid] = ((wr == 23) ? (ri < 4 ? 1 : 2) : 0) * 3
                 + ((wc == 23) ? (ci < 4 ? 1 : 2) : 0);
    }
    __syncthreads();

    const int wg = tid >> 5, tx = tid & 31;   // 16 warps
    const int mg = tx >> 2, mt = tx & 3;      // mma lane coords
    const int m0 = (wg & 3) * 16;             // m-tile
    const int nch = wg >> 2;                  // n-chunk

    // ---- QKV GEMM: 64x288x96 via mma; warp covers 16 rows x 72 cols ----
    {
        float4 acc[9];
        #pragma unroll
        for (int j = 0; j < 9; j++) {
            int c = nch * 72 + j * 8 + 2 * mt;
            float b0 = __ldg(&bqkv[c]), b1 = __ldg(&bqkv[c + 1]);
            acc[j].x = b0; acc[j].y = b1; acc[j].z = b0; acc[j].w = b1;
        }
        mma_gemm<9, 12>(acc, Xs, QS, m0, wqkv2, 27648, 288, nch * 72, mg, mt);
        #pragma unroll
        for (int j = 0; j < 9; j++) {
            int c = nch * 72 + j * 8 + 2 * mt;
            int rA = m0 + mg, rB = rA + 8;
            float v[4] = {acc[j].x, acc[j].y, acc[j].z, acc[j].w};
            int   rr[4] = {rA, rA, rB, rB};
            int   cc[4] = {c, c + 1, c, c + 1};
            #pragma unroll
            for (int e = 0; e < 4; e++) {
                int col = cc[e];
                if (col < 96)       Qb[rr[e] * QS + col]         = v[e];
                else if (col < 192) Kb[rr[e] * QS + (col - 96)]  = v[e];
                else                Vb[rr[e] * QS + (col - 192)] = v[e];
            }
        }
    }
    __syncthreads();

    // ---- heads: 2 in flight (warps 0-7 -> head 2it, warps 8-15 -> 2it+1) ----
    const int hg   = wg >> 3;          // head group
    const int rowg = wg & 7;
    const int i0   = rowg * 8;
    int cni[8], cj0 = 0, cj1 = 0;
    if (SHIFTED) {
        cj0 = Cnt[tx]; cj1 = Cnt[tx + 32];
        #pragma unroll
        for (int r = 0; r < 8; r++) cni[r] = Cnt[i0 + r];
    }
    for (int it = 0; it < 3; it++) {
        const int hd = it * 2 + hg;
        float* Sg = S + hg * 64 * 68;

        float sc[8][2];
        #pragma unroll
        for (int r = 0; r < 8; r++) { sc[r][0] = 0.f; sc[r][1] = 0.f; }
        #pragma unroll
        for (int d4 = 0; d4 < 4; d4++) {
            float4 k0 = *(const float4*)&Kb[tx * QS + hd * 16 + d4 * 4];
            float4 k1 = *(const float4*)&Kb[(tx + 32) * QS + hd * 16 + d4 * 4];
            #pragma unroll
            for (int r = 0; r < 8; r++) {
                float4 q = *(const float4*)&Qb[(i0 + r) * QS + hd * 16 + d4 * 4];
                sc[r][0] = fmaf(q.x, k0.x, fmaf(q.y, k0.y, fmaf(q.z, k0.z, fmaf(q.w, k0.w, sc[r][0]))));
                sc[r][1] = fmaf(q.x, k1.x, fmaf(q.y, k1.y, fmaf(q.z, k1.z, fmaf(q.w, k1.w, sc[r][1]))));
            }
        }
        #pragma unroll
        for (int r = 0; r < 8; r++) {
            int i = i0 + r;
            int ri = i >> 3, ci = i & 7;
            float v[2];
            #pragma unroll
            for (int cj = 0; cj < 2; cj++) {
                int j = tx + 32 * cj;
                int rj = j >> 3, cjj = j & 7;
                int ridx = (ri - rj + 7) * 15 + (ci - cjj + 7);
                float bias = Tb[ridx * 6 + hd];
                if (SHIFTED) {
                    int cjv = cj ? cj1 : cj0;
                    if (cni[r] != cjv) bias -= 100.f;
                }
                v[cj] = fmaf(sc[r][cj], 0.25f, bias);
            }
            float mx = fmaxf(v[0], v[1]);
            #pragma unroll
            for (int o = 16; o > 0; o >>= 1) mx = fmaxf(mx, __shfl_xor_sync(0xffffffffu, mx, o));
            float e0 = fexp(v[0] - mx), e1 = fexp(v[1] - mx);
            float ssum = e0 + e1;
            #pragma unroll
            for (int o = 16; o > 0; o >>= 1) ssum += __shfl_xor_sync(0xffffffffu, ssum, o);
            float inv = 1.0f / ssum;
            Sg[i * 68 + tx]      = e0 * inv;
            Sg[i * 68 + tx + 32] = e1 * inv;
        }
        __syncthreads();

        // attn @ V : thread = (row, d4 group) within its head's 256 threads
        {
            int gtid = tid & 255;
            int d4   = gtid & 3;
            int row  = gtid >> 2;
            float4 o = make_float4(0.f, 0.f, 0.f, 0.f);
            #pragma unroll 4
            for (int j4 = 0; j4 < 16; j4++) {
                float4 s4 = *(const float4*)&Sg[row * 68 + j4 * 4];
                #pragma unroll
                for (int jj = 0; jj < 4; jj++) {
                    float sj = (jj == 0) ? s4.x : (jj == 1) ? s4.y : (jj == 2) ? s4.z : s4.w;
                    float4 v4 = *(const float4*)&Vb[(j4 * 4 + jj) * QS + hd * 16 + d4 * 4];
                    o.x = fmaf(sj, v4.x, o.x);
                    o.y = fmaf(sj, v4.y, o.y);
                    o.z = fmaf(sj, v4.z, o.z);
                    o.w = fmaf(sj, v4.w, o.w);
                }
            }
            *(float4*)&Ob[row * QS + hd * 16 + d4 * 4] = o;
        }
        __syncthreads();
    }

    // ---- proj GEMM 64x96x96 via mma + residual ----
    float* Y = Qb;  // reuse
    {
        float4 acc[3];
        #pragma unroll
        for (int j = 0; j < 3; j++) {
            int c = nch * 24 + j * 8 + 2 * mt;
            float b0 = __ldg(&bproj[c]), b1 = __ldg(&bproj[c + 1]);
            acc[j].x = b0; acc[j].y = b1; acc[j].z = b0; acc[j].w = b1;
        }
        mma_gemm<3, 12>(acc, Ob, QS, m0, wproj2, 9216, 96, nch * 24, mg, mt);
        #pragma unroll
        for (int j = 0; j < 3; j++) {
            int c = nch * 24 + j * 8 + 2 * mt;
            int rA = m0 + mg, rB = rA + 8;
            Y[rA * QS + c]     = acc[j].x + Xs[rA * QS + c];
            Y[rA * QS + c + 1] = acc[j].y + Xs[rA * QS + c + 1];
            Y[rB * QS + c]     = acc[j].z + Xs[rB * QS + c];
            Y[rB * QS + c + 1] = acc[j].w + Xs[rB * QS + c + 1];
        }
    }
    __syncthreads();

    // ---- LayerNorm: 8 threads per row, single pass ----
    {
        int row = tid >> 3, l8 = tid & 7;
        float s = 0.f, s2 = 0.f;
        #pragma unroll
        for (int q = 0; q < 3; q++) {
            float4 y = *(const float4*)&Y[row * QS + l8 * 12 + q * 4];
            s += (y.x + y.y) + (y.z + y.w);
            s2 = fmaf(y.x, y.x, fmaf(y.y, y.y, fmaf(y.z, y.z, fmaf(y.w, y.w, s2))));
        }
        #pragma unroll
        for (int o = 4; o > 0; o >>= 1) {
            s  += __shfl_xor_sync(0xffffffffu, s,  o);
            s2 += __shfl_xor_sync(0xffffffffu, s2, o);
        }
        if (l8 == 0) {
            float mean = s * (1.0f / 96.0f);
            float var  = fmaf(-mean, mean, s2 * (1.0f / 96.0f));
            stats[row]      = mean;
            stats[64 + row] = rsqrtf(var + 1e-5f);
        }
    }
    __syncthreads();

    // ---- scatter (same coords as gather: roll cancels) ----
    for (int idx = tid; idx < NTOK * CH; idx += 512) {
        int t = idx / CH, c = idx - t * CH;
        int r = t >> 3, cl = t & 7;
        int h = wr * 8 + r, w = wc * 8 + cl;
        if (SHIFTED) { h += 4; if (h >= HH) h -= HH; w += 4; if (w >= WWI) w -= WWI; }
        float yv = (Y[t * QS + c] - stats[t]) * stats[64 + t];
        dst[(h * WWI + w) * CH + c] = fmaf(yv, gam[c], beta[c]);
    }
}

// ---------------------------------------------------------------------------
// Fused FFN: both GEMMs on tensor cores (3xTF32, two-plane weights).
// smem floats: Xs 64x100 | H1 64x196 | Y 64x100 | stats 128 = 25,472
// ---------------------------------------------------------------------------
#define FFN_SMEM (25472 * 4)

__global__ void __launch_bounds__(512, 1) ffn_kernel(
    const float* __restrict__ in, float* __restrict__ out,
    const float* __restrict__ w12, const float* __restrict__ b1,
    const float* __restrict__ w22, const float* __restrict__ b2,
    const float* __restrict__ gam, const float* __restrict__ beta)
{
    extern __shared__ float sm[];
    float* Xs    = sm;                  // 64 x QS
    float* H1    = Xs + 64*QS;          // 64 x HS
    float* Y     = H1 + 64*HS;          // 64 x QS
    float* stats = Y + 64*QS;

    const int tid = threadIdx.x;
    const size_t t0 = (size_t)blockIdx.x * 64;
    const float* src = in + t0 * CH;
    float*       dst = out + t0 * CH;

    for (int idx = tid; idx < 6144; idx += 512) {
        int t = idx / CH, c = idx - t * CH;
        Xs[t * QS + c] = src[idx];
    }
    __syncthreads();

    const int wg = tid >> 5, tx = tid & 31;
    const int mg = tx >> 2, mt = tx & 3;
    const int m0 = (wg & 3) * 16;
    const int nch = wg >> 2;

    // GEMM1: 64x192x96 + GELU -> H1
    {
        float4 acc[6];
        #pragma unroll
        for (int j = 0; j < 6; j++) {
            int c = nch * 48 + j * 8 + 2 * mt;
            float v0 = __ldg(&b1[c]), v1 = __ldg(&b1[c + 1]);
            acc[j].x = v0; acc[j].y = v1; acc[j].z = v0; acc[j].w = v1;
        }
        mma_gemm<6, 12>(acc, Xs, QS, m0, w12, 18432, 192, nch * 48, mg, mt);
        #pragma unroll
        for (int j = 0; j < 6; j++) {
            int c = nch * 48 + j * 8 + 2 * mt;
            int rA = m0 + mg, rB = rA + 8;
            float v[4] = {acc[j].x, acc[j].y, acc[j].z, acc[j].w};
            int   rr[4] = {rA, rA, rB, rB};
            int   cc[4] = {c, c + 1, c, c + 1};
            #pragma unroll
            for (int e = 0; e < 4; e++) {
                float x = v[e];
                H1[rr[e] * HS + cc[e]] = 0.5f * x * (1.0f + erff(x * 0.70710678118654752f));
            }
        }
    }
    __syncthreads();

    // GEMM2: 64x96x192 + residual -> Y
    {
        float4 acc[3];
        #pragma unroll
        for (int j = 0; j < 3; j++) {
            int c = nch * 24 + j * 8 + 2 * mt;
            float v0 = __ldg(&b2[c]), v1 = __ldg(&b2[c + 1]);
            acc[j].x = v0; acc[j].y = v1; acc[j].z = v0; acc[j].w = v1;
        }
        mma_gemm<3, 24>(acc, H1, HS, m0, w22, 18432, 96, nch * 24, mg, mt);
        #pragma unroll
        for (int j = 0; j < 3; j++) {
            int c = nch * 24 + j * 8 + 2 * mt;
            int rA = m0 + mg, rB = rA + 8;
            Y[rA * QS + c]     = acc[j].x + Xs[rA * QS + c];
            Y[rA * QS + c + 1] = acc[j].y + Xs[rA * QS + c + 1];
            Y[rB * QS + c]     = acc[j].z + Xs[rB * QS + c];
            Y[rB * QS + c + 1] = acc[j].w + Xs[rB * QS + c + 1];
        }
    }
    __syncthreads();

    // LayerNorm: 8 threads per row, single pass
    {
        int row = tid >> 3, l8 = tid & 7;
        float s = 0.f, s2 = 0.f;
        #pragma unroll
        for (int q = 0; q < 3; q++) {
            float4 y = *(const float4*)&Y[row * QS + l8 * 12 + q * 4];
            s += (y.x + y.y) + (y.z + y.w);
            s2 = fmaf(y.x, y.x, fmaf(y.y, y.y, fmaf(y.z, y.z, fmaf(y.w, y.w, s2))));
        }
        #pragma unroll
        for (int o = 4; o > 0; o >>= 1) {
            s  += __shfl_xor_sync(0xffffffffu, s,  o);
            s2 += __shfl_xor_sync(0xffffffffu, s2, o);
        }
        if (l8 == 0) {
            float mean = s * (1.0f / 96.0f);
            float var  = fmaf(-mean, mean, s2 * (1.0f / 96.0f));
            stats[row]      = mean;
            stats[64 + row] = rsqrtf(var + 1e-5f);
        }
    }
    __syncthreads();

    for (int idx = tid; idx < 6144; idx += 512) {
        int t = idx / CH, c = idx - t * CH;
        float yv = (Y[t * QS + c] - stats[t]) * stats[64 + t];
        dst[idx] = fmaf(yv, gam[c], beta[c]);
    }
}

// ---------------------------------------------------------------------------
// Input order (setup_inputs dict order):
//   0: x | 1..7: sa1 | 8..14: sa2 | 15..20: ff1 | 21..26: ff2
// ---------------------------------------------------------------------------
extern "C" void kernel_launch(void* const* d_in, const int* in_sizes, int n_in,
                              void* d_out, int out_size) {
    const float* x = (const float*)d_in[0];
    float *imgA, *imgB, *ws;
    cudaGetSymbolAddress((void**)&imgA, g_imgA);
    cudaGetSymbolAddress((void**)&imgB, g_imgB);
    cudaGetSymbolAddress((void**)&ws,   g_wsplit);

    cudaFuncSetAttribute(attn_kernel<0>, cudaFuncAttributeMaxDynamicSharedMemorySize, ATTN_SMEM);
    cudaFuncSetAttribute(attn_kernel<1>, cudaFuncAttributeMaxDynamicSharedMemorySize, ATTN_SMEM);
    cudaFuncSetAttribute(ffn_kernel,     cudaFuncAttributeMaxDynamicSharedMemorySize, FFN_SMEM);

    // pre-split weights into tf32 hi/lo planes
    split_weights_kernel<<<(27648+255)/256, 256>>>((const float*)d_in[1],  ws + WS_SA1_QKV,  27648);
    split_weights_kernel<<<(9216 +255)/256, 256>>>((const float*)d_in[4],  ws + WS_SA1_PROJ, 9216);
    split_weights_kernel<<<(27648+255)/256, 256>>>((const float*)d_in[8],  ws + WS_SA2_QKV,  27648);
    split_weights_kernel<<<(9216 +255)/256, 256>>>((const float*)d_in[11], ws + WS_SA2_PROJ, 9216);
    split_weights_kernel<<<(18432+255)/256, 256>>>((const float*)d_in[15], ws + WS_FF1_W1,   18432);
    split_weights_kernel<<<(18432+255)/256, 256>>>((const float*)d_in[17], ws + WS_FF1_W2,   18432);
    split_weights_kernel<<<(18432+255)/256, 256>>>((const float*)d_in[21], ws + WS_FF2_W1,   18432);
    split_weights_kernel<<<(18432+255)/256, 256>>>((const float*)d_in[23], ws + WS_FF2_W2,   18432);

    dim3 tb(32, 8);
    dim3 tg(HW / 32, CH / 32, BATCH);

    transpose_in_kernel<<<tg, tb>>>(x, imgA);

    attn_kernel<0><<<NWIN, 512, ATTN_SMEM>>>(
        imgA, imgB,
        ws + WS_SA1_QKV, (const float*)d_in[2], (const float*)d_in[3],
        ws + WS_SA1_PROJ, (const float*)d_in[5], (const float*)d_in[6],
        (const float*)d_in[7]);

    ffn_kernel<<<NWIN, 512, FFN_SMEM>>>(
        imgB, imgA,
        ws + WS_FF1_W1, (const float*)d_in[16], ws + WS_FF1_W2,
        (const float*)d_in[18], (const float*)d_in[19], (const float*)d_in[20]);

    attn_kernel<1><<<NWIN, 512, ATTN_SMEM>>>(
        imgA, imgB,
        ws + WS_SA2_QKV, (const float*)d_in[9], (const float*)d_in[10],
        ws + WS_SA2_PROJ, (const float*)d_in[12], (const float*)d_in[13],
        (const float*)d_in[14]);

    ffn_kernel<<<NWIN, 512, FFN_SMEM>>>(
        imgB, imgA,
        ws + WS_FF2_W1, (const float*)d_in[22], ws + WS_FF2_W2,
        (const float*)d_in[24], (const float*)d_in[25], (const float*)d_in[26]);

    transpose_out_kernel<<<tg, tb>>>(imgA, (float*)d_out);
}

// round 10
// speedup vs baseline: 1.3099x; 1.3043x over previous
#include <cuda_runtime.h>
#include <math.h>
#include <stdint.h>

#define CH    96
#define HH    192
#define WWI   192
#define HW    (HH*WWI)        // 36864
#define BATCH 4
#define NWIN_PER 576          // 24*24 windows per image
#define NWIN  (BATCH*NWIN_PER)
#define NTOK  64
#define NHEAD 6
#define HDIM  16
#define QS    100             // row stride for 64-row fp32 tiles
#define HS    196             // FFN hidden stride

// 56.6 MB each — static device scratch (no allocations allowed)
__device__ float g_imgA[BATCH*HW*CH];
__device__ float g_imgB[BATCH*HW*CH];

// ---------------------------------------------------------------------------
// FMA-only exp. Valid for x <= 0 (softmax-shifted logits); clamps at -80.
// ---------------------------------------------------------------------------
__device__ __forceinline__ float fexp(float x) {
    x = fmaxf(x, -80.0f);
    const float L2E = 1.4426950408889634f;
    float t = fmaf(x, L2E, 12582912.0f);
    float n = t - 12582912.0f;
    float f = fmaf(x, L2E, -n);
    float p = 1.5403530393381608e-4f;
    p = fmaf(p, f, 1.3333558146428443e-3f);
    p = fmaf(p, f, 9.6181291076284772e-3f);
    p = fmaf(p, f, 5.5504108664821580e-2f);
    p = fmaf(p, f, 2.4022650695910072e-1f);
    p = fmaf(p, f, 6.9314718055994531e-1f);
    p = fmaf(p, f, 1.0f);
    int e = (int)n;
    float s = __int_as_float((127 + e) << 23);
    return p * s;
}

// ---------------------------------------------------------------------------
// tf32 MMA helpers (3xTF32 split for near-fp32 accuracy)
// ---------------------------------------------------------------------------
__device__ __forceinline__ uint32_t f2tf(float x) {
    uint32_t r; asm("cvt.rna.tf32.f32 %0, %1;" : "=r"(r) : "f"(x)); return r;
}
__device__ __forceinline__ void tfsplit(float x, uint32_t& h, uint32_t& l) {
    h = f2tf(x);
    l = f2tf(x - __uint_as_float(h));
}
__device__ __forceinline__ void mma_m16n8k8(float4& d,
    uint32_t a0, uint32_t a1, uint32_t a2, uint32_t a3,
    uint32_t b0, uint32_t b1)
{
    asm volatile("mma.sync.aligned.m16n8k8.row.col.f32.tf32.tf32.f32 "
                 "{%0,%1,%2,%3},{%4,%5,%6,%7},{%8,%9},{%0,%1,%2,%3};"
                 : "+f"(d.x), "+f"(d.y), "+f"(d.z), "+f"(d.w)
                 : "r"(a0), "r"(a1), "r"(a2), "r"(a3), "r"(b0), "r"(b1));
}

// C = A(64 x K, smem, row stride lda) @ B(K x N, fp32 gmem row-major, stride ldb)
// In-loop 3xTF32 split (R7 config: 2 LDG + ALU beats 4 LDG on the L1tex pipe).
template<int NT, int KSTEPS>
__device__ __forceinline__ void mma_gemm(
    float4* acc, const float* A, int lda, int m0,
    const float* __restrict__ B, int ldb, int n0, int mg, int mt)
{
    #pragma unroll 2
    for (int ks = 0; ks < KSTEPS; ks++) {
        const int k0 = ks * 8;
        uint32_t ah[4], al[4];
        tfsplit(A[(m0 + mg) * lda + k0 + mt],         ah[0], al[0]);
        tfsplit(A[(m0 + mg + 8) * lda + k0 + mt],     ah[1], al[1]);
        tfsplit(A[(m0 + mg) * lda + k0 + mt + 4],     ah[2], al[2]);
        tfsplit(A[(m0 + mg + 8) * lda + k0 + mt + 4], ah[3], al[3]);
        #pragma unroll
        for (int j = 0; j < NT; j++) {
            float w0 = __ldg(&B[(k0 + mt) * ldb + n0 + j * 8 + mg]);
            float w1 = __ldg(&B[(k0 + mt + 4) * ldb + n0 + j * 8 + mg]);
            uint32_t bh0, bl0, bh1, bl1;
            tfsplit(w0, bh0, bl0);
            tfsplit(w1, bh1, bl1);
            mma_m16n8k8(acc[j], ah[0], ah[1], ah[2], ah[3], bh0, bh1);
            mma_m16n8k8(acc[j], ah[0], ah[1], ah[2], ah[3], bl0, bl1);
            mma_m16n8k8(acc[j], al[0], al[1], al[2], al[3], bh0, bh1);
        }
    }
}

// ---------------------------------------------------------------------------
// Transposes: [B,C,H,W] <-> [B,HW,C]
// ---------------------------------------------------------------------------
__global__ void transpose_in_kernel(const float* __restrict__ x, float* __restrict__ img) {
    __shared__ float tile[32][33];
    int b = blockIdx.z;
    int hw0 = blockIdx.x * 32, c0 = blockIdx.y * 32;
    const float* src = x + (size_t)b * CH * HW;
    float* dst = img + (size_t)b * HW * CH;
    #pragma unroll
    for (int i = threadIdx.y; i < 32; i += 8)
        tile[i][threadIdx.x] = src[(size_t)(c0 + i) * HW + hw0 + threadIdx.x];
    __syncthreads();
    #pragma unroll
    for (int i = threadIdx.y; i < 32; i += 8)
        dst[(size_t)(hw0 + i) * CH + c0 + threadIdx.x] = tile[threadIdx.x][i];
}

__global__ void transpose_out_kernel(const float* __restrict__ img, float* __restrict__ x) {
    __shared__ float tile[32][33];
    int b = blockIdx.z;
    int hw0 = blockIdx.x * 32, c0 = blockIdx.y * 32;
    const float* src = img + (size_t)b * HW * CH;
    float* dst = x + (size_t)b * CH * HW;
    #pragma unroll
    for (int i = threadIdx.y; i < 32; i += 8)
        tile[i][threadIdx.x] = src[(size_t)(hw0 + i) * CH + c0 + threadIdx.x];
    __syncthreads();
    #pragma unroll
    for (int i = threadIdx.y; i < 32; i += 8)
        dst[(size_t)(c0 + i) * HW + hw0 + threadIdx.x] = tile[threadIdx.x][i];
}

// ---------------------------------------------------------------------------
// Fused window attention: ALL matmuls (QKV, QK^T, AV, proj) on tensor cores
// (3xTF32). Softmax flat-SIMT. 512 threads (16 warps).
// smem floats: Xs/Qb/Kb/Vb/Ob 5*6400 | S 2*64*68 | Tb 1360 | stats 128 |
//              Cnt 64  = 42,256 floats = 169,024 B
// ---------------------------------------------------------------------------
#define ATTN_SMEM (42256 * 4)

template<int SHIFTED>
__global__ void __launch_bounds__(512, 1) attn_kernel(
    const float* __restrict__ in, float* __restrict__ out,
    const float* __restrict__ wqkv, const float* __restrict__ bqkv,
    const float* __restrict__ table, const float* __restrict__ wproj,
    const float* __restrict__ bproj, const float* __restrict__ gam,
    const float* __restrict__ beta)
{
    extern __shared__ float sm[];
    float* Xs    = sm;                 // 64 x QS
    float* Qb    = Xs + 64*QS;         // 64 x QS (later reused as Y)
    float* Kb    = Qb + 64*QS;
    float* Vb    = Kb + 64*QS;
    float* Ob    = Vb + 64*QS;
    float* S     = Ob + 64*QS;         // 2 x 64 x 68
    float* Tb    = S + 2*64*68;        // 1360 (1350 used)
    float* stats = Tb + 1360;          // 128
    int*   Cnt   = (int*)(stats + 128);// 64

    const int tid = threadIdx.x;
    const int wid = blockIdx.x;
    const int b  = wid / NWIN_PER;
    const int wl = wid - b * NWIN_PER;
    const int wr = wl / 24, wc = wl - (wl / 24) * 24;
    const float* src = in  + (size_t)b * HW * CH;
    float*       dst = out + (size_t)b * HW * CH;

    // ---- gather window tokens + stage table + region ids ----
    for (int idx = tid; idx < NTOK * CH; idx += 512) {
        int t = idx / CH, c = idx - t * CH;
        int r = t >> 3, cl = t & 7;
        int h = wr * 8 + r, w = wc * 8 + cl;
        if (SHIFTED) { h += 4; if (h >= HH) h -= HH; w += 4; if (w >= WWI) w -= WWI; }
        Xs[t * QS + c] = src[(h * WWI + w) * CH + c];
    }
    for (int idx = tid; idx < 1350; idx += 512) Tb[idx] = table[idx];
    if (tid < 64) {
        int ri = tid >> 3, ci = tid & 7;
        Cnt[tid] = SHIFTED ? (((wr == 23) ? (ri < 4 ? 1 : 2) : 0) * 3
                            + ((wc == 23) ? (ci < 4 ? 1 : 2) : 0)) : 0;
    }
    __syncthreads();

    const int wg = tid >> 5, tx = tid & 31;   // 16 warps
    const int mg = tx >> 2, mt = tx & 3;      // mma lane coords
    const int m0 = (wg & 3) * 16;             // m-tile (for QKV/proj)
    const int nch = wg >> 2;                  // n-chunk

    // ---- QKV GEMM: 64x288x96 via mma; warp covers 16 rows x 72 cols ----
    {
        float4 acc[9];
        #pragma unroll
        for (int j = 0; j < 9; j++) {
            int c = nch * 72 + j * 8 + 2 * mt;
            float b0 = __ldg(&bqkv[c]), b1 = __ldg(&bqkv[c + 1]);
            acc[j].x = b0; acc[j].y = b1; acc[j].z = b0; acc[j].w = b1;
        }
        mma_gemm<9, 12>(acc, Xs, QS, m0, wqkv, 288, nch * 72, mg, mt);
        #pragma unroll
        for (int j = 0; j < 9; j++) {
            int c = nch * 72 + j * 8 + 2 * mt;
            int rA = m0 + mg, rB = rA + 8;
            float v[4] = {acc[j].x, acc[j].y, acc[j].z, acc[j].w};
            int   rr[4] = {rA, rA, rB, rB};
            int   cc[4] = {c, c + 1, c, c + 1};
            #pragma unroll
            for (int e = 0; e < 4; e++) {
                int col = cc[e];
                if (col < 96)       Qb[rr[e] * QS + col]         = v[e];
                else if (col < 192) Kb[rr[e] * QS + (col - 96)]  = v[e];
                else                Vb[rr[e] * QS + (col - 192)] = v[e];
            }
        }
    }
    __syncthreads();

    // ---- heads: 2 in flight; 8 warps per head; MMA scores + MMA AV ----
    const int hg = wg >> 3;           // head group 0/1
    const int w8 = wg & 7;            // warp within head group
    const int hm = w8 & 3;            // m-tile for heads phase
    const int nh = w8 >> 2;           // n-half (scores) / d-half (AV)

    for (int it = 0; it < 3; it++) {
        const int hd = it * 2 + hg;
        float* Sg = S + hg * 64 * 68;
        const int kc0 = hd * 16;      // head's column base in Qb/Kb/Vb

        // --- scores: warp computes 16 rows x 32 cols of Q@K^T (3xTF32) ---
        {
            float4 acc[4];
            #pragma unroll
            for (int jt = 0; jt < 4; jt++) acc[jt] = make_float4(0.f, 0.f, 0.f, 0.f);
            #pragma unroll
            for (int ks = 0; ks < 2; ks++) {
                int kk = kc0 + ks * 8;
                uint32_t ah[4], al[4];
                tfsplit(Qb[(hm * 16 + mg) * QS + kk + mt],         ah[0], al[0]);
                tfsplit(Qb[(hm * 16 + mg + 8) * QS + kk + mt],     ah[1], al[1]);
                tfsplit(Qb[(hm * 16 + mg) * QS + kk + mt + 4],     ah[2], al[2]);
                tfsplit(Qb[(hm * 16 + mg + 8) * QS + kk + mt + 4], ah[3], al[3]);
                #pragma unroll
                for (int jt = 0; jt < 4; jt++) {
                    int tok = nh * 32 + jt * 8 + mg;
                    uint32_t bh0, bl0, bh1, bl1;
                    tfsplit(Kb[tok * QS + kk + mt],     bh0, bl0);
                    tfsplit(Kb[tok * QS + kk + mt + 4], bh1, bl1);
                    mma_m16n8k8(acc[jt], ah[0], ah[1], ah[2], ah[3], bh0, bh1);
                    mma_m16n8k8(acc[jt], ah[0], ah[1], ah[2], ah[3], bl0, bl1);
                    mma_m16n8k8(acc[jt], al[0], al[1], al[2], al[3], bh0, bh1);
                }
            }
            // epilogue: bias + mask, write raw logits to Sg
            int iA = hm * 16 + mg, iB = iA + 8;
            int riA = iA >> 3, ciA = iA & 7, riB = iB >> 3, ciB = iB & 7;
            int cntA = Cnt[iA], cntB = Cnt[iB];
            #pragma unroll
            for (int jt = 0; jt < 4; jt++) {
                int c = nh * 32 + jt * 8 + 2 * mt;
                #pragma unroll
                for (int e = 0; e < 2; e++) {
                    int j = c + e;
                    int rj = j >> 3, cj = j & 7;
                    int cntJ = Cnt[j];
                    float bA = Tb[((riA - rj + 7) * 15 + (ciA - cj + 7)) * 6 + hd];
                    float bB = Tb[((riB - rj + 7) * 15 + (ciB - cj + 7)) * 6 + hd];
                    if (SHIFTED) {
                        if (cntA != cntJ) bA -= 100.f;
                        if (cntB != cntJ) bB -= 100.f;
                    }
                    float vA = (e == 0) ? acc[jt].x : acc[jt].y;
                    float vB = (e == 0) ? acc[jt].z : acc[jt].w;
                    Sg[iA * 68 + j] = fmaf(vA, 0.25f, bA);
                    Sg[iB * 68 + j] = fmaf(vB, 0.25f, bB);
                }
            }
        }
        __syncthreads();

        // --- softmax: 4 threads per row, 128 rows (both heads) ---
        {
            int row = tid >> 2, l4 = tid & 2 ? (tid & 3) : (tid & 3); // l4 = tid&3
            l4 = tid & 3;
            float* Sr = S + (row >> 6) * 64 * 68 + (row & 63) * 68;
            float4 v[4];
            float mx = -1e30f;
            #pragma unroll
            for (int q = 0; q < 4; q++) {
                v[q] = *(const float4*)&Sr[l4 * 16 + q * 4];
                mx = fmaxf(mx, fmaxf(fmaxf(v[q].x, v[q].y), fmaxf(v[q].z, v[q].w)));
            }
            mx = fmaxf(mx, __shfl_xor_sync(0xffffffffu, mx, 1));
            mx = fmaxf(mx, __shfl_xor_sync(0xffffffffu, mx, 2));
            float ssum = 0.f;
            #pragma unroll
            for (int q = 0; q < 4; q++) {
                v[q].x = fexp(v[q].x - mx); v[q].y = fexp(v[q].y - mx);
                v[q].z = fexp(v[q].z - mx); v[q].w = fexp(v[q].w - mx);
                ssum += (v[q].x + v[q].y) + (v[q].z + v[q].w);
            }
            ssum += __shfl_xor_sync(0xffffffffu, ssum, 1);
            ssum += __shfl_xor_sync(0xffffffffu, ssum, 2);
            float inv = 1.0f / ssum;
            #pragma unroll
            for (int q = 0; q < 4; q++) {
                v[q].x *= inv; v[q].y *= inv; v[q].z *= inv; v[q].w *= inv;
                *(float4*)&Sr[l4 * 16 + q * 4] = v[q];
            }
        }
        __syncthreads();

        // --- AV: warp computes 16 rows x 8 dims via MMA (3xTF32) ---
        {
            int nc0 = kc0 + nh * 8;   // output dim base
            float4 acc = make_float4(0.f, 0.f, 0.f, 0.f);
            #pragma unroll
            for (int ks = 0; ks < 8; ks++) {
                int k0 = ks * 8;
                uint32_t ah[4], al[4];
                tfsplit(Sg[(hm * 16 + mg) * 68 + k0 + mt],         ah[0], al[0]);
                tfsplit(Sg[(hm * 16 + mg + 8) * 68 + k0 + mt],     ah[1], al[1]);
                tfsplit(Sg[(hm * 16 + mg) * 68 + k0 + mt + 4],     ah[2], al[2]);
                tfsplit(Sg[(hm * 16 + mg + 8) * 68 + k0 + mt + 4], ah[3], al[3]);
                uint32_t bh0, bl0, bh1, bl1;
                tfsplit(Vb[(k0 + mt) * QS + nc0 + mg],     bh0, bl0);
                tfsplit(Vb[(k0 + mt + 4) * QS + nc0 + mg], bh1, bl1);
                mma_m16n8k8(acc, ah[0], ah[1], ah[2], ah[3], bh0, bh1);
                mma_m16n8k8(acc, ah[0], ah[1], ah[2], ah[3], bl0, bl1);
                mma_m16n8k8(acc, al[0], al[1], al[2], al[3], bh0, bh1);
            }
            int rA = hm * 16 + mg, rB = rA + 8, c = nc0 + 2 * mt;
            Ob[rA * QS + c]     = acc.x;
            Ob[rA * QS + c + 1] = acc.y;
            Ob[rB * QS + c]     = acc.z;
            Ob[rB * QS + c + 1] = acc.w;
        }
        __syncthreads();
    }

    // ---- proj GEMM 64x96x96 via mma + residual ----
    float* Y = Qb;  // reuse
    {
        float4 acc[3];
        #pragma unroll
        for (int j = 0; j < 3; j++) {
            int c = nch * 24 + j * 8 + 2 * mt;
            float b0 = __ldg(&bproj[c]), b1 = __ldg(&bproj[c + 1]);
            acc[j].x = b0; acc[j].y = b1; acc[j].z = b0; acc[j].w = b1;
        }
        mma_gemm<3, 12>(acc, Ob, QS, m0, wproj, 96, nch * 24, mg, mt);
        __syncthreads();   // all Qb reads (scores) done; safe to overwrite as Y
        #pragma unroll
        for (int j = 0; j < 3; j++) {
            int c = nch * 24 + j * 8 + 2 * mt;
            int rA = m0 + mg, rB = rA + 8;
            Y[rA * QS + c]     = acc[j].x + Xs[rA * QS + c];
            Y[rA * QS + c + 1] = acc[j].y + Xs[rA * QS + c + 1];
            Y[rB * QS + c]     = acc[j].z + Xs[rB * QS + c];
            Y[rB * QS + c + 1] = acc[j].w + Xs[rB * QS + c + 1];
        }
    }
    __syncthreads();

    // ---- LayerNorm: 8 threads per row, single pass ----
    {
        int row = tid >> 3, l8 = tid & 7;
        float s = 0.f, s2 = 0.f;
        #pragma unroll
        for (int q = 0; q < 3; q++) {
            float4 y = *(const float4*)&Y[row * QS + l8 * 12 + q * 4];
            s += (y.x + y.y) + (y.z + y.w);
            s2 = fmaf(y.x, y.x, fmaf(y.y, y.y, fmaf(y.z, y.z, fmaf(y.w, y.w, s2))));
        }
        #pragma unroll
        for (int o = 4; o > 0; o >>= 1) {
            s  += __shfl_xor_sync(0xffffffffu, s,  o);
            s2 += __shfl_xor_sync(0xffffffffu, s2, o);
        }
        if (l8 == 0) {
            float mean = s * (1.0f / 96.0f);
            float var  = fmaf(-mean, mean, s2 * (1.0f / 96.0f));
            stats[row]      = mean;
            stats[64 + row] = rsqrtf(var + 1e-5f);
        }
    }
    __syncthreads();

    // ---- scatter (same coords as gather: roll cancels) ----
    for (int idx = tid; idx < NTOK * CH; idx += 512) {
        int t = idx / CH, c = idx - t * CH;
        int r = t >> 3, cl = t & 7;
        int h = wr * 8 + r, w = wc * 8 + cl;
        if (SHIFTED) { h += 4; if (h >= HH) h -= HH; w += 4; if (w >= WWI) w -= WWI; }
        float yv = (Y[t * QS + c] - stats[t]) * stats[64 + t];
        dst[(h * WWI + w) * CH + c] = fmaf(yv, gam[c], beta[c]);
    }
}

// ---------------------------------------------------------------------------
// Fused FFN: both GEMMs on tensor cores (3xTF32, fp32 weights direct).
// smem floats: Xs 64x100 | H1 64x196 | Y 64x100 | stats 128 = 25,472
// ---------------------------------------------------------------------------
#define FFN_SMEM (25472 * 4)

__global__ void __launch_bounds__(512, 1) ffn_kernel(
    const float* __restrict__ in, float* __restrict__ out,
    const float* __restrict__ w1, const float* __restrict__ b1,
    const float* __restrict__ w2, const float* __restrict__ b2,
    const float* __restrict__ gam, const float* __restrict__ beta)
{
    extern __shared__ float sm[];
    float* Xs    = sm;                  // 64 x QS
    float* H1    = Xs + 64*QS;          // 64 x HS
    float* Y     = H1 + 64*HS;          // 64 x QS
    float* stats = Y + 64*QS;

    const int tid = threadIdx.x;
    const size_t t0 = (size_t)blockIdx.x * 64;
    const float* src = in + t0 * CH;
    float*       dst = out + t0 * CH;

    for (int idx = tid; idx < 6144; idx += 512) {
        int t = idx / CH, c = idx - t * CH;
        Xs[t * QS + c] = src[idx];
    }
    __syncthreads();

    const int wg = tid >> 5, tx = tid & 31;
    const int mg = tx >> 2, mt = tx & 3;
    const int m0 = (wg & 3) * 16;
    const int nch = wg >> 2;

    // GEMM1: 64x192x96 + GELU -> H1
    {
        float4 acc[6];
        #pragma unroll
        for (int j = 0; j < 6; j++) {
            int c = nch * 48 + j * 8 + 2 * mt;
            float v0 = __ldg(&b1[c]), v1 = __ldg(&b1[c + 1]);
            acc[j].x = v0; acc[j].y = v1; acc[j].z = v0; acc[j].w = v1;
        }
        mma_gemm<6, 12>(acc, Xs, QS, m0, w1, 192, nch * 48, mg, mt);
        #pragma unroll
        for (int j = 0; j < 6; j++) {
            int c = nch * 48 + j * 8 + 2 * mt;
            int rA = m0 + mg, rB = rA + 8;
            float v[4] = {acc[j].x, acc[j].y, acc[j].z, acc[j].w};
            int   rr[4] = {rA, rA, rB, rB};
            int   cc[4] = {c, c + 1, c, c + 1};
            #pragma unroll
            for (int e = 0; e < 4; e++) {
                float x = v[e];
                H1[rr[e] * HS + cc[e]] = 0.5f * x * (1.0f + erff(x * 0.70710678118654752f));
            }
        }
    }
    __syncthreads();

    // GEMM2: 64x96x192 + residual -> Y
    {
        float4 acc[3];
        #pragma unroll
        for (int j = 0; j < 3; j++) {
            int c = nch * 24 + j * 8 + 2 * mt;
            float v0 = __ldg(&b2[c]), v1 = __ldg(&b2[c + 1]);
            acc[j].x = v0; acc[j].y = v1; acc[j].z = v0; acc[j].w = v1;
        }
        mma_gemm<3, 24>(acc, H1, HS, m0, w2, 96, nch * 24, mg, mt);
        #pragma unroll
        for (int j = 0; j < 3; j++) {
            int c = nch * 24 + j * 8 + 2 * mt;
            int rA = m0 + mg, rB = rA + 8;
            Y[rA * QS + c]     = acc[j].x + Xs[rA * QS + c];
            Y[rA * QS + c + 1] = acc[j].y + Xs[rA * QS + c + 1];
            Y[rB * QS + c]     = acc[j].z + Xs[rB * QS + c];
            Y[rB * QS + c + 1] = acc[j].w + Xs[rB * QS + c + 1];
        }
    }
    __syncthreads();

    // LayerNorm: 8 threads per row, single pass
    {
        int row = tid >> 3, l8 = tid & 7;
        float s = 0.f, s2 = 0.f;
        #pragma unroll
        for (int q = 0; q < 3; q++) {
            float4 y = *(const float4*)&Y[row * QS + l8 * 12 + q * 4];
            s += (y.x + y.y) + (y.z + y.w);
            s2 = fmaf(y.x, y.x, fmaf(y.y, y.y, fmaf(y.z, y.z, fmaf(y.w, y.w, s2))));
        }
        #pragma unroll
        for (int o = 4; o > 0; o >>= 1) {
            s  += __shfl_xor_sync(0xffffffffu, s,  o);
            s2 += __shfl_xor_sync(0xffffffffu, s2, o);
        }
        if (l8 == 0) {
            float mean = s * (1.0f / 96.0f);
            float var  = fmaf(-mean, mean, s2 * (1.0f / 96.0f));
            stats[row]      = mean;
            stats[64 + row] = rsqrtf(var + 1e-5f);
        }
    }
    __syncthreads();

    for (int idx = tid; idx < 6144; idx += 512) {
        int t = idx / CH, c = idx - t * CH;
        float yv = (Y[t * QS + c] - stats[t]) * stats[64 + t];
        dst[idx] = fmaf(yv, gam[c], beta[c]);
    }
}

// ---------------------------------------------------------------------------
// Input order (setup_inputs dict order):
//   0: x | 1..7: sa1 | 8..14: sa2 | 15..20: ff1 | 21..26: ff2
// ---------------------------------------------------------------------------
extern "C" void kernel_launch(void* const* d_in, const int* in_sizes, int n_in,
                              void* d_out, int out_size) {
    const float* x = (const float*)d_in[0];
    float *imgA, *imgB;
    cudaGetSymbolAddress((void**)&imgA, g_imgA);
    cudaGetSymbolAddress((void**)&imgB, g_imgB);

    cudaFuncSetAttribute(attn_kernel<0>, cudaFuncAttributeMaxDynamicSharedMemorySize, ATTN_SMEM);
    cudaFuncSetAttribute(attn_kernel<1>, cudaFuncAttributeMaxDynamicSharedMemorySize, ATTN_SMEM);
    cudaFuncSetAttribute(ffn_kernel,     cudaFuncAttributeMaxDynamicSharedMemorySize, FFN_SMEM);

    dim3 tb(32, 8);
    dim3 tg(HW / 32, CH / 32, BATCH);

    transpose_in_kernel<<<tg, tb>>>(x, imgA);

    attn_kernel<0><<<NWIN, 512, ATTN_SMEM>>>(
        imgA, imgB,
        (const float*)d_in[1], (const float*)d_in[2], (const float*)d_in[3],
        (const float*)d_in[4], (const float*)d_in[5], (const float*)d_in[6],
        (const float*)d_in[7]);

    ffn_kernel<<<NWIN, 512, FFN_SMEM>>>(
        imgB, imgA,
        (const float*)d_in[15], (const float*)d_in[16], (const float*)d_in[17],
        (const float*)d_in[18], (const float*)d_in[19], (const float*)d_in[20]);

    attn_kernel<1><<<NWIN, 512, ATTN_SMEM>>>(
        imgA, imgB,
        (const float*)d_in[8], (const float*)d_in[9], (const float*)d_in[10],
        (const float*)d_in[11], (const float*)d_in[12], (const float*)d_in[13],
        (const float*)d_in[14]);

    ffn_kernel<<<NWIN, 512, FFN_SMEM>>>(
        imgB, imgA,
        (const float*)d_in[21], (const float*)d_in[22], (const float*)d_in[23],
        (const float*)d_in[24], (const float*)d_in[25], (const float*)d_in[26]);

    transpose_out_kernel<<<tg, tb>>>(imgA, (float*)d_out);
}

// round 11
// speedup vs baseline: 1.3756x; 1.0502x over previous
#include <cuda_runtime.h>
#include <cuda_bf16.h>
#include <math.h>
#include <stdint.h>

#define CH    96
#define HH    192
#define WWI   192
#define HW    (HH*WWI)        // 36864
#define BATCH 4
#define NWIN_PER 576          // 24*24 windows per image
#define NWIN  (BATCH*NWIN_PER)
#define NTOK  64
#define NHEAD 6
#define HDIM  16
#define QS    100             // row stride for 64-row fp32 tiles
#define HS    196             // FFN hidden stride

// 56.6 MB each — static device scratch (no allocations allowed)
__device__ float g_imgA[BATCH*HW*CH];
__device__ float g_imgB[BATCH*HW*CH];

// pre-split bf16 weight planes, TRANSPOSED [N][K]: hi plane + lo plane
#define WS_SA1_QKV   0            // 27648
#define WS_SA1_PROJ  27648        // 9216
#define WS_SA2_QKV   36864        // 27648
#define WS_SA2_PROJ  64512        // 9216
#define WS_FF1_W1    73728        // 18432
#define WS_FF1_W2    92160        // 18432
#define WS_FF2_W1    110592       // 18432
#define WS_FF2_W2    129024       // 18432  -> total 147456
__device__ __align__(16) __nv_bfloat16 g_wh[147456];
__device__ __align__(16) __nv_bfloat16 g_wl[147456];

// ---------------------------------------------------------------------------
// FMA-only exp. Valid for x <= 0 (softmax-shifted logits); clamps at -80.
// ---------------------------------------------------------------------------
__device__ __forceinline__ float fexp(float x) {
    x = fmaxf(x, -80.0f);
    const float L2E = 1.4426950408889634f;
    float t = fmaf(x, L2E, 12582912.0f);
    float n = t - 12582912.0f;
    float f = fmaf(x, L2E, -n);
    float p = 1.5403530393381608e-4f;
    p = fmaf(p, f, 1.3333558146428443e-3f);
    p = fmaf(p, f, 9.6181291076284772e-3f);
    p = fmaf(p, f, 5.5504108664821580e-2f);
    p = fmaf(p, f, 2.4022650695910072e-1f);
    p = fmaf(p, f, 6.9314718055994531e-1f);
    p = fmaf(p, f, 1.0f);
    int e = (int)n;
    float s = __int_as_float((127 + e) << 23);
    return p * s;
}

// ---------------------------------------------------------------------------
// bf16 split helpers + m16n8k16 bf16 MMA (3-term split: err ~2^-18)
// ---------------------------------------------------------------------------
// pack (x0,x1) -> bf16x2 hi + bf16x2 lo ; lo half of reg = x0 (k=2t element)
__device__ __forceinline__ void bfsplit2(float x0, float x1, uint32_t& h2, uint32_t& l2) {
    uint32_t h;
    asm("cvt.rn.bf16x2.f32 %0, %1, %2;" : "=r"(h) : "f"(x1), "f"(x0));
    float h0 = __uint_as_float(h << 16);
    float h1 = __uint_as_float(h & 0xffff0000u);
    uint32_t l;
    asm("cvt.rn.bf16x2.f32 %0, %1, %2;" : "=r"(l) : "f"(x1 - h1), "f"(x0 - h0));
    h2 = h; l2 = l;
}
__device__ __forceinline__ void bfsplit1(float x, __nv_bfloat16& h, __nv_bfloat16& l) {
    h = __float2bfloat16(x);
    l = __float2bfloat16(x - __bfloat162float(h));
}
__device__ __forceinline__ void mma_bf16(float4& d, const uint32_t* a,
                                         uint32_t b0, uint32_t b1) {
    asm volatile("mma.sync.aligned.m16n8k16.row.col.f32.bf16.bf16.f32 "
                 "{%0,%1,%2,%3},{%4,%5,%6,%7},{%8,%9},{%0,%1,%2,%3};"
                 : "+f"(d.x), "+f"(d.y), "+f"(d.z), "+f"(d.w)
                 : "r"(a[0]), "r"(a[1]), "r"(a[2]), "r"(a[3]), "r"(b0), "r"(b1));
}

// C = A(64 x K fp32 smem, stride lda) @ B(pre-split transposed bf16 planes [N][K])
// ldbw = K/2 (32-bit words per N-row). Warp: 16-row m-tile x NT 8-col n-tiles.
template<int NT, int KSTEPS>
__device__ __forceinline__ void mma_gemm_bf16(
    float4* acc, const float* A, int lda, int m0,
    const uint32_t* __restrict__ BH, const uint32_t* __restrict__ BL,
    int ldbw, int n0, int mg, int mt)
{
    #pragma unroll
    for (int ks = 0; ks < KSTEPS; ks++) {
        const int k0 = ks * 16;
        uint32_t ah[4], al[4];
        float2 p;
        p = *(const float2*)&A[(m0 + mg) * lda + k0 + 2 * mt];         bfsplit2(p.x, p.y, ah[0], al[0]);
        p = *(const float2*)&A[(m0 + mg + 8) * lda + k0 + 2 * mt];     bfsplit2(p.x, p.y, ah[1], al[1]);
        p = *(const float2*)&A[(m0 + mg) * lda + k0 + 8 + 2 * mt];     bfsplit2(p.x, p.y, ah[2], al[2]);
        p = *(const float2*)&A[(m0 + mg + 8) * lda + k0 + 8 + 2 * mt]; bfsplit2(p.x, p.y, ah[3], al[3]);
        #pragma unroll
        for (int j = 0; j < NT; j++) {
            int wb = (n0 + j * 8 + mg) * ldbw + ks * 8 + mt;
            uint32_t bh0 = __ldg(BH + wb), bh1 = __ldg(BH + wb + 4);
            uint32_t bl0 = __ldg(BL + wb), bl1 = __ldg(BL + wb + 4);
            mma_bf16(acc[j], ah, bh0, bh1);
            mma_bf16(acc[j], ah, bl0, bl1);
            mma_bf16(acc[j], al, bh0, bh1);
        }
    }
}

// ---------------------------------------------------------------------------
// Weight prep: W[K][N] fp32 -> transposed bf16 planes Wt_hi/Wt_lo [N][K].
// One launch for all 8 matrices (blockIdx.y selects matrix).
// ---------------------------------------------------------------------------
__global__ void split_all_weights(
    const float* s0, const float* s1, const float* s2, const float* s3,
    const float* s4, const float* s5, const float* s6, const float* s7)
{
    const int Ks[8]  = {96, 96, 96, 96, 96, 96, 192, 192};
    const int Ns[8]  = {288, 96, 288, 96, 192, 192, 96, 96};
    const int off[8] = {WS_SA1_QKV, WS_SA1_PROJ, WS_SA2_QKV, WS_SA2_PROJ,
                        WS_FF1_W1, WS_FF2_W1, WS_FF1_W2, WS_FF2_W2};
    int m = blockIdx.y;
    int K = Ks[m], N = Ns[m];
    int idx = blockIdx.x * 256 + threadIdx.x;
    if (idx >= K * N) return;
    const float* src;
    switch (m) {
        case 0: src = s0; break; case 1: src = s1; break;
        case 2: src = s2; break; case 3: src = s3; break;
        case 4: src = s4; break; case 5: src = s5; break;
        case 6: src = s6; break; default: src = s7; break;
    }
    int k = idx / N, n = idx - k * N;
    float x = src[idx];
    __nv_bfloat16 hb, lb;
    bfsplit1(x, hb, lb);
    g_wh[off[m] + n * K + k] = hb;
    g_wl[off[m] + n * K + k] = lb;
}

// ---------------------------------------------------------------------------
// Transposes: [B,C,H,W] <-> [B,HW,C]
// ---------------------------------------------------------------------------
__global__ void transpose_in_kernel(const float* __restrict__ x, float* __restrict__ img) {
    __shared__ float tile[32][33];
    int b = blockIdx.z;
    int hw0 = blockIdx.x * 32, c0 = blockIdx.y * 32;
    const float* src = x + (size_t)b * CH * HW;
    float* dst = img + (size_t)b * HW * CH;
    #pragma unroll
    for (int i = threadIdx.y; i < 32; i += 8)
        tile[i][threadIdx.x] = src[(size_t)(c0 + i) * HW + hw0 + threadIdx.x];
    __syncthreads();
    #pragma unroll
    for (int i = threadIdx.y; i < 32; i += 8)
        dst[(size_t)(hw0 + i) * CH + c0 + threadIdx.x] = tile[threadIdx.x][i];
}

__global__ void transpose_out_kernel(const float* __restrict__ img, float* __restrict__ x) {
    __shared__ float tile[32][33];
    int b = blockIdx.z;
    int hw0 = blockIdx.x * 32, c0 = blockIdx.y * 32;
    const float* src = img + (size_t)b * HW * CH;
    float* dst = x + (size_t)b * CH * HW;
    #pragma unroll
    for (int i = threadIdx.y; i < 32; i += 8)
        tile[i][threadIdx.x] = src[(size_t)(hw0 + i) * CH + c0 + threadIdx.x];
    __syncthreads();
    #pragma unroll
    for (int i = threadIdx.y; i < 32; i += 8)
        dst[(size_t)(c0 + i) * HW + hw0 + threadIdx.x] = tile[threadIdx.x][i];
}

// ---------------------------------------------------------------------------
// Fused window attention, all matmuls bf16 m16n8k16 3-term.
// smem: Xs 6400f | Ob 6400f | S 8704f (reused as Y) | Tb 1360f | stats 128f |
//       Cnt 64i | QH/QL/KH/KL 3200w each | VH/VL 3456w each  = 171072 B
// Q/K planes: [tok][dim] bf16, row stride 50 words (conflict-free).
// V planes:   [dim][tok] bf16, row stride 36 words (conflict-free).
// ---------------------------------------------------------------------------
#define ATTN_SMEM 171072

template<int SHIFTED>
__global__ void __launch_bounds__(512, 1) attn_kernel(
    const float* __restrict__ in, float* __restrict__ out,
    const uint32_t* __restrict__ WQH, const uint32_t* __restrict__ WQL,
    const float* __restrict__ bqkv, const float* __restrict__ table,
    const uint32_t* __restrict__ WPH, const uint32_t* __restrict__ WPL,
    const float* __restrict__ bproj, const float* __restrict__ gam,
    const float* __restrict__ beta)
{
    extern __shared__ float sm[];
    float* Xs    = sm;                   // 6400
    float* Ob    = Xs + 6400;            // 6400
    float* S     = Ob + 6400;            // 8704 (2 x 64 x 68); later Y
    float* Tb    = S + 8704;             // 1360
    float* stats = Tb + 1360;            // 128
    int*   Cnt   = (int*)(stats + 128);  // 64
    uint32_t* QH = (uint32_t*)(Cnt + 64);// 3200 words (64 x 50)
    uint32_t* QL = QH + 3200;
    uint32_t* KH = QL + 3200;
    uint32_t* KL = KH + 3200;
    uint32_t* VH = KL + 3200;            // 3456 words (96 x 36)
    uint32_t* VL = VH + 3456;
    __nv_bfloat16* VHs = (__nv_bfloat16*)VH;  // [dim][tok], row stride 72 halves
    __nv_bfloat16* VLs = (__nv_bfloat16*)VL;

    const int tid = threadIdx.x;
    const int wid = blockIdx.x;
    const int b  = wid / NWIN_PER;
    const int wl = wid - b * NWIN_PER;
    const int wr = wl / 24, wc = wl - (wl / 24) * 24;
    const float* src = in  + (size_t)b * HW * CH;
    float*       dst = out + (size_t)b * HW * CH;

    // ---- gather window tokens + stage table + region ids ----
    for (int idx = tid; idx < NTOK * CH; idx += 512) {
        int t = idx / CH, c = idx - t * CH;
        int r = t >> 3, cl = t & 7;
        int h = wr * 8 + r, w = wc * 8 + cl;
        if (SHIFTED) { h += 4; if (h >= HH) h -= HH; w += 4; if (w >= WWI) w -= WWI; }
        Xs[t * QS + c] = src[(h * WWI + w) * CH + c];
    }
    for (int idx = tid; idx < 1350; idx += 512) Tb[idx] = table[idx];
    if (tid < 64) {
        int ri = tid >> 3, ci = tid & 7;
        Cnt[tid] = SHIFTED ? (((wr == 23) ? (ri < 4 ? 1 : 2) : 0) * 3
                            + ((wc == 23) ? (ci < 4 ? 1 : 2) : 0)) : 0;
    }
    __syncthreads();

    const int wg = tid >> 5, tx = tid & 31;   // 16 warps
    const int mg = tx >> 2, mt = tx & 3;      // mma lane coords
    const int m0 = (wg & 3) * 16;             // m-tile (QKV/proj)
    const int nch = wg >> 2;                  // n-chunk

    // ---- QKV GEMM: 64x288x96 bf16 mma; epilogue writes split Q/K/V planes --
    {
        float4 acc[9];
        #pragma unroll
        for (int j = 0; j < 9; j++) {
            int c = nch * 72 + j * 8 + 2 * mt;
            float b0 = __ldg(&bqkv[c]), b1 = __ldg(&bqkv[c + 1]);
            acc[j].x = b0; acc[j].y = b1; acc[j].z = b0; acc[j].w = b1;
        }
        mma_gemm_bf16<9, 6>(acc, Xs, QS, m0, WQH, WQL, 48, nch * 72, mg, mt);
        #pragma unroll
        for (int j = 0; j < 9; j++) {
            int cb = nch * 72 + j * 8;        // tile base col (uniform region)
            int c  = cb + 2 * mt;
            int rA = m0 + mg, rB = rA + 8;
            if (cb < 96) {                    // Q plane [tok][dim]
                uint32_t h, l;
                bfsplit2(acc[j].x, acc[j].y, h, l);
                QH[rA * 50 + c / 2] = h; QL[rA * 50 + c / 2] = l;
                bfsplit2(acc[j].z, acc[j].w, h, l);
                QH[rB * 50 + c / 2] = h; QL[rB * 50 + c / 2] = l;
            } else if (cb < 192) {            // K plane [tok][dim]
                int cw = (c - 96) / 2;
                uint32_t h, l;
                bfsplit2(acc[j].x, acc[j].y, h, l);
                KH[rA * 50 + cw] = h; KL[rA * 50 + cw] = l;
                bfsplit2(acc[j].z, acc[j].w, h, l);
                KH[rB * 50 + cw] = h; KL[rB * 50 + cw] = l;
            } else {                          // V transposed plane [dim][tok]
                int d = c - 192;
                __nv_bfloat16 h, l;
                bfsplit1(acc[j].x, h, l); VHs[d * 72 + rA] = h;       VLs[d * 72 + rA] = l;
                bfsplit1(acc[j].y, h, l); VHs[(d + 1) * 72 + rA] = h; VLs[(d + 1) * 72 + rA] = l;
                bfsplit1(acc[j].z, h, l); VHs[d * 72 + rB] = h;       VLs[d * 72 + rB] = l;
                bfsplit1(acc[j].w, h, l); VHs[(d + 1) * 72 + rB] = h; VLs[(d + 1) * 72 + rB] = l;
            }
        }
    }
    __syncthreads();

    // ---- heads: 2 in flight; 8 warps/head: MMA scores + MMA AV ----
    const int hg = wg >> 3;           // head group 0/1
    const int w8 = wg & 7;
    const int hm = w8 & 3;            // m-tile
    const int nh = w8 >> 2;           // n-half / d-half

    for (int it = 0; it < 3; it++) {
        const int hd = it * 2 + hg;
        float* Sg = S + hg * 64 * 68;

        // --- scores: 16 rows x 32 cols of Q@K^T (pure LDS + mma) ---
        {
            float4 acc[4];
            #pragma unroll
            for (int jt = 0; jt < 4; jt++) acc[jt] = make_float4(0.f, 0.f, 0.f, 0.f);
            int qw = (hm * 16 + mg) * 50 + hd * 8 + mt;
            uint32_t ah[4] = {QH[qw], QH[qw + 400], QH[qw + 4], QH[qw + 404]};
            uint32_t al[4] = {QL[qw], QL[qw + 400], QL[qw + 4], QL[qw + 404]};
            #pragma unroll
            for (int jt = 0; jt < 4; jt++) {
                int kw = (nh * 32 + jt * 8 + mg) * 50 + hd * 8 + mt;
                uint32_t bh0 = KH[kw], bh1 = KH[kw + 4];
                uint32_t bl0 = KL[kw], bl1 = KL[kw + 4];
                mma_bf16(acc[jt], ah, bh0, bh1);
                mma_bf16(acc[jt], ah, bl0, bl1);
                mma_bf16(acc[jt], al, bh0, bh1);
            }
            // epilogue: scale + bias + mask -> raw logits in Sg
            int iA = hm * 16 + mg, iB = iA + 8;
            int riA = iA >> 3, ciA = iA & 7, riB = iB >> 3, ciB = iB & 7;
            int cntA = Cnt[iA], cntB = Cnt[iB];
            #pragma unroll
            for (int jt = 0; jt < 4; jt++) {
                int c = nh * 32 + jt * 8 + 2 * mt;
                #pragma unroll
                for (int e = 0; e < 2; e++) {
                    int j = c + e;
                    int rj = j >> 3, cj = j & 7;
                    int cntJ = Cnt[j];
                    float bA = Tb[((riA - rj + 7) * 15 + (ciA - cj + 7)) * 6 + hd];
                    float bB = Tb[((riB - rj + 7) * 15 + (ciB - cj + 7)) * 6 + hd];
                    if (SHIFTED) {
                        if (cntA != cntJ) bA -= 100.f;
                        if (cntB != cntJ) bB -= 100.f;
                    }
                    float vA = (e == 0) ? acc[jt].x : acc[jt].y;
                    float vB = (e == 0) ? acc[jt].z : acc[jt].w;
                    Sg[iA * 68 + j] = fmaf(vA, 0.25f, bA);
                    Sg[iB * 68 + j] = fmaf(vB, 0.25f, bB);
                }
            }
        }
        __syncthreads();

        // --- softmax: 4 threads per row, 128 rows (both heads) ---
        {
            int row = tid >> 2, l4 = tid & 3;
            float* Sr = S + (row >> 6) * 64 * 68 + (row & 63) * 68;
            float4 v[4];
            float mx = -1e30f;
            #pragma unroll
            for (int q = 0; q < 4; q++) {
                v[q] = *(const float4*)&Sr[l4 * 16 + q * 4];
                mx = fmaxf(mx, fmaxf(fmaxf(v[q].x, v[q].y), fmaxf(v[q].z, v[q].w)));
            }
            mx = fmaxf(mx, __shfl_xor_sync(0xffffffffu, mx, 1));
            mx = fmaxf(mx, __shfl_xor_sync(0xffffffffu, mx, 2));
            float ssum = 0.f;
            #pragma unroll
            for (int q = 0; q < 4; q++) {
                v[q].x = fexp(v[q].x - mx); v[q].y = fexp(v[q].y - mx);
                v[q].z = fexp(v[q].z - mx); v[q].w = fexp(v[q].w - mx);
                ssum += (v[q].x + v[q].y) + (v[q].z + v[q].w);
            }
            ssum += __shfl_xor_sync(0xffffffffu, ssum, 1);
            ssum += __shfl_xor_sync(0xffffffffu, ssum, 2);
            float inv = 1.0f / ssum;
            #pragma unroll
            for (int q = 0; q < 4; q++) {
                v[q].x *= inv; v[q].y *= inv; v[q].z *= inv; v[q].w *= inv;
                *(float4*)&Sr[l4 * 16 + q * 4] = v[q];
            }
        }
        __syncthreads();

        // --- AV: 16 rows x 8 dims; A=S (split on the fly), B=V planes ---
        {
            int nc0 = hd * 16 + nh * 8;
            float4 acc = make_float4(0.f, 0.f, 0.f, 0.f);
            #pragma unroll
            for (int ks = 0; ks < 4; ks++) {
                int k0 = ks * 16;
                uint32_t ah[4], al[4];
                float2 p;
                p = *(const float2*)&Sg[(hm * 16 + mg) * 68 + k0 + 2 * mt];         bfsplit2(p.x, p.y, ah[0], al[0]);
                p = *(const float2*)&Sg[(hm * 16 + mg + 8) * 68 + k0 + 2 * mt];     bfsplit2(p.x, p.y, ah[1], al[1]);
                p = *(const float2*)&Sg[(hm * 16 + mg) * 68 + k0 + 8 + 2 * mt];     bfsplit2(p.x, p.y, ah[2], al[2]);
                p = *(const float2*)&Sg[(hm * 16 + mg + 8) * 68 + k0 + 8 + 2 * mt]; bfsplit2(p.x, p.y, ah[3], al[3]);
                int vw = (nc0 + mg) * 36 + ks * 8 + mt;
                uint32_t bh0 = VH[vw], bh1 = VH[vw + 4];
                uint32_t bl0 = VL[vw], bl1 = VL[vw + 4];
                mma_bf16(acc, ah, bh0, bh1);
                mma_bf16(acc, ah, bl0, bl1);
                mma_bf16(acc, al, bh0, bh1);
            }
            int rA = hm * 16 + mg, rB = rA + 8, c = nc0 + 2 * mt;
            Ob[rA * QS + c]     = acc.x;
            Ob[rA * QS + c + 1] = acc.y;
            Ob[rB * QS + c]     = acc.z;
            Ob[rB * QS + c + 1] = acc.w;
        }
        __syncthreads();
    }

    // ---- proj GEMM 64x96x96 bf16 mma + residual; Y overlays S ----
    float* Y = S;
    {
        float4 acc[3];
        #pragma unroll
        for (int j = 0; j < 3; j++) {
            int c = nch * 24 + j * 8 + 2 * mt;
            float b0 = __ldg(&bproj[c]), b1 = __ldg(&bproj[c + 1]);
            acc[j].x = b0; acc[j].y = b1; acc[j].z = b0; acc[j].w = b1;
        }
        mma_gemm_bf16<3, 6>(acc, Ob, QS, m0, WPH, WPL, 48, nch * 24, mg, mt);
        #pragma unroll
        for (int j = 0; j < 3; j++) {
            int c = nch * 24 + j * 8 + 2 * mt;
            int rA = m0 + mg, rB = rA + 8;
            Y[rA * QS + c]     = acc[j].x + Xs[rA * QS + c];
            Y[rA * QS + c + 1] = acc[j].y + Xs[rA * QS + c + 1];
            Y[rB * QS + c]     = acc[j].z + Xs[rB * QS + c];
            Y[rB * QS + c + 1] = acc[j].w + Xs[rB * QS + c + 1];
        }
    }
    __syncthreads();

    // ---- LayerNorm: 8 threads per row ----
    {
        int row = tid >> 3, l8 = tid & 7;
        float s = 0.f, s2 = 0.f;
        #pragma unroll
        for (int q = 0; q < 3; q++) {
            float4 y = *(const float4*)&Y[row * QS + l8 * 12 + q * 4];
            s += (y.x + y.y) + (y.z + y.w);
            s2 = fmaf(y.x, y.x, fmaf(y.y, y.y, fmaf(y.z, y.z, fmaf(y.w, y.w, s2))));
        }
        #pragma unroll
        for (int o = 4; o > 0; o >>= 1) {
            s  += __shfl_xor_sync(0xffffffffu, s,  o);
            s2 += __shfl_xor_sync(0xffffffffu, s2, o);
        }
        if (l8 == 0) {
            float mean = s * (1.0f / 96.0f);
            float var  = fmaf(-mean, mean, s2 * (1.0f / 96.0f));
            stats[row]      = mean;
            stats[64 + row] = rsqrtf(var + 1e-5f);
        }
    }
    __syncthreads();

    // ---- scatter (same coords as gather: roll cancels) ----
    for (int idx = tid; idx < NTOK * CH; idx += 512) {
        int t = idx / CH, c = idx - t * CH;
        int r = t >> 3, cl = t & 7;
        int h = wr * 8 + r, w = wc * 8 + cl;
        if (SHIFTED) { h += 4; if (h >= HH) h -= HH; w += 4; if (w >= WWI) w -= WWI; }
        float yv = (Y[t * QS + c] - stats[t]) * stats[64 + t];
        dst[(h * WWI + w) * CH + c] = fmaf(yv, gam[c], beta[c]);
    }
}

// ---------------------------------------------------------------------------
// Fused FFN: both GEMMs bf16 mma with pre-split transposed weights.
// smem floats: Xs 64x100 | H1 64x196 | Y 64x100 | stats 128 = 25,472
// ---------------------------------------------------------------------------
#define FFN_SMEM (25472 * 4)

__global__ void __launch_bounds__(512, 1) ffn_kernel(
    const float* __restrict__ in, float* __restrict__ out,
    const uint32_t* __restrict__ W1H, const uint32_t* __restrict__ W1L,
    const float* __restrict__ b1,
    const uint32_t* __restrict__ W2H, const uint32_t* __restrict__ W2L,
    const float* __restrict__ b2,
    const float* __restrict__ gam, const float* __restrict__ beta)
{
    extern __shared__ float sm[];
    float* Xs    = sm;                  // 64 x QS
    float* H1    = Xs + 64*QS;          // 64 x HS
    float* Y     = H1 + 64*HS;          // 64 x QS
    float* stats = Y + 64*QS;

    const int tid = threadIdx.x;
    const size_t t0 = (size_t)blockIdx.x * 64;
    const float* src = in + t0 * CH;
    float*       dst = out + t0 * CH;

    for (int idx = tid; idx < 6144; idx += 512) {
        int t = idx / CH, c = idx - t * CH;
        Xs[t * QS + c] = src[idx];
    }
    __syncthreads();

    const int wg = tid >> 5, tx = tid & 31;
    const int mg = tx >> 2, mt = tx & 3;
    const int m0 = (wg & 3) * 16;
    const int nch = wg >> 2;

    // GEMM1: 64x192x96 + GELU -> H1
    {
        float4 acc[6];
        #pragma unroll
        for (int j = 0; j < 6; j++) {
            int c = nch * 48 + j * 8 + 2 * mt;
            float v0 = __ldg(&b1[c]), v1 = __ldg(&b1[c + 1]);
            acc[j].x = v0; acc[j].y = v1; acc[j].z = v0; acc[j].w = v1;
        }
        mma_gemm_bf16<6, 6>(acc, Xs, QS, m0, W1H, W1L, 48, nch * 48, mg, mt);
        #pragma unroll
        for (int j = 0; j < 6; j++) {
            int c = nch * 48 + j * 8 + 2 * mt;
            int rA = m0 + mg, rB = rA + 8;
            float v[4] = {acc[j].x, acc[j].y, acc[j].z, acc[j].w};
            int   rr[4] = {rA, rA, rB, rB};
            int   cc[4] = {c, c + 1, c, c + 1};
            #pragma unroll
            for (int e = 0; e < 4; e++) {
                float x = v[e];
                H1[rr[e] * HS + cc[e]] = 0.5f * x * (1.0f + erff(x * 0.70710678118654752f));
            }
        }
    }
    __syncthreads();

    // GEMM2: 64x96x192 + residual -> Y
    {
        float4 acc[3];
        #pragma unroll
        for (int j = 0; j < 3; j++) {
            int c = nch * 24 + j * 8 + 2 * mt;
            float v0 = __ldg(&b2[c]), v1 = __ldg(&b2[c + 1]);
            acc[j].x = v0; acc[j].y = v1; acc[j].z = v0; acc[j].w = v1;
        }
        mma_gemm_bf16<3, 12>(acc, H1, HS, m0, W2H, W2L, 96, nch * 24, mg, mt);
        #pragma unroll
        for (int j = 0; j < 3; j++) {
            int c = nch * 24 + j * 8 + 2 * mt;
            int rA = m0 + mg, rB = rA + 8;
            Y[rA * QS + c]     = acc[j].x + Xs[rA * QS + c];
            Y[rA * QS + c + 1] = acc[j].y + Xs[rA * QS + c + 1];
            Y[rB * QS + c]     = acc[j].z + Xs[rB * QS + c];
            Y[rB * QS + c + 1] = acc[j].w + Xs[rB * QS + c + 1];
        }
    }
    __syncthreads();

    // LayerNorm: 8 threads per row
    {
        int row = tid >> 3, l8 = tid & 7;
        float s = 0.f, s2 = 0.f;
        #pragma unroll
        for (int q = 0; q < 3; q++) {
            float4 y = *(const float4*)&Y[row * QS + l8 * 12 + q * 4];
            s += (y.x + y.y) + (y.z + y.w);
            s2 = fmaf(y.x, y.x, fmaf(y.y, y.y, fmaf(y.z, y.z, fmaf(y.w, y.w, s2))));
        }
        #pragma unroll
        for (int o = 4; o > 0; o >>= 1) {
            s  += __shfl_xor_sync(0xffffffffu, s,  o);
            s2 += __shfl_xor_sync(0xffffffffu, s2, o);
        }
        if (l8 == 0) {
            float mean = s * (1.0f / 96.0f);
            float var  = fmaf(-mean, mean, s2 * (1.0f / 96.0f));
            stats[row]      = mean;
            stats[64 + row] = rsqrtf(var + 1e-5f);
        }
    }
    __syncthreads();

    for (int idx = tid; idx < 6144; idx += 512) {
        int t = idx / CH, c = idx - t * CH;
        float yv = (Y[t * QS + c] - stats[t]) * stats[64 + t];
        dst[idx] = fmaf(yv, gam[c], beta[c]);
    }
}

// ---------------------------------------------------------------------------
// Input order (setup_inputs dict order):
//   0: x | 1..7: sa1 | 8..14: sa2 | 15..20: ff1 | 21..26: ff2
// ---------------------------------------------------------------------------
extern "C" void kernel_launch(void* const* d_in, const int* in_sizes, int n_in,
                              void* d_out, int out_size) {
    const float* x = (const float*)d_in[0];
    float *imgA, *imgB;
    __nv_bfloat16 *wh, *wlp;
    cudaGetSymbolAddress((void**)&imgA, g_imgA);
    cudaGetSymbolAddress((void**)&imgB, g_imgB);
    cudaGetSymbolAddress((void**)&wh,  g_wh);
    cudaGetSymbolAddress((void**)&wlp, g_wl);

    cudaFuncSetAttribute(attn_kernel<0>, cudaFuncAttributeMaxDynamicSharedMemorySize, ATTN_SMEM);
    cudaFuncSetAttribute(attn_kernel<1>, cudaFuncAttributeMaxDynamicSharedMemorySize, ATTN_SMEM);
    cudaFuncSetAttribute(ffn_kernel,     cudaFuncAttributeMaxDynamicSharedMemorySize, FFN_SMEM);

    // one prep launch for all 8 matrices (order matches table in kernel)
    split_all_weights<<<dim3((27648 + 255) / 256, 8), 256>>>(
        (const float*)d_in[1],  (const float*)d_in[4],
        (const float*)d_in[8],  (const float*)d_in[11],
        (const float*)d_in[15], (const float*)d_in[21],
        (const float*)d_in[17], (const float*)d_in[23]);

    dim3 tb(32, 8);
    dim3 tg(HW / 32, CH / 32, BATCH);

    transpose_in_kernel<<<tg, tb>>>(x, imgA);

    #define WW32(off) ((const uint32_t*)(wh + (off))), ((const uint32_t*)(wlp + (off)))

    attn_kernel<0><<<NWIN, 512, ATTN_SMEM>>>(
        imgA, imgB, WW32(WS_SA1_QKV),
        (const float*)d_in[2], (const float*)d_in[3],
        WW32(WS_SA1_PROJ), (const float*)d_in[5],
        (const float*)d_in[6], (const float*)d_in[7]);

    ffn_kernel<<<NWIN, 512, FFN_SMEM>>>(
        imgB, imgA, WW32(WS_FF1_W1), (const float*)d_in[16],
        WW32(WS_FF1_W2), (const float*)d_in[18],
        (const float*)d_in[19], (const float*)d_in[20]);

    attn_kernel<1><<<NWIN, 512, ATTN_SMEM>>>(
        imgA, imgB, WW32(WS_SA2_QKV),
        (const float*)d_in[9], (const float*)d_in[10],
        WW32(WS_SA2_PROJ), (const float*)d_in[12],
        (const float*)d_in[13], (const float*)d_in[14]);

    ffn_kernel<<<NWIN, 512, FFN_SMEM>>>(
        imgB, imgA, WW32(WS_FF2_W1), (const float*)d_in[22],
        WW32(WS_FF2_W2), (const float*)d_in[24],
        (const float*)d_in[25], (const float*)d_in[26]);

    transpose_out_kernel<<<tg, tb>>>(imgA, (float*)d_out);
}

// round 12
// speedup vs baseline: 1.9856x; 1.4435x over previous
#include <cuda_runtime.h>
#include <cuda_bf16.h>
#include <math.h>
#include <stdint.h>

#define CH    96
#define HH    192
#define WWI   192
#define HW    (HH*WWI)        // 36864
#define BATCH 4
#define NWIN_PER 576          // 24*24 windows per image
#define NWIN  (BATCH*NWIN_PER)
#define NTOK  64
#define NHEAD 6
#define HDIM  16
#define QS    100             // row stride for 64-row fp32 tiles
#define HS    196             // FFN hidden stride

// 56.6 MB each — static device scratch (no allocations allowed)
__device__ float g_imgA[BATCH*HW*CH];
__device__ float g_imgB[BATCH*HW*CH];

// fragment-packed bf16 weights: per (n_tile, ks) 32 x uint4{bh0,bh1,bl0,bl1}
// entries per matrix = N*K/4 (uint4)
#define WF_SA1_QKV   0         // 288*96/4 = 6912
#define WF_SA1_PROJ  6912      // 96*96/4  = 2304
#define WF_SA2_QKV   9216
#define WF_SA2_PROJ  16128
#define WF_FF1_W1    18432     // 192*96/4 = 4608
#define WF_FF2_W1    23040
#define WF_FF1_W2    27648     // 96*192/4 = 4608
#define WF_FF2_W2    32256     // -> total 36864
__device__ __align__(16) uint4 g_wfrag[36864];

// ---------------------------------------------------------------------------
// FMA-only exp. Valid for x <= 0 (softmax-shifted logits); clamps at -80.
// ---------------------------------------------------------------------------
__device__ __forceinline__ float fexp(float x) {
    x = fmaxf(x, -80.0f);
    const float L2E = 1.4426950408889634f;
    float t = fmaf(x, L2E, 12582912.0f);
    float n = t - 12582912.0f;
    float f = fmaf(x, L2E, -n);
    float p = 1.5403530393381608e-4f;
    p = fmaf(p, f, 1.3333558146428443e-3f);
    p = fmaf(p, f, 9.6181291076284772e-3f);
    p = fmaf(p, f, 5.5504108664821580e-2f);
    p = fmaf(p, f, 2.4022650695910072e-1f);
    p = fmaf(p, f, 6.9314718055994531e-1f);
    p = fmaf(p, f, 1.0f);
    int e = (int)n;
    float s = __int_as_float((127 + e) << 23);
    return p * s;
}

// ---------------------------------------------------------------------------
// bf16 split helpers + m16n8k16 bf16 MMA (3-term split: err ~2^-18)
// ---------------------------------------------------------------------------
__device__ __forceinline__ void bfsplit2(float x0, float x1, uint32_t& h2, uint32_t& l2) {
    uint32_t h;
    asm("cvt.rn.bf16x2.f32 %0, %1, %2;" : "=r"(h) : "f"(x1), "f"(x0));
    float h0 = __uint_as_float(h << 16);
    float h1 = __uint_as_float(h & 0xffff0000u);
    uint32_t l;
    asm("cvt.rn.bf16x2.f32 %0, %1, %2;" : "=r"(l) : "f"(x1 - h1), "f"(x0 - h0));
    h2 = h; l2 = l;
}
__device__ __forceinline__ void bfsplit1(float x, __nv_bfloat16& h, __nv_bfloat16& l) {
    h = __float2bfloat16(x);
    l = __float2bfloat16(x - __bfloat162float(h));
}
__device__ __forceinline__ void mma_bf16(float4& d, const uint32_t* a,
                                         uint32_t b0, uint32_t b1) {
    asm volatile("mma.sync.aligned.m16n8k16.row.col.f32.bf16.bf16.f32 "
                 "{%0,%1,%2,%3},{%4,%5,%6,%7},{%8,%9},{%0,%1,%2,%3};"
                 : "+f"(d.x), "+f"(d.y), "+f"(d.z), "+f"(d.w)
                 : "r"(a[0]), "r"(a[1]), "r"(a[2]), "r"(a[3]), "r"(b0), "r"(b1));
}

// C = A(64 x K fp32 smem, stride lda) @ B(fragment-packed uint4 planes)
// Bf indexed by ((nt0 + j) * KST + ks) * 32 + lane.
template<int NT, int KST>
__device__ __forceinline__ void mma_gemm_bf16(
    float4* acc, const float* A, int lda, int m0,
    const uint4* __restrict__ Bf, int nt0, int mg, int mt, int tx)
{
    #pragma unroll
    for (int ks = 0; ks < KST; ks++) {
        const int k0 = ks * 16;
        uint32_t ah[4], al[4];
        float2 p;
        p = *(const float2*)&A[(m0 + mg) * lda + k0 + 2 * mt];         bfsplit2(p.x, p.y, ah[0], al[0]);
        p = *(const float2*)&A[(m0 + mg + 8) * lda + k0 + 2 * mt];     bfsplit2(p.x, p.y, ah[1], al[1]);
        p = *(const float2*)&A[(m0 + mg) * lda + k0 + 8 + 2 * mt];     bfsplit2(p.x, p.y, ah[2], al[2]);
        p = *(const float2*)&A[(m0 + mg + 8) * lda + k0 + 8 + 2 * mt]; bfsplit2(p.x, p.y, ah[3], al[3]);
        #pragma unroll
        for (int j = 0; j < NT; j++) {
            uint4 w = __ldg(&Bf[((nt0 + j) * KST + ks) * 32 + tx]);
            mma_bf16(acc[j], ah, w.x, w.y);
            mma_bf16(acc[j], ah, w.z, w.w);
            mma_bf16(acc[j], al, w.x, w.y);
        }
    }
}

// ---------------------------------------------------------------------------
// Weight prep: W[K][N] fp32 -> fragment-packed uint4 per (n_tile, ks, lane).
// ---------------------------------------------------------------------------
__global__ void split_all_weights(
    const float* s0, const float* s1, const float* s2, const float* s3,
    const float* s4, const float* s5, const float* s6, const float* s7)
{
    const int Ks[8]  = {96, 96, 96, 96, 96, 96, 192, 192};
    const int Ns[8]  = {288, 96, 288, 96, 192, 192, 96, 96};
    const int off[8] = {WF_SA1_QKV, WF_SA1_PROJ, WF_SA2_QKV, WF_SA2_PROJ,
                        WF_FF1_W1, WF_FF2_W1, WF_FF1_W2, WF_FF2_W2};
    int m = blockIdx.y;
    int K = Ks[m], N = Ns[m];
    int KST = K / 16;
    int total = (N / 8) * KST * 32;
    int e = blockIdx.x * 256 + threadIdx.x;
    if (e >= total) return;
    const float* src;
    switch (m) {
        case 0: src = s0; break; case 1: src = s1; break;
        case 2: src = s2; break; case 3: src = s3; break;
        case 4: src = s4; break; case 5: src = s5; break;
        case 6: src = s6; break; default: src = s7; break;
    }
    int lane  = e & 31;
    int ks    = (e >> 5) % KST;
    int ntile = e / (32 * KST);
    int mg = lane >> 2, mt = lane & 3;
    int n  = ntile * 8 + mg;
    int k0 = ks * 16;
    float x0 = src[(k0 + 2 * mt)     * N + n];
    float x1 = src[(k0 + 2 * mt + 1) * N + n];
    float x2 = src[(k0 + 8 + 2 * mt)     * N + n];
    float x3 = src[(k0 + 8 + 2 * mt + 1) * N + n];
    uint32_t bh0, bl0, bh1, bl1;
    bfsplit2(x0, x1, bh0, bl0);
    bfsplit2(x2, x3, bh1, bl1);
    g_wfrag[off[m] + e] = make_uint4(bh0, bh1, bl0, bl1);
}

// ---------------------------------------------------------------------------
// Transposes: [B,C,H,W] <-> [B,HW,C]
// ---------------------------------------------------------------------------
__global__ void transpose_in_kernel(const float* __restrict__ x, float* __restrict__ img) {
    __shared__ float tile[32][33];
    int b = blockIdx.z;
    int hw0 = blockIdx.x * 32, c0 = blockIdx.y * 32;
    const float* src = x + (size_t)b * CH * HW;
    float* dst = img + (size_t)b * HW * CH;
    #pragma unroll
    for (int i = threadIdx.y; i < 32; i += 8)
        tile[i][threadIdx.x] = src[(size_t)(c0 + i) * HW + hw0 + threadIdx.x];
    __syncthreads();
    #pragma unroll
    for (int i = threadIdx.y; i < 32; i += 8)
        dst[(size_t)(hw0 + i) * CH + c0 + threadIdx.x] = tile[threadIdx.x][i];
}

__global__ void transpose_out_kernel(const float* __restrict__ img, float* __restrict__ x) {
    __shared__ float tile[32][33];
    int b = blockIdx.z;
    int hw0 = blockIdx.x * 32, c0 = blockIdx.y * 32;
    const float* src = img + (size_t)b * HW * CH;
    float* dst = x + (size_t)b * CH * HW;
    #pragma unroll
    for (int i = threadIdx.y; i < 32; i += 8)
        tile[i][threadIdx.x] = src[(size_t)(hw0 + i) * CH + c0 + threadIdx.x];
    __syncthreads();
    #pragma unroll
    for (int i = threadIdx.y; i < 32; i += 8)
        dst[(size_t)(c0 + i) * HW + hw0 + threadIdx.x] = tile[threadIdx.x][i];
}

// ---------------------------------------------------------------------------
// Fused window attention, all matmuls bf16 m16n8k16 3-term; weight GEMMs use
// fragment-packed uint4 LDG.128.
// smem: Xs 6400f | Ob 6400f | S 8704f (reused as Y) | Tb 1360f | stats 128f |
//       Cnt 64i | QH/QL/KH/KL 3200w each | VH/VL 3456w each  = 171072 B
// ---------------------------------------------------------------------------
#define ATTN_SMEM 171072

template<int SHIFTED>
__global__ void __launch_bounds__(512, 1) attn_kernel(
    const float* __restrict__ in, float* __restrict__ out,
    const uint4* __restrict__ WQF, const float* __restrict__ bqkv,
    const float* __restrict__ table,
    const uint4* __restrict__ WPF, const float* __restrict__ bproj,
    const float* __restrict__ gam, const float* __restrict__ beta)
{
    extern __shared__ float sm[];
    float* Xs    = sm;                   // 6400
    float* Ob    = Xs + 6400;            // 6400
    float* S     = Ob + 6400;            // 8704 (2 x 64 x 68); later Y
    float* Tb    = S + 8704;             // 1360
    float* stats = Tb + 1360;            // 128
    int*   Cnt   = (int*)(stats + 128);  // 64
    uint32_t* QH = (uint32_t*)(Cnt + 64);// 3200 words (64 x 50)
    uint32_t* QL = QH + 3200;
    uint32_t* KH = QL + 3200;
    uint32_t* KL = KH + 3200;
    uint32_t* VH = KL + 3200;            // 3456 words (96 x 36)
    uint32_t* VL = VH + 3456;
    __nv_bfloat16* VHs = (__nv_bfloat16*)VH;  // [dim][tok], row stride 72
    __nv_bfloat16* VLs = (__nv_bfloat16*)VL;

    const int tid = threadIdx.x;
    const int wid = blockIdx.x;
    const int b  = wid / NWIN_PER;
    const int wl = wid - b * NWIN_PER;
    const int wr = wl / 24, wc = wl - (wl / 24) * 24;
    const float* src = in  + (size_t)b * HW * CH;
    float*       dst = out + (size_t)b * HW * CH;

    // ---- gather window tokens + stage table + region ids ----
    for (int idx = tid; idx < NTOK * CH; idx += 512) {
        int t = idx / CH, c = idx - t * CH;
        int r = t >> 3, cl = t & 7;
        int h = wr * 8 + r, w = wc * 8 + cl;
        if (SHIFTED) { h += 4; if (h >= HH) h -= HH; w += 4; if (w >= WWI) w -= WWI; }
        Xs[t * QS + c] = src[(h * WWI + w) * CH + c];
    }
    for (int idx = tid; idx < 1350; idx += 512) Tb[idx] = table[idx];
    if (tid < 64) {
        int ri = tid >> 3, ci = tid & 7;
        Cnt[tid] = SHIFTED ? (((wr == 23) ? (ri < 4 ? 1 : 2) : 0) * 3
                            + ((wc == 23) ? (ci < 4 ? 1 : 2) : 0)) : 0;
    }
    __syncthreads();

    const int wg = tid >> 5, tx = tid & 31;   // 16 warps
    const int mg = tx >> 2, mt = tx & 3;      // mma lane coords
    const int m0 = (wg & 3) * 16;             // m-tile (QKV/proj)
    const int nch = wg >> 2;                  // n-chunk

    // ---- QKV GEMM: 64x288x96 bf16 mma; epilogue writes split Q/K/V planes --
    {
        float4 acc[9];
        #pragma unroll
        for (int j = 0; j < 9; j++) {
            int c = nch * 72 + j * 8 + 2 * mt;
            float b0 = __ldg(&bqkv[c]), b1 = __ldg(&bqkv[c + 1]);
            acc[j].x = b0; acc[j].y = b1; acc[j].z = b0; acc[j].w = b1;
        }
        mma_gemm_bf16<9, 6>(acc, Xs, QS, m0, WQF, nch * 9, mg, mt, tx);
        #pragma unroll
        for (int j = 0; j < 9; j++) {
            int cb = nch * 72 + j * 8;        // tile base col (uniform region)
            int c  = cb + 2 * mt;
            int rA = m0 + mg, rB = rA + 8;
            if (cb < 96) {                    // Q plane [tok][dim]
                uint32_t h, l;
                bfsplit2(acc[j].x, acc[j].y, h, l);
                QH[rA * 50 + c / 2] = h; QL[rA * 50 + c / 2] = l;
                bfsplit2(acc[j].z, acc[j].w, h, l);
                QH[rB * 50 + c / 2] = h; QL[rB * 50 + c / 2] = l;
            } else if (cb < 192) {            // K plane [tok][dim]
                int cw = (c - 96) / 2;
                uint32_t h, l;
                bfsplit2(acc[j].x, acc[j].y, h, l);
                KH[rA * 50 + cw] = h; KL[rA * 50 + cw] = l;
                bfsplit2(acc[j].z, acc[j].w, h, l);
                KH[rB * 50 + cw] = h; KL[rB * 50 + cw] = l;
            } else {                          // V transposed plane [dim][tok]
                int d = c - 192;
                __nv_bfloat16 h, l;
                bfsplit1(acc[j].x, h, l); VHs[d * 72 + rA] = h;       VLs[d * 72 + rA] = l;
                bfsplit1(acc[j].y, h, l); VHs[(d + 1) * 72 + rA] = h; VLs[(d + 1) * 72 + rA] = l;
                bfsplit1(acc[j].z, h, l); VHs[d * 72 + rB] = h;       VLs[d * 72 + rB] = l;
                bfsplit1(acc[j].w, h, l); VHs[(d + 1) * 72 + rB] = h; VLs[(d + 1) * 72 + rB] = l;
            }
        }
    }
    __syncthreads();

    // ---- heads: 2 in flight; 8 warps/head: MMA scores + MMA AV ----
    const int hg = wg >> 3;
    const int w8 = wg & 7;
    const int hm = w8 & 3;
    const int nh = w8 >> 2;

    for (int it = 0; it < 3; it++) {
        const int hd = it * 2 + hg;
        float* Sg = S + hg * 64 * 68;

        // --- scores: 16 rows x 32 cols of Q@K^T (pure LDS + mma) ---
        {
            float4 acc[4];
            #pragma unroll
            for (int jt = 0; jt < 4; jt++) acc[jt] = make_float4(0.f, 0.f, 0.f, 0.f);
            int qw = (hm * 16 + mg) * 50 + hd * 8 + mt;
            uint32_t ah[4] = {QH[qw], QH[qw + 400], QH[qw + 4], QH[qw + 404]};
            uint32_t al[4] = {QL[qw], QL[qw + 400], QL[qw + 4], QL[qw + 404]};
            #pragma unroll
            for (int jt = 0; jt < 4; jt++) {
                int kw = (nh * 32 + jt * 8 + mg) * 50 + hd * 8 + mt;
                uint32_t bh0 = KH[kw], bh1 = KH[kw + 4];
                uint32_t bl0 = KL[kw], bl1 = KL[kw + 4];
                mma_bf16(acc[jt], ah, bh0, bh1);
                mma_bf16(acc[jt], ah, bl0, bl1);
                mma_bf16(acc[jt], al, bh0, bh1);
            }
            int iA = hm * 16 + mg, iB = iA + 8;
            int riA = iA >> 3, ciA = iA & 7, riB = iB >> 3, ciB = iB & 7;
            int cntA = Cnt[iA], cntB = Cnt[iB];
            #pragma unroll
            for (int jt = 0; jt < 4; jt++) {
                int c = nh * 32 + jt * 8 + 2 * mt;
                #pragma unroll
                for (int e = 0; e < 2; e++) {
                    int j = c + e;
                    int rj = j >> 3, cj = j & 7;
                    int cntJ = Cnt[j];
                    float bA = Tb[((riA - rj + 7) * 15 + (ciA - cj + 7)) * 6 + hd];
                    float bB = Tb[((riB - rj + 7) * 15 + (ciB - cj + 7)) * 6 + hd];
                    if (SHIFTED) {
                        if (cntA != cntJ) bA -= 100.f;
                        if (cntB != cntJ) bB -= 100.f;
                    }
                    float vA = (e == 0) ? acc[jt].x : acc[jt].y;
                    float vB = (e == 0) ? acc[jt].z : acc[jt].w;
                    Sg[iA * 68 + j] = fmaf(vA, 0.25f, bA);
                    Sg[iB * 68 + j] = fmaf(vB, 0.25f, bB);
                }
            }
        }
        __syncthreads();

        // --- softmax: 4 threads per row, 128 rows ---
        {
            int row = tid >> 2, l4 = tid & 3;
            float* Sr = S + (row >> 6) * 64 * 68 + (row & 63) * 68;
            float4 v[4];
            float mx = -1e30f;
            #pragma unroll
            for (int q = 0; q < 4; q++) {
                v[q] = *(const float4*)&Sr[l4 * 16 + q * 4];
                mx = fmaxf(mx, fmaxf(fmaxf(v[q].x, v[q].y), fmaxf(v[q].z, v[q].w)));
            }
            mx = fmaxf(mx, __shfl_xor_sync(0xffffffffu, mx, 1));
            mx = fmaxf(mx, __shfl_xor_sync(0xffffffffu, mx, 2));
            float ssum = 0.f;
            #pragma unroll
            for (int q = 0; q < 4; q++) {
                v[q].x = fexp(v[q].x - mx); v[q].y = fexp(v[q].y - mx);
                v[q].z = fexp(v[q].z - mx); v[q].w = fexp(v[q].w - mx);
                ssum += (v[q].x + v[q].y) + (v[q].z + v[q].w);
            }
            ssum += __shfl_xor_sync(0xffffffffu, ssum, 1);
            ssum += __shfl_xor_sync(0xffffffffu, ssum, 2);
            float inv = 1.0f / ssum;
            #pragma unroll
            for (int q = 0; q < 4; q++) {
                v[q].x *= inv; v[q].y *= inv; v[q].z *= inv; v[q].w *= inv;
                *(float4*)&Sr[l4 * 16 + q * 4] = v[q];
            }
        }
        __syncthreads();

        // --- AV: 16 rows x 8 dims; A=S (split on the fly), B=V planes ---
        {
            int nc0 = hd * 16 + nh * 8;
            float4 acc = make_float4(0.f, 0.f, 0.f, 0.f);
            #pragma unroll
            for (int ks = 0; ks < 4; ks++) {
                int k0 = ks * 16;
                uint32_t ah[4], al[4];
                float2 p;
                p = *(const float2*)&Sg[(hm * 16 + mg) * 68 + k0 + 2 * mt];         bfsplit2(p.x, p.y, ah[0], al[0]);
                p = *(const float2*)&Sg[(hm * 16 + mg + 8) * 68 + k0 + 2 * mt];     bfsplit2(p.x, p.y, ah[1], al[1]);
                p = *(const float2*)&Sg[(hm * 16 + mg) * 68 + k0 + 8 + 2 * mt];     bfsplit2(p.x, p.y, ah[2], al[2]);
                p = *(const float2*)&Sg[(hm * 16 + mg + 8) * 68 + k0 + 8 + 2 * mt]; bfsplit2(p.x, p.y, ah[3], al[3]);
                int vw = (nc0 + mg) * 36 + ks * 8 + mt;
                uint32_t bh0 = VH[vw], bh1 = VH[vw + 4];
                uint32_t bl0 = VL[vw], bl1 = VL[vw + 4];
                mma_bf16(acc, ah, bh0, bh1);
                mma_bf16(acc, ah, bl0, bl1);
                mma_bf16(acc, al, bh0, bh1);
            }
            int rA = hm * 16 + mg, rB = rA + 8, c = nc0 + 2 * mt;
            Ob[rA * QS + c]     = acc.x;
            Ob[rA * QS + c + 1] = acc.y;
            Ob[rB * QS + c]     = acc.z;
            Ob[rB * QS + c + 1] = acc.w;
        }
        __syncthreads();
    }

    // ---- proj GEMM 64x96x96 bf16 mma + residual; Y overlays S ----
    float* Y = S;
    {
        float4 acc[3];
        #pragma unroll
        for (int j = 0; j < 3; j++) {
            int c = nch * 24 + j * 8 + 2 * mt;
            float b0 = __ldg(&bproj[c]), b1 = __ldg(&bproj[c + 1]);
            acc[j].x = b0; acc[j].y = b1; acc[j].z = b0; acc[j].w = b1;
        }
        mma_gemm_bf16<3, 6>(acc, Ob, QS, m0, WPF, nch * 3, mg, mt, tx);
        #pragma unroll
        for (int j = 0; j < 3; j++) {
            int c = nch * 24 + j * 8 + 2 * mt;
            int rA = m0 + mg, rB = rA + 8;
            Y[rA * QS + c]     = acc[j].x + Xs[rA * QS + c];
            Y[rA * QS + c + 1] = acc[j].y + Xs[rA * QS + c + 1];
            Y[rB * QS + c]     = acc[j].z + Xs[rB * QS + c];
            Y[rB * QS + c + 1] = acc[j].w + Xs[rB * QS + c + 1];
        }
    }
    __syncthreads();

    // ---- LayerNorm: 8 threads per row ----
    {
        int row = tid >> 3, l8 = tid & 7;
        float s = 0.f, s2 = 0.f;
        #pragma unroll
        for (int q = 0; q < 3; q++) {
            float4 y = *(const float4*)&Y[row * QS + l8 * 12 + q * 4];
            s += (y.x + y.y) + (y.z + y.w);
            s2 = fmaf(y.x, y.x, fmaf(y.y, y.y, fmaf(y.z, y.z, fmaf(y.w, y.w, s2))));
        }
        #pragma unroll
        for (int o = 4; o > 0; o >>= 1) {
            s  += __shfl_xor_sync(0xffffffffu, s,  o);
            s2 += __shfl_xor_sync(0xffffffffu, s2, o);
        }
        if (l8 == 0) {
            float mean = s * (1.0f / 96.0f);
            float var  = fmaf(-mean, mean, s2 * (1.0f / 96.0f));
            stats[row]      = mean;
            stats[64 + row] = rsqrtf(var + 1e-5f);
        }
    }
    __syncthreads();

    // ---- scatter (same coords as gather: roll cancels) ----
    for (int idx = tid; idx < NTOK * CH; idx += 512) {
        int t = idx / CH, c = idx - t * CH;
        int r = t >> 3, cl = t & 7;
        int h = wr * 8 + r, w = wc * 8 + cl;
        if (SHIFTED) { h += 4; if (h >= HH) h -= HH; w += 4; if (w >= WWI) w -= WWI; }
        float yv = (Y[t * QS + c] - stats[t]) * stats[64 + t];
        dst[(h * WWI + w) * CH + c] = fmaf(yv, gam[c], beta[c]);
    }
}

// ---------------------------------------------------------------------------
// Fused FFN: both GEMMs bf16 mma with fragment-packed weights (LDG.128).
// smem floats: Xs 64x100 | H1 64x196 | Y 64x100 | stats 128 = 25,472
// ---------------------------------------------------------------------------
#define FFN_SMEM (25472 * 4)

__global__ void __launch_bounds__(512, 1) ffn_kernel(
    const float* __restrict__ in, float* __restrict__ out,
    const uint4* __restrict__ W1F, const float* __restrict__ b1,
    const uint4* __restrict__ W2F, const float* __restrict__ b2,
    const float* __restrict__ gam, const float* __restrict__ beta)
{
    extern __shared__ float sm[];
    float* Xs    = sm;                  // 64 x QS
    float* H1    = Xs + 64*QS;          // 64 x HS
    float* Y     = H1 + 64*HS;          // 64 x QS
    float* stats = Y + 64*QS;

    const int tid = threadIdx.x;
    const size_t t0 = (size_t)blockIdx.x * 64;
    const float* src = in + t0 * CH;
    float*       dst = out + t0 * CH;

    for (int idx = tid; idx < 6144; idx += 512) {
        int t = idx / CH, c = idx - t * CH;
        Xs[t * QS + c] = src[idx];
    }
    __syncthreads();

    const int wg = tid >> 5, tx = tid & 31;
    const int mg = tx >> 2, mt = tx & 3;
    const int m0 = (wg & 3) * 16;
    const int nch = wg >> 2;

    // GEMM1: 64x192x96 + GELU -> H1
    {
        float4 acc[6];
        #pragma unroll
        for (int j = 0; j < 6; j++) {
            int c = nch * 48 + j * 8 + 2 * mt;
            float v0 = __ldg(&b1[c]), v1 = __ldg(&b1[c + 1]);
            acc[j].x = v0; acc[j].y = v1; acc[j].z = v0; acc[j].w = v1;
        }
        mma_gemm_bf16<6, 6>(acc, Xs, QS, m0, W1F, nch * 6, mg, mt, tx);
        #pragma unroll
        for (int j = 0; j < 6; j++) {
            int c = nch * 48 + j * 8 + 2 * mt;
            int rA = m0 + mg, rB = rA + 8;
            float v[4] = {acc[j].x, acc[j].y, acc[j].z, acc[j].w};
            int   rr[4] = {rA, rA, rB, rB};
            int   cc[4] = {c, c + 1, c, c + 1};
            #pragma unroll
            for (int e = 0; e < 4; e++) {
                float x = v[e];
                H1[rr[e] * HS + cc[e]] = 0.5f * x * (1.0f + erff(x * 0.70710678118654752f));
            }
        }
    }
    __syncthreads();

    // GEMM2: 64x96x192 + residual -> Y
    {
        float4 acc[3];
        #pragma unroll
        for (int j = 0; j < 3; j++) {
            int c = nch * 24 + j * 8 + 2 * mt;
            float v0 = __ldg(&b2[c]), v1 = __ldg(&b2[c + 1]);
            acc[j].x = v0; acc[j].y = v1; acc[j].z = v0; acc[j].w = v1;
        }
        mma_gemm_bf16<3, 12>(acc, H1, HS, m0, W2F, nch * 3, mg, mt, tx);
        #pragma unroll
        for (int j = 0; j < 3; j++) {
            int c = nch * 24 + j * 8 + 2 * mt;
            int rA = m0 + mg, rB = rA + 8;
            Y[rA * QS + c]     = acc[j].x + Xs[rA * QS + c];
            Y[rA * QS + c + 1] = acc[j].y + Xs[rA * QS + c + 1];
            Y[rB * QS + c]     = acc[j].z + Xs[rB * QS + c];
            Y[rB * QS + c + 1] = acc[j].w + Xs[rB * QS + c + 1];
        }
    }
    __syncthreads();

    // LayerNorm: 8 threads per row
    {
        int row = tid >> 3, l8 = tid & 7;
        float s = 0.f, s2 = 0.f;
        #pragma unroll
        for (int q = 0; q < 3; q++) {
            float4 y = *(const float4*)&Y[row * QS + l8 * 12 + q * 4];
            s += (y.x + y.y) + (y.z + y.w);
            s2 = fmaf(y.x, y.x, fmaf(y.y, y.y, fmaf(y.z, y.z, fmaf(y.w, y.w, s2))));
        }
        #pragma unroll
        for (int o = 4; o > 0; o >>= 1) {
            s  += __shfl_xor_sync(0xffffffffu, s,  o);
            s2 += __shfl_xor_sync(0xffffffffu, s2, o);
        }
        if (l8 == 0) {
            float mean = s * (1.0f / 96.0f);
            float var  = fmaf(-mean, mean, s2 * (1.0f / 96.0f));
            stats[row]      = mean;
            stats[64 + row] = rsqrtf(var + 1e-5f);
        }
    }
    __syncthreads();

    for (int idx = tid; idx < 6144; idx += 512) {
        int t = idx / CH, c = idx - t * CH;
        float yv = (Y[t * QS + c] - stats[t]) * stats[64 + t];
        dst[idx] = fmaf(yv, gam[c], beta[c]);
    }
}

// ---------------------------------------------------------------------------
// Input order (setup_inputs dict order):
//   0: x | 1..7: sa1 | 8..14: sa2 | 15..20: ff1 | 21..26: ff2
// ---------------------------------------------------------------------------
extern "C" void kernel_launch(void* const* d_in, const int* in_sizes, int n_in,
                              void* d_out, int out_size) {
    const float* x = (const float*)d_in[0];
    float *imgA, *imgB;
    uint4* wf;
    cudaGetSymbolAddress((void**)&imgA, g_imgA);
    cudaGetSymbolAddress((void**)&imgB, g_imgB);
    cudaGetSymbolAddress((void**)&wf,   g_wfrag);

    cudaFuncSetAttribute(attn_kernel<0>, cudaFuncAttributeMaxDynamicSharedMemorySize, ATTN_SMEM);
    cudaFuncSetAttribute(attn_kernel<1>, cudaFuncAttributeMaxDynamicSharedMemorySize, ATTN_SMEM);
    cudaFuncSetAttribute(ffn_kernel,     cudaFuncAttributeMaxDynamicSharedMemorySize, FFN_SMEM);

    // one prep launch for all 8 matrices (max entries 6912 -> 27 blocks)
    split_all_weights<<<dim3(27, 8), 256>>>(
        (const float*)d_in[1],  (const float*)d_in[4],
        (const float*)d_in[8],  (const float*)d_in[11],
        (const float*)d_in[15], (const float*)d_in[21],
        (const float*)d_in[17], (const float*)d_in[23]);

    dim3 tb(32, 8);
    dim3 tg(HW / 32, CH / 32, BATCH);

    transpose_in_kernel<<<tg, tb>>>(x, imgA);

    attn_kernel<0><<<NWIN, 512, ATTN_SMEM>>>(
        imgA, imgB, wf + WF_SA1_QKV,
        (const float*)d_in[2], (const float*)d_in[3],
        wf + WF_SA1_PROJ, (const float*)d_in[5],
        (const float*)d_in[6], (const float*)d_in[7]);

    ffn_kernel<<<NWIN, 512, FFN_SMEM>>>(
        imgB, imgA, wf + WF_FF1_W1, (const float*)d_in[16],
        wf + WF_FF1_W2, (const float*)d_in[18],
        (const float*)d_in[19], (const float*)d_in[20]);

    attn_kernel<1><<<NWIN, 512, ATTN_SMEM>>>(
        imgA, imgB, wf + WF_SA2_QKV,
        (const float*)d_in[9], (const float*)d_in[10],
        wf + WF_SA2_PROJ, (const float*)d_in[12],
        (const float*)d_in[13], (const float*)d_in[14]);

    ffn_kernel<<<NWIN, 512, FFN_SMEM>>>(
        imgB, imgA, wf + WF_FF2_W1, (const float*)d_in[22],
        wf + WF_FF2_W2, (const float*)d_in[24],
        (const float*)d_in[25], (const float*)d_in[26]);

    transpose_out_kernel<<<tg, tb>>>(imgA, (float*)d_out);
}

// round 13
// speedup vs baseline: 2.2047x; 1.1103x over previous
#include <cuda_runtime.h>
#include <cuda_bf16.h>
#include <math.h>
#include <stdint.h>

#define CH    96
#define HH    192
#define WWI   192
#define HW    (HH*WWI)        // 36864
#define BATCH 4
#define NWIN_PER 576          // 24*24 windows per image
#define NWIN  (BATCH*NWIN_PER)
#define NTOK  64
#define QS    100             // fp32 row stride (Y)

// 56.6 MB each — static device scratch (no allocations allowed)
__device__ float g_imgA[BATCH*HW*CH];
__device__ float g_imgB[BATCH*HW*CH];

// fragment-packed bf16 weights: per (n_tile, ks) 32 x uint4{bh0,bh1,bl0,bl1}
#define WF_SA1_QKV   0         // 288*96/4 = 6912
#define WF_SA1_PROJ  6912      // 96*96/4  = 2304
#define WF_SA2_QKV   9216
#define WF_SA2_PROJ  16128
#define WF_FF1_W1    18432     // 192*96/4 = 4608
#define WF_FF2_W1    23040
#define WF_FF1_W2    27648     // 96*192/4 = 4608
#define WF_FF2_W2    32256     // -> total 36864
__device__ __align__(16) uint4 g_wfrag[36864];

// ---------------------------------------------------------------------------
__device__ __forceinline__ float fexp(float x) {
    x = fmaxf(x, -80.0f);
    const float L2E = 1.4426950408889634f;
    float t = fmaf(x, L2E, 12582912.0f);
    float n = t - 12582912.0f;
    float f = fmaf(x, L2E, -n);
    float p = 1.5403530393381608e-4f;
    p = fmaf(p, f, 1.3333558146428443e-3f);
    p = fmaf(p, f, 9.6181291076284772e-3f);
    p = fmaf(p, f, 5.5504108664821580e-2f);
    p = fmaf(p, f, 2.4022650695910072e-1f);
    p = fmaf(p, f, 6.9314718055994531e-1f);
    p = fmaf(p, f, 1.0f);
    int e = (int)n;
    float s = __int_as_float((127 + e) << 23);
    return p * s;
}

// ---------------------------------------------------------------------------
// bf16 split/reconstruct + m16n8k16 bf16 MMA (3-term: err ~2^-18)
// ---------------------------------------------------------------------------
__device__ __forceinline__ void bfsplit2(float x0, float x1, uint32_t& h2, uint32_t& l2) {
    uint32_t h;
    asm("cvt.rn.bf16x2.f32 %0, %1, %2;" : "=r"(h) : "f"(x1), "f"(x0));
    float h0 = __uint_as_float(h << 16);
    float h1 = __uint_as_float(h & 0xffff0000u);
    uint32_t l;
    asm("cvt.rn.bf16x2.f32 %0, %1, %2;" : "=r"(l) : "f"(x1 - h1), "f"(x0 - h0));
    h2 = h; l2 = l;
}
__device__ __forceinline__ void bfsplit1(float x, __nv_bfloat16& h, __nv_bfloat16& l) {
    h = __float2bfloat16(x);
    l = __float2bfloat16(x - __bfloat162float(h));
}
__device__ __forceinline__ void bfrec2(uint2 w, float& x0, float& x1) {
    x0 = __uint_as_float(w.x << 16)          + __uint_as_float(w.y << 16);
    x1 = __uint_as_float(w.x & 0xffff0000u)  + __uint_as_float(w.y & 0xffff0000u);
}
__device__ __forceinline__ void mma_bf16(float4& d, const uint32_t* a,
                                         uint32_t b0, uint32_t b1) {
    asm volatile("mma.sync.aligned.m16n8k16.row.col.f32.bf16.bf16.f32 "
                 "{%0,%1,%2,%3},{%4,%5,%6,%7},{%8,%9},{%0,%1,%2,%3};"
                 : "+f"(d.x), "+f"(d.y), "+f"(d.z), "+f"(d.w)
                 : "r"(a[0]), "r"(a[1]), "r"(a[2]), "r"(a[3]), "r"(b0), "r"(b1));
}

// C = A(pre-split interleaved uint2 plane [row][kword], stride ldaw)
//   @ B(fragment-packed uint4). Zero per-iteration conversions.
template<int NT, int KST>
__device__ __forceinline__ void mma_gemm_pk(
    float4* acc, const uint2* A, int ldaw, int m0,
    const uint4* __restrict__ Bf, int nt0, int mg, int mt, int tx)
{
    #pragma unroll
    for (int ks = 0; ks < KST; ks++) {
        uint2 a0 = A[(m0 + mg) * ldaw + ks * 8 + mt];
        uint2 a1 = A[(m0 + mg + 8) * ldaw + ks * 8 + mt];
        uint2 a2 = A[(m0 + mg) * ldaw + ks * 8 + 4 + mt];
        uint2 a3 = A[(m0 + mg + 8) * ldaw + ks * 8 + 4 + mt];
        uint32_t ah[4] = {a0.x, a1.x, a2.x, a3.x};
        uint32_t al[4] = {a0.y, a1.y, a2.y, a3.y};
        #pragma unroll
        for (int j = 0; j < NT; j++) {
            uint4 w = __ldg(&Bf[((nt0 + j) * KST + ks) * 32 + tx]);
            mma_bf16(acc[j], ah, w.x, w.y);
            mma_bf16(acc[j], ah, w.z, w.w);
            mma_bf16(acc[j], al, w.x, w.y);
        }
    }
}

// ---------------------------------------------------------------------------
// Weight prep: W[K][N] fp32 -> fragment-packed uint4 per (n_tile, ks, lane).
// ---------------------------------------------------------------------------
__global__ void split_all_weights(
    const float* s0, const float* s1, const float* s2, const float* s3,
    const float* s4, const float* s5, const float* s6, const float* s7)
{
    const int Ks[8]  = {96, 96, 96, 96, 96, 96, 192, 192};
    const int Ns[8]  = {288, 96, 288, 96, 192, 192, 96, 96};
    const int off[8] = {WF_SA1_QKV, WF_SA1_PROJ, WF_SA2_QKV, WF_SA2_PROJ,
                        WF_FF1_W1, WF_FF2_W1, WF_FF1_W2, WF_FF2_W2};
    int m = blockIdx.y;
    int K = Ks[m], N = Ns[m];
    int KST = K / 16;
    int total = (N / 8) * KST * 32;
    int e = blockIdx.x * 256 + threadIdx.x;
    if (e >= total) return;
    const float* src;
    switch (m) {
        case 0: src = s0; break; case 1: src = s1; break;
        case 2: src = s2; break; case 3: src = s3; break;
        case 4: src = s4; break; case 5: src = s5; break;
        case 6: src = s6; break; default: src = s7; break;
    }
    int lane  = e & 31;
    int ks    = (e >> 5) % KST;
    int ntile = e / (32 * KST);
    int mg = lane >> 2, mt = lane & 3;
    int n  = ntile * 8 + mg;
    int k0 = ks * 16;
    float x0 = src[(k0 + 2 * mt)     * N + n];
    float x1 = src[(k0 + 2 * mt + 1) * N + n];
    float x2 = src[(k0 + 8 + 2 * mt)     * N + n];
    float x3 = src[(k0 + 8 + 2 * mt + 1) * N + n];
    uint32_t bh0, bl0, bh1, bl1;
    bfsplit2(x0, x1, bh0, bl0);
    bfsplit2(x2, x3, bh1, bl1);
    g_wfrag[off[m] + e] = make_uint4(bh0, bh1, bl0, bl1);
}

// ---------------------------------------------------------------------------
// Transposes: [B,C,H,W] <-> [B,HW,C]
// ---------------------------------------------------------------------------
__global__ void transpose_in_kernel(const float* __restrict__ x, float* __restrict__ img) {
    __shared__ float tile[32][33];
    int b = blockIdx.z;
    int hw0 = blockIdx.x * 32, c0 = blockIdx.y * 32;
    const float* src = x + (size_t)b * CH * HW;
    float* dst = img + (size_t)b * HW * CH;
    #pragma unroll
    for (int i = threadIdx.y; i < 32; i += 8)
        tile[i][threadIdx.x] = src[(size_t)(c0 + i) * HW + hw0 + threadIdx.x];
    __syncthreads();
    #pragma unroll
    for (int i = threadIdx.y; i < 32; i += 8)
        dst[(size_t)(hw0 + i) * CH + c0 + threadIdx.x] = tile[threadIdx.x][i];
}

__global__ void transpose_out_kernel(const float* __restrict__ img, float* __restrict__ x) {
    __shared__ float tile[32][33];
    int b = blockIdx.z;
    int hw0 = blockIdx.x * 32, c0 = blockIdx.y * 32;
    const float* src = img + (size_t)b * HW * CH;
    float* dst = x + (size_t)b * CH * HW;
    #pragma unroll
    for (int i = threadIdx.y; i < 32; i += 8)
        tile[i][threadIdx.x] = src[(size_t)(hw0 + i) * CH + c0 + threadIdx.x];
    __syncthreads();
    #pragma unroll
    for (int i = threadIdx.y; i < 32; i += 8)
        dst[(size_t)(c0 + i) * HW + hw0 + threadIdx.x] = tile[threadIdx.x][i];
}

// ---------------------------------------------------------------------------
// Fused window attention: all operands pre-split; all matmuls bf16 3-term mma.
// smem (4B words): S 8704 (logits; later Y fp32) | Tb 1360 | stats 128 |
//   Cnt 64 | XP 6400 | OP 6400 | QP 6400 | KP 6400 | SP 8704 | VH 3456 |
//   VL 3456  = 51,472 words = 205,888 B
// ---------------------------------------------------------------------------
#define ATTN_SMEM 205888

template<int SHIFTED>
__global__ void __launch_bounds__(512, 1) attn_kernel(
    const float* __restrict__ in, float* __restrict__ out,
    const uint4* __restrict__ WQF, const float* __restrict__ bqkv,
    const float* __restrict__ table,
    const uint4* __restrict__ WPF, const float* __restrict__ bproj,
    const float* __restrict__ gam, const float* __restrict__ beta)
{
    extern __shared__ float sm[];
    float* S     = sm;                   // 8704 (2 x 64 x 68); later Y (64 x QS)
    float* Tb    = S + 8704;             // 1360
    float* stats = Tb + 1360;            // 128
    int*   Cnt   = (int*)(stats + 128);  // 64
    uint2* XP    = (uint2*)(Cnt + 64);   // 64 x 50 (X split, kword planes)
    uint2* OP    = XP + 3200;            // 64 x 50 (attn out split)
    uint2* QP    = OP + 3200;            // 64 x 50 (Q split)
    uint2* KP    = QP + 3200;            // 64 x 50 (K split)
    uint2* SP    = KP + 3200;            // 2 x 64 x 34 (softmax split)
    uint32_t* VH = (uint32_t*)(SP + 4352); // 96 x 36 words ([dim][tok] hi)
    uint32_t* VL = VH + 3456;
    __nv_bfloat16* VHs = (__nv_bfloat16*)VH;  // stride 72 halves
    __nv_bfloat16* VLs = (__nv_bfloat16*)VL;

    const int tid = threadIdx.x;
    const int wid = blockIdx.x;
    const int b  = wid / NWIN_PER;
    const int wl = wid - b * NWIN_PER;
    const int wr = wl / 24, wc = wl - (wl / 24) * 24;
    const float* src = in  + (size_t)b * HW * CH;
    float*       dst = out + (size_t)b * HW * CH;

    // ---- gather window tokens directly into split plane XP ----
    for (int idx = tid; idx < 64 * 48; idx += 512) {
        int t = idx / 48, wd = idx - t * 48;
        int r = t >> 3, cl = t & 7;
        int h = wr * 8 + r, w = wc * 8 + cl;
        if (SHIFTED) { h += 4; if (h >= HH) h -= HH; w += 4; if (w >= WWI) w -= WWI; }
        float2 v = *(const float2*)&src[(h * WWI + w) * CH + 2 * wd];
        uint32_t hh, ll;
        bfsplit2(v.x, v.y, hh, ll);
        XP[t * 50 + wd] = make_uint2(hh, ll);
    }
    for (int idx = tid; idx < 1350; idx += 512) Tb[idx] = table[idx];
    if (tid < 64) {
        int ri = tid >> 3, ci = tid & 7;
        Cnt[tid] = SHIFTED ? (((wr == 23) ? (ri < 4 ? 1 : 2) : 0) * 3
                            + ((wc == 23) ? (ci < 4 ? 1 : 2) : 0)) : 0;
    }
    __syncthreads();

    const int wg = tid >> 5, tx = tid & 31;   // 16 warps
    const int mg = tx >> 2, mt = tx & 3;      // mma lane coords
    const int m0 = (wg & 3) * 16;             // m-tile (QKV/proj)
    const int nch = wg >> 2;                  // n-chunk

    // ---- QKV GEMM: epilogue writes split Q/K planes + transposed V planes --
    {
        float4 acc[9];
        #pragma unroll
        for (int j = 0; j < 9; j++) {
            int c = nch * 72 + j * 8 + 2 * mt;
            float b0 = __ldg(&bqkv[c]), b1 = __ldg(&bqkv[c + 1]);
            acc[j].x = b0; acc[j].y = b1; acc[j].z = b0; acc[j].w = b1;
        }
        mma_gemm_pk<9, 6>(acc, XP, 50, m0, WQF, nch * 9, mg, mt, tx);
        #pragma unroll
        for (int j = 0; j < 9; j++) {
            int cb = nch * 72 + j * 8;        // uniform per tile
            int c  = cb + 2 * mt;
            int rA = m0 + mg, rB = rA + 8;
            if (cb < 96) {
                int cw = c / 2;
                uint32_t h, l;
                bfsplit2(acc[j].x, acc[j].y, h, l); QP[rA * 50 + cw] = make_uint2(h, l);
                bfsplit2(acc[j].z, acc[j].w, h, l); QP[rB * 50 + cw] = make_uint2(h, l);
            } else if (cb < 192) {
                int cw = (c - 96) / 2;
                uint32_t h, l;
                bfsplit2(acc[j].x, acc[j].y, h, l); KP[rA * 50 + cw] = make_uint2(h, l);
                bfsplit2(acc[j].z, acc[j].w, h, l); KP[rB * 50 + cw] = make_uint2(h, l);
            } else {                          // V transposed [dim][tok]
                int d = c - 192;
                __nv_bfloat16 h, l;
                bfsplit1(acc[j].x, h, l); VHs[d * 72 + rA] = h;       VLs[d * 72 + rA] = l;
                bfsplit1(acc[j].y, h, l); VHs[(d + 1) * 72 + rA] = h; VLs[(d + 1) * 72 + rA] = l;
                bfsplit1(acc[j].z, h, l); VHs[d * 72 + rB] = h;       VLs[d * 72 + rB] = l;
                bfsplit1(acc[j].w, h, l); VHs[(d + 1) * 72 + rB] = h; VLs[(d + 1) * 72 + rB] = l;
            }
        }
    }
    __syncthreads();

    // ---- heads: 2 in flight; 8 warps/head ----
    const int hg = wg >> 3;
    const int w8 = wg & 7;
    const int hm = w8 & 3;
    const int nh = w8 >> 2;

    for (int it = 0; it < 3; it++) {
        const int hd = it * 2 + hg;
        float* Sg = S + hg * 4352;           // 64 x 68 logits
        uint2* SPg = SP + hg * (64 * 34);

        // --- scores: 16x32 of Q@K^T, pure LDS.64 + mma ---
        {
            float4 acc[4];
            #pragma unroll
            for (int jt = 0; jt < 4; jt++) acc[jt] = make_float4(0.f, 0.f, 0.f, 0.f);
            int qw = (hm * 16 + mg) * 50 + hd * 8 + mt;
            uint2 q0 = QP[qw], q1 = QP[qw + 400], q2 = QP[qw + 4], q3 = QP[qw + 404];
            uint32_t ah[4] = {q0.x, q1.x, q2.x, q3.x};
            uint32_t al[4] = {q0.y, q1.y, q2.y, q3.y};
            #pragma unroll
            for (int jt = 0; jt < 4; jt++) {
                int kw = (nh * 32 + jt * 8 + mg) * 50 + hd * 8 + mt;
                uint2 b0 = KP[kw], b1 = KP[kw + 4];
                mma_bf16(acc[jt], ah, b0.x, b1.x);
                mma_bf16(acc[jt], ah, b0.y, b1.y);
                mma_bf16(acc[jt], al, b0.x, b1.x);
            }
            int iA = hm * 16 + mg, iB = iA + 8;
            int riA = iA >> 3, ciA = iA & 7, riB = iB >> 3, ciB = iB & 7;
            int cntA = Cnt[iA], cntB = Cnt[iB];
            #pragma unroll
            for (int jt = 0; jt < 4; jt++) {
                int c = nh * 32 + jt * 8 + 2 * mt;
                #pragma unroll
                for (int e = 0; e < 2; e++) {
                    int j = c + e;
                    int rj = j >> 3, cj = j & 7;
                    int cntJ = Cnt[j];
                    float bA = Tb[((riA - rj + 7) * 15 + (ciA - cj + 7)) * 6 + hd];
                    float bB = Tb[((riB - rj + 7) * 15 + (ciB - cj + 7)) * 6 + hd];
                    if (SHIFTED) {
                        if (cntA != cntJ) bA -= 100.f;
                        if (cntB != cntJ) bB -= 100.f;
                    }
                    float vA = (e == 0) ? acc[jt].x : acc[jt].y;
                    float vB = (e == 0) ? acc[jt].z : acc[jt].w;
                    Sg[iA * 68 + j] = fmaf(vA, 0.25f, bA);
                    Sg[iB * 68 + j] = fmaf(vB, 0.25f, bB);
                }
            }
        }
        __syncthreads();

        // --- softmax: 4 threads/row, writes SPLIT probabilities to SP ---
        {
            int row = tid >> 2, l4 = tid & 3;
            int rg = row >> 6, rr = row & 63;
            float* Sr = S + rg * 4352 + rr * 68;
            float4 v[4];
            float mx = -1e30f;
            #pragma unroll
            for (int q = 0; q < 4; q++) {
                v[q] = *(const float4*)&Sr[l4 * 16 + q * 4];
                mx = fmaxf(mx, fmaxf(fmaxf(v[q].x, v[q].y), fmaxf(v[q].z, v[q].w)));
            }
            mx = fmaxf(mx, __shfl_xor_sync(0xffffffffu, mx, 1));
            mx = fmaxf(mx, __shfl_xor_sync(0xffffffffu, mx, 2));
            float ssum = 0.f;
            #pragma unroll
            for (int q = 0; q < 4; q++) {
                v[q].x = fexp(v[q].x - mx); v[q].y = fexp(v[q].y - mx);
                v[q].z = fexp(v[q].z - mx); v[q].w = fexp(v[q].w - mx);
                ssum += (v[q].x + v[q].y) + (v[q].z + v[q].w);
            }
            ssum += __shfl_xor_sync(0xffffffffu, ssum, 1);
            ssum += __shfl_xor_sync(0xffffffffu, ssum, 2);
            float inv = 1.0f / ssum;
            uint4* SP4 = (uint4*)(SP + rg * (64 * 34) + rr * 34 + l4 * 8);
            #pragma unroll
            for (int q = 0; q < 4; q++) {
                uint32_t hA, lA, hB, lB;
                bfsplit2(v[q].x * inv, v[q].y * inv, hA, lA);
                bfsplit2(v[q].z * inv, v[q].w * inv, hB, lB);
                SP4[q] = make_uint4(hA, lA, hB, lB);
            }
        }
        __syncthreads();

        // --- AV: 16 rows x 8 dims; A from SP (LDS.64), B from V planes ---
        {
            int nc0 = hd * 16 + nh * 8;
            float4 acc = make_float4(0.f, 0.f, 0.f, 0.f);
            #pragma unroll
            for (int ks = 0; ks < 4; ks++) {
                int spw = (hm * 16 + mg) * 34 + ks * 8 + mt;
                uint2 a0 = SPg[spw],       a1 = SPg[spw + 272];
                uint2 a2 = SPg[spw + 4],   a3 = SPg[spw + 276];
                uint32_t ah[4] = {a0.x, a1.x, a2.x, a3.x};
                uint32_t al[4] = {a0.y, a1.y, a2.y, a3.y};
                int vw = (nc0 + mg) * 36 + ks * 8 + mt;
                uint32_t bh0 = VH[vw], bh1 = VH[vw + 4];
                uint32_t bl0 = VL[vw], bl1 = VL[vw + 4];
                mma_bf16(acc, ah, bh0, bh1);
                mma_bf16(acc, ah, bl0, bl1);
                mma_bf16(acc, al, bh0, bh1);
            }
            int rA = hm * 16 + mg, rB = rA + 8;
            int cw = hd * 8 + nh * 4 + mt;
            uint32_t h, l;
            bfsplit2(acc.x, acc.y, h, l); OP[rA * 50 + cw] = make_uint2(h, l);
            bfsplit2(acc.z, acc.w, h, l); OP[rB * 50 + cw] = make_uint2(h, l);
        }
        __syncthreads();
    }

    // ---- proj GEMM + residual (X reconstructed from XP); Y overlays S ----
    float* Y = S;
    {
        float4 acc[3];
        #pragma unroll
        for (int j = 0; j < 3; j++) {
            int c = nch * 24 + j * 8 + 2 * mt;
            float b0 = __ldg(&bproj[c]), b1 = __ldg(&bproj[c + 1]);
            acc[j].x = b0; acc[j].y = b1; acc[j].z = b0; acc[j].w = b1;
        }
        mma_gemm_pk<3, 6>(acc, OP, 50, m0, WPF, nch * 3, mg, mt, tx);
        __syncthreads();   // logits reads done; safe to overwrite S as Y
        #pragma unroll
        for (int j = 0; j < 3; j++) {
            int c = nch * 24 + j * 8 + 2 * mt;
            int cw = c / 2;
            int rA = m0 + mg, rB = rA + 8;
            float xA0, xA1, xB0, xB1;
            bfrec2(XP[rA * 50 + cw], xA0, xA1);
            bfrec2(XP[rB * 50 + cw], xB0, xB1);
            Y[rA * QS + c]     = acc[j].x + xA0;
            Y[rA * QS + c + 1] = acc[j].y + xA1;
            Y[rB * QS + c]     = acc[j].z + xB0;
            Y[rB * QS + c + 1] = acc[j].w + xB1;
        }
    }
    __syncthreads();

    // ---- LayerNorm: 8 threads per row ----
    {
        int row = tid >> 3, l8 = tid & 7;
        float s = 0.f, s2 = 0.f;
        #pragma unroll
        for (int q = 0; q < 3; q++) {
            float4 y = *(const float4*)&Y[row * QS + l8 * 12 + q * 4];
            s += (y.x + y.y) + (y.z + y.w);
            s2 = fmaf(y.x, y.x, fmaf(y.y, y.y, fmaf(y.z, y.z, fmaf(y.w, y.w, s2))));
        }
        #pragma unroll
        for (int o = 4; o > 0; o >>= 1) {
            s  += __shfl_xor_sync(0xffffffffu, s,  o);
            s2 += __shfl_xor_sync(0xffffffffu, s2, o);
        }
        if (l8 == 0) {
            float mean = s * (1.0f / 96.0f);
            float var  = fmaf(-mean, mean, s2 * (1.0f / 96.0f));
            stats[row]      = mean;
            stats[64 + row] = rsqrtf(var + 1e-5f);
        }
    }
    __syncthreads();

    // ---- scatter (same coords as gather: roll cancels) ----
    for (int idx = tid; idx < NTOK * CH; idx += 512) {
        int t = idx / CH, c = idx - t * CH;
        int r = t >> 3, cl = t & 7;
        int h = wr * 8 + r, w = wc * 8 + cl;
        if (SHIFTED) { h += 4; if (h >= HH) h -= HH; w += 4; if (w >= WWI) w -= WWI; }
        float yv = (Y[t * QS + c] - stats[t]) * stats[64 + t];
        dst[(h * WWI + w) * CH + c] = fmaf(yv, gam[c], beta[c]);
    }
}

// ---------------------------------------------------------------------------
// Fused FFN: pre-split X and H1 planes; fragment-packed weights.
// smem (4B words): Y 6400 | stats 128 | XP 6400 | HP 12544 = 25,472 w = 101,888 B
// ---------------------------------------------------------------------------
#define FFN_SMEM 101888

__global__ void __launch_bounds__(512, 1) ffn_kernel(
    const float* __restrict__ in, float* __restrict__ out,
    const uint4* __restrict__ W1F, const float* __restrict__ b1,
    const uint4* __restrict__ W2F, const float* __restrict__ b2,
    const float* __restrict__ gam, const float* __restrict__ beta)
{
    extern __shared__ float sm[];
    float* Y     = sm;                   // 64 x QS
    float* stats = Y + 6400;             // 128
    uint2* XP    = (uint2*)(stats + 128);// 64 x 50
    uint2* HP    = XP + 3200;            // 64 x 98

    const int tid = threadIdx.x;
    const size_t t0 = (size_t)blockIdx.x * 64;
    const float* src = in + t0 * CH;
    float*       dst = out + t0 * CH;

    // gather -> split X plane
    for (int idx = tid; idx < 64 * 48; idx += 512) {
        int t = idx / 48, wd = idx - t * 48;
        float2 v = *(const float2*)&src[t * CH + 2 * wd];
        uint32_t hh, ll;
        bfsplit2(v.x, v.y, hh, ll);
        XP[t * 50 + wd] = make_uint2(hh, ll);
    }
    __syncthreads();

    const int wg = tid >> 5, tx = tid & 31;
    const int mg = tx >> 2, mt = tx & 3;
    const int m0 = (wg & 3) * 16;
    const int nch = wg >> 2;

    // GEMM1: 64x192x96 + GELU -> HP (split plane)
    {
        float4 acc[6];
        #pragma unroll
        for (int j = 0; j < 6; j++) {
            int c = nch * 48 + j * 8 + 2 * mt;
            float v0 = __ldg(&b1[c]), v1 = __ldg(&b1[c + 1]);
            acc[j].x = v0; acc[j].y = v1; acc[j].z = v0; acc[j].w = v1;
        }
        mma_gemm_pk<6, 6>(acc, XP, 50, m0, W1F, nch * 6, mg, mt, tx);
        #pragma unroll
        for (int j = 0; j < 6; j++) {
            int cw = nch * 24 + j * 4 + mt;  // = c/2
            int rA = m0 + mg, rB = rA + 8;
            float g0 = 0.5f * acc[j].x * (1.0f + erff(acc[j].x * 0.70710678118654752f));
            float g1 = 0.5f * acc[j].y * (1.0f + erff(acc[j].y * 0.70710678118654752f));
            float g2 = 0.5f * acc[j].z * (1.0f + erff(acc[j].z * 0.70710678118654752f));
            float g3 = 0.5f * acc[j].w * (1.0f + erff(acc[j].w * 0.70710678118654752f));
            uint32_t h, l;
            bfsplit2(g0, g1, h, l); HP[rA * 98 + cw] = make_uint2(h, l);
            bfsplit2(g2, g3, h, l); HP[rB * 98 + cw] = make_uint2(h, l);
        }
    }
    __syncthreads();

    // GEMM2: 64x96x192 + residual (X reconstructed) -> Y
    {
        float4 acc[3];
        #pragma unroll
        for (int j = 0; j < 3; j++) {
            int c = nch * 24 + j * 8 + 2 * mt;
            float v0 = __ldg(&b2[c]), v1 = __ldg(&b2[c + 1]);
            acc[j].x = v0; acc[j].y = v1; acc[j].z = v0; acc[j].w = v1;
        }
        mma_gemm_pk<3, 12>(acc, HP, 98, m0, W2F, nch * 3, mg, mt, tx);
        #pragma unroll
        for (int j = 0; j < 3; j++) {
            int c = nch * 24 + j * 8 + 2 * mt;
            int cw = c / 2;
            int rA = m0 + mg, rB = rA + 8;
            float xA0, xA1, xB0, xB1;
            bfrec2(XP[rA * 50 + cw], xA0, xA1);
            bfrec2(XP[rB * 50 + cw], xB0, xB1);
            Y[rA * QS + c]     = acc[j].x + xA0;
            Y[rA * QS + c + 1] = acc[j].y + xA1;
            Y[rB * QS + c]     = acc[j].z + xB0;
            Y[rB * QS + c + 1] = acc[j].w + xB1;
        }
    }
    __syncthreads();

    // LayerNorm: 8 threads per row
    {
        int row = tid >> 3, l8 = tid & 7;
        float s = 0.f, s2 = 0.f;
        #pragma unroll
        for (int q = 0; q < 3; q++) {
            float4 y = *(const float4*)&Y[row * QS + l8 * 12 + q * 4];
            s += (y.x + y.y) + (y.z + y.w);
            s2 = fmaf(y.x, y.x, fmaf(y.y, y.y, fmaf(y.z, y.z, fmaf(y.w, y.w, s2))));
        }
        #pragma unroll
        for (int o = 4; o > 0; o >>= 1) {
            s  += __shfl_xor_sync(0xffffffffu, s,  o);
            s2 += __shfl_xor_sync(0xffffffffu, s2, o);
        }
        if (l8 == 0) {
            float mean = s * (1.0f / 96.0f);
            float var  = fmaf(-mean, mean, s2 * (1.0f / 96.0f));
            stats[row]      = mean;
            stats[64 + row] = rsqrtf(var + 1e-5f);
        }
    }
    __syncthreads();

    for (int idx = tid; idx < 6144; idx += 512) {
        int t = idx / CH, c = idx - t * CH;
        float yv = (Y[t * QS + c] - stats[t]) * stats[64 + t];
        dst[idx] = fmaf(yv, gam[c], beta[c]);
    }
}

// ---------------------------------------------------------------------------
// Input order (setup_inputs dict order):
//   0: x | 1..7: sa1 | 8..14: sa2 | 15..20: ff1 | 21..26: ff2
// ---------------------------------------------------------------------------
extern "C" void kernel_launch(void* const* d_in, const int* in_sizes, int n_in,
                              void* d_out, int out_size) {
    const float* x = (const float*)d_in[0];
    float *imgA, *imgB;
    uint4* wf;
    cudaGetSymbolAddress((void**)&imgA, g_imgA);
    cudaGetSymbolAddress((void**)&imgB, g_imgB);
    cudaGetSymbolAddress((void**)&wf,   g_wfrag);

    cudaFuncSetAttribute(attn_kernel<0>, cudaFuncAttributeMaxDynamicSharedMemorySize, ATTN_SMEM);
    cudaFuncSetAttribute(attn_kernel<1>, cudaFuncAttributeMaxDynamicSharedMemorySize, ATTN_SMEM);
    cudaFuncSetAttribute(ffn_kernel,     cudaFuncAttributeMaxDynamicSharedMemorySize, FFN_SMEM);

    split_all_weights<<<dim3(27, 8), 256>>>(
        (const float*)d_in[1],  (const float*)d_in[4],
        (const float*)d_in[8],  (const float*)d_in[11],
        (const float*)d_in[15], (const float*)d_in[21],
        (const float*)d_in[17], (const float*)d_in[23]);

    dim3 tb(32, 8);
    dim3 tg(HW / 32, CH / 32, BATCH);

    transpose_in_kernel<<<tg, tb>>>(x, imgA);

    attn_kernel<0><<<NWIN, 512, ATTN_SMEM>>>(
        imgA, imgB, wf + WF_SA1_QKV,
        (const float*)d_in[2], (const float*)d_in[3],
        wf + WF_SA1_PROJ, (const float*)d_in[5],
        (const float*)d_in[6], (const float*)d_in[7]);

    ffn_kernel<<<NWIN, 512, FFN_SMEM>>>(
        imgB, imgA, wf + WF_FF1_W1, (const float*)d_in[16],
        wf + WF_FF1_W2, (const float*)d_in[18],
        (const float*)d_in[19], (const float*)d_in[20]);

    attn_kernel<1><<<NWIN, 512, ATTN_SMEM>>>(
        imgA, imgB, wf + WF_SA2_QKV,
        (const float*)d_in[9], (const float*)d_in[10],
        wf + WF_SA2_PROJ, (const float*)d_in[12],
        (const float*)d_in[13], (const float*)d_in[14]);

    ffn_kernel<<<NWIN, 512, FFN_SMEM>>>(
        imgB, imgA, wf + WF_FF2_W1, (const float*)d_in[22],
        wf + WF_FF2_W2, (const float*)d_in[24],
        (const float*)d_in[25], (const float*)d_in[26]);

    transpose_out_kernel<<<tg, tb>>>(imgA, (float*)d_out);
}

// round 14
// speedup vs baseline: 2.4128x; 1.0944x over previous
#include <cuda_runtime.h>
#include <cuda_bf16.h>
#include <math.h>
#include <stdint.h>

#define CH    96
#define HH    192
#define WWI   192
#define HW    (HH*WWI)        // 36864
#define BATCH 4
#define NWIN_PER 576          // 24*24 windows per image
#define NWIN  (BATCH*NWIN_PER)
#define NTOK  64
#define QS    100             // fp32 row stride (Y)

// 56.6 MB each — static device scratch (no allocations allowed)
__device__ float g_imgA[BATCH*HW*CH];
__device__ float g_imgB[BATCH*HW*CH];

// fragment-packed bf16 weights: per (n_tile, ks) 32 x uint4{bh0,bh1,bl0,bl1}
#define WF_SA1_QKV   0         // 288*96/4 = 6912
#define WF_SA1_PROJ  6912      // 96*96/4  = 2304
#define WF_SA2_QKV   9216
#define WF_SA2_PROJ  16128
#define WF_FF1_W1    18432     // 192*96/4 = 4608
#define WF_FF2_W1    23040
#define WF_FF1_W2    27648     // 96*192/4 = 4608
#define WF_FF2_W2    32256     // -> total 36864
__device__ __align__(16) uint4 g_wfrag[36864];

// ---------------------------------------------------------------------------
__device__ __forceinline__ float fexp(float x) {
    x = fmaxf(x, -80.0f);
    const float L2E = 1.4426950408889634f;
    float t = fmaf(x, L2E, 12582912.0f);
    float n = t - 12582912.0f;
    float f = fmaf(x, L2E, -n);
    float p = 1.5403530393381608e-4f;
    p = fmaf(p, f, 1.3333558146428443e-3f);
    p = fmaf(p, f, 9.6181291076284772e-3f);
    p = fmaf(p, f, 5.5504108664821580e-2f);
    p = fmaf(p, f, 2.4022650695910072e-1f);
    p = fmaf(p, f, 6.9314718055994531e-1f);
    p = fmaf(p, f, 1.0f);
    int e = (int)n;
    float s = __int_as_float((127 + e) << 23);
    return p * s;
}

// ---------------------------------------------------------------------------
// bf16 split/reconstruct + m16n8k16 bf16 MMA (3-term: err ~2^-18)
// ---------------------------------------------------------------------------
__device__ __forceinline__ void bfsplit2(float x0, float x1, uint32_t& h2, uint32_t& l2) {
    uint32_t h;
    asm("cvt.rn.bf16x2.f32 %0, %1, %2;" : "=r"(h) : "f"(x1), "f"(x0));
    float h0 = __uint_as_float(h << 16);
    float h1 = __uint_as_float(h & 0xffff0000u);
    uint32_t l;
    asm("cvt.rn.bf16x2.f32 %0, %1, %2;" : "=r"(l) : "f"(x1 - h1), "f"(x0 - h0));
    h2 = h; l2 = l;
}
__device__ __forceinline__ void bfsplit1(float x, __nv_bfloat16& h, __nv_bfloat16& l) {
    h = __float2bfloat16(x);
    l = __float2bfloat16(x - __bfloat162float(h));
}
__device__ __forceinline__ void bfrec2(uint2 w, float& x0, float& x1) {
    x0 = __uint_as_float(w.x << 16)          + __uint_as_float(w.y << 16);
    x1 = __uint_as_float(w.x & 0xffff0000u)  + __uint_as_float(w.y & 0xffff0000u);
}
__device__ __forceinline__ void mma_bf16(float4& d, const uint32_t* a,
                                         uint32_t b0, uint32_t b1) {
    asm volatile("mma.sync.aligned.m16n8k16.row.col.f32.bf16.bf16.f32 "
                 "{%0,%1,%2,%3},{%4,%5,%6,%7},{%8,%9},{%0,%1,%2,%3};"
                 : "+f"(d.x), "+f"(d.y), "+f"(d.z), "+f"(d.w)
                 : "r"(a[0]), "r"(a[1]), "r"(a[2]), "r"(a[3]), "r"(b0), "r"(b1));
}

// C = A(pre-split interleaved uint2 plane [row][kword], stride ldaw)
//   @ B(fragment-packed uint4). Zero per-iteration conversions.
template<int NT, int KST>
__device__ __forceinline__ void mma_gemm_pk(
    float4* acc, const uint2* A, int ldaw, int m0,
    const uint4* __restrict__ Bf, int nt0, int mg, int mt, int tx)
{
    #pragma unroll
    for (int ks = 0; ks < KST; ks++) {
        uint2 a0 = A[(m0 + mg) * ldaw + ks * 8 + mt];
        uint2 a1 = A[(m0 + mg + 8) * ldaw + ks * 8 + mt];
        uint2 a2 = A[(m0 + mg) * ldaw + ks * 8 + 4 + mt];
        uint2 a3 = A[(m0 + mg + 8) * ldaw + ks * 8 + 4 + mt];
        uint32_t ah[4] = {a0.x, a1.x, a2.x, a3.x};
        uint32_t al[4] = {a0.y, a1.y, a2.y, a3.y};
        #pragma unroll
        for (int j = 0; j < NT; j++) {
            uint4 w = __ldg(&Bf[((nt0 + j) * KST + ks) * 32 + tx]);
            mma_bf16(acc[j], ah, w.x, w.y);
            mma_bf16(acc[j], ah, w.z, w.w);
            mma_bf16(acc[j], al, w.x, w.y);
        }
    }
}

// ---------------------------------------------------------------------------
// Weight prep: W[K][N] fp32 -> fragment-packed uint4 per (n_tile, ks, lane).
// ---------------------------------------------------------------------------
__global__ void split_all_weights(
    const float* s0, const float* s1, const float* s2, const float* s3,
    const float* s4, const float* s5, const float* s6, const float* s7)
{
    const int Ks[8]  = {96, 96, 96, 96, 96, 96, 192, 192};
    const int Ns[8]  = {288, 96, 288, 96, 192, 192, 96, 96};
    const int off[8] = {WF_SA1_QKV, WF_SA1_PROJ, WF_SA2_QKV, WF_SA2_PROJ,
                        WF_FF1_W1, WF_FF2_W1, WF_FF1_W2, WF_FF2_W2};
    int m = blockIdx.y;
    int K = Ks[m], N = Ns[m];
    int KST = K / 16;
    int total = (N / 8) * KST * 32;
    int e = blockIdx.x * 256 + threadIdx.x;
    if (e >= total) return;
    const float* src;
    switch (m) {
        case 0: src = s0; break; case 1: src = s1; break;
        case 2: src = s2; break; case 3: src = s3; break;
        case 4: src = s4; break; case 5: src = s5; break;
        case 6: src = s6; break; default: src = s7; break;
    }
    int lane  = e & 31;
    int ks    = (e >> 5) % KST;
    int ntile = e / (32 * KST);
    int mg = lane >> 2, mt = lane & 3;
    int n  = ntile * 8 + mg;
    int k0 = ks * 16;
    float x0 = src[(k0 + 2 * mt)     * N + n];
    float x1 = src[(k0 + 2 * mt + 1) * N + n];
    float x2 = src[(k0 + 8 + 2 * mt)     * N + n];
    float x3 = src[(k0 + 8 + 2 * mt + 1) * N + n];
    uint32_t bh0, bl0, bh1, bl1;
    bfsplit2(x0, x1, bh0, bl0);
    bfsplit2(x2, x3, bh1, bl1);
    g_wfrag[off[m] + e] = make_uint4(bh0, bh1, bl0, bl1);
}

// ---------------------------------------------------------------------------
// Transposes: [B,C,H,W] <-> [B,HW,C]
// ---------------------------------------------------------------------------
__global__ void transpose_in_kernel(const float* __restrict__ x, float* __restrict__ img) {
    __shared__ float tile[32][33];
    int b = blockIdx.z;
    int hw0 = blockIdx.x * 32, c0 = blockIdx.y * 32;
    const float* src = x + (size_t)b * CH * HW;
    float* dst = img + (size_t)b * HW * CH;
    #pragma unroll
    for (int i = threadIdx.y; i < 32; i += 8)
        tile[i][threadIdx.x] = src[(size_t)(c0 + i) * HW + hw0 + threadIdx.x];
    __syncthreads();
    #pragma unroll
    for (int i = threadIdx.y; i < 32; i += 8)
        dst[(size_t)(hw0 + i) * CH + c0 + threadIdx.x] = tile[threadIdx.x][i];
}

__global__ void transpose_out_kernel(const float* __restrict__ img, float* __restrict__ x) {
    __shared__ float tile[32][33];
    int b = blockIdx.z;
    int hw0 = blockIdx.x * 32, c0 = blockIdx.y * 32;
    const float* src = img + (size_t)b * HW * CH;
    float* dst = x + (size_t)b * CH * HW;
    #pragma unroll
    for (int i = threadIdx.y; i < 32; i += 8)
        tile[i][threadIdx.x] = src[(size_t)(hw0 + i) * CH + c0 + threadIdx.x];
    __syncthreads();
    #pragma unroll
    for (int i = threadIdx.y; i < 32; i += 8)
        dst[(size_t)(c0 + i) * HW + hw0 + threadIdx.x] = tile[threadIdx.x][i];
}

// ---------------------------------------------------------------------------
// Fused Swin block (attention + FFN) per window. All matmuls bf16 3-term mma;
// all multiply-consumed operands pre-split. One gmem gather + one scatter.
// smem (4B words): S 8704 (logits / Y fp32) | Tb 1360 | stats 128 | Cnt 64 |
//   XP 6400 | OP 6400 | QP 6400 | KP 6400 | SP 8704 | VH 3456 | VL 3456
//   = 51,472 words = 205,888 B.  FFN: HP overlays QP+KP (12544 of 12800 w).
// ---------------------------------------------------------------------------
#define BLK_SMEM 205888

template<int SHIFTED>
__global__ void __launch_bounds__(512, 1) block_kernel(
    const float* __restrict__ in, float* __restrict__ out,
    const uint4* __restrict__ WQF, const float* __restrict__ bqkv,
    const float* __restrict__ table,
    const uint4* __restrict__ WPF, const float* __restrict__ bproj,
    const float* __restrict__ gam1, const float* __restrict__ beta1,
    const uint4* __restrict__ W1F, const float* __restrict__ b1,
    const uint4* __restrict__ W2F, const float* __restrict__ b2,
    const float* __restrict__ gam2, const float* __restrict__ beta2)
{
    extern __shared__ float sm[];
    float* S     = sm;                   // 8704 (2x64x68 logits); later Y fp32
    float* Tb    = S + 8704;             // 1360
    float* stats = Tb + 1360;            // 128
    int*   Cnt   = (int*)(stats + 128);  // 64
    uint2* XP    = (uint2*)(Cnt + 64);   // 64 x 50
    uint2* OP    = XP + 3200;            // 64 x 50
    uint2* QP    = OP + 3200;            // 64 x 50
    uint2* KP    = QP + 3200;            // 64 x 50
    uint2* SP    = KP + 3200;            // 2 x 64 x 34
    uint32_t* VH = (uint32_t*)(SP + 4352); // 96 x 36 words
    uint32_t* VL = VH + 3456;
    __nv_bfloat16* VHs = (__nv_bfloat16*)VH;
    __nv_bfloat16* VLs = (__nv_bfloat16*)VL;
    uint2* HP    = QP;                   // FFN hidden split (64 x 98) overlays QP+KP

    const int tid = threadIdx.x;
    const int wid = blockIdx.x;
    const int b  = wid / NWIN_PER;
    const int wl = wid - b * NWIN_PER;
    const int wr = wl / 24, wc = wl - (wl / 24) * 24;
    const float* src = in  + (size_t)b * HW * CH;
    float*       dst = out + (size_t)b * HW * CH;

    // ---- gather window tokens into split plane XP ----
    for (int idx = tid; idx < 64 * 48; idx += 512) {
        int t = idx / 48, wd = idx - t * 48;
        int r = t >> 3, cl = t & 7;
        int h = wr * 8 + r, w = wc * 8 + cl;
        if (SHIFTED) { h += 4; if (h >= HH) h -= HH; w += 4; if (w >= WWI) w -= WWI; }
        float2 v = *(const float2*)&src[(h * WWI + w) * CH + 2 * wd];
        uint32_t hh, ll;
        bfsplit2(v.x, v.y, hh, ll);
        XP[t * 50 + wd] = make_uint2(hh, ll);
    }
    for (int idx = tid; idx < 1350; idx += 512) Tb[idx] = table[idx];
    if (tid < 64) {
        int ri = tid >> 3, ci = tid & 7;
        Cnt[tid] = SHIFTED ? (((wr == 23) ? (ri < 4 ? 1 : 2) : 0) * 3
                            + ((wc == 23) ? (ci < 4 ? 1 : 2) : 0)) : 0;
    }
    __syncthreads();

    const int wg = tid >> 5, tx = tid & 31;   // 16 warps
    const int mg = tx >> 2, mt = tx & 3;
    const int m0 = (wg & 3) * 16;
    const int nch = wg >> 2;

    // ================= ATTENTION =================
    // ---- QKV GEMM -> split Q/K planes + transposed V planes ----
    {
        float4 acc[9];
        #pragma unroll
        for (int j = 0; j < 9; j++) {
            int c = nch * 72 + j * 8 + 2 * mt;
            float b0 = __ldg(&bqkv[c]), b1v = __ldg(&bqkv[c + 1]);
            acc[j].x = b0; acc[j].y = b1v; acc[j].z = b0; acc[j].w = b1v;
        }
        mma_gemm_pk<9, 6>(acc, XP, 50, m0, WQF, nch * 9, mg, mt, tx);
        #pragma unroll
        for (int j = 0; j < 9; j++) {
            int cb = nch * 72 + j * 8;
            int c  = cb + 2 * mt;
            int rA = m0 + mg, rB = rA + 8;
            if (cb < 96) {
                int cw = c / 2;
                uint32_t h, l;
                bfsplit2(acc[j].x, acc[j].y, h, l); QP[rA * 50 + cw] = make_uint2(h, l);
                bfsplit2(acc[j].z, acc[j].w, h, l); QP[rB * 50 + cw] = make_uint2(h, l);
            } else if (cb < 192) {
                int cw = (c - 96) / 2;
                uint32_t h, l;
                bfsplit2(acc[j].x, acc[j].y, h, l); KP[rA * 50 + cw] = make_uint2(h, l);
                bfsplit2(acc[j].z, acc[j].w, h, l); KP[rB * 50 + cw] = make_uint2(h, l);
            } else {
                int d = c - 192;
                __nv_bfloat16 h, l;
                bfsplit1(acc[j].x, h, l); VHs[d * 72 + rA] = h;       VLs[d * 72 + rA] = l;
                bfsplit1(acc[j].y, h, l); VHs[(d + 1) * 72 + rA] = h; VLs[(d + 1) * 72 + rA] = l;
                bfsplit1(acc[j].z, h, l); VHs[d * 72 + rB] = h;       VLs[d * 72 + rB] = l;
                bfsplit1(acc[j].w, h, l); VHs[(d + 1) * 72 + rB] = h; VLs[(d + 1) * 72 + rB] = l;
            }
        }
    }
    __syncthreads();

    // ---- heads: 2 in flight; 8 warps/head ----
    const int hg = wg >> 3;
    const int w8 = wg & 7;
    const int hm = w8 & 3;
    const int nh = w8 >> 2;

    for (int it = 0; it < 3; it++) {
        const int hd = it * 2 + hg;
        float* Sg = S + hg * 4352;
        uint2* SPg = SP + hg * (64 * 34);

        // scores
        {
            float4 acc[4];
            #pragma unroll
            for (int jt = 0; jt < 4; jt++) acc[jt] = make_float4(0.f, 0.f, 0.f, 0.f);
            int qw = (hm * 16 + mg) * 50 + hd * 8 + mt;
            uint2 q0 = QP[qw], q1 = QP[qw + 400], q2 = QP[qw + 4], q3 = QP[qw + 404];
            uint32_t ah[4] = {q0.x, q1.x, q2.x, q3.x};
            uint32_t al[4] = {q0.y, q1.y, q2.y, q3.y};
            #pragma unroll
            for (int jt = 0; jt < 4; jt++) {
                int kw = (nh * 32 + jt * 8 + mg) * 50 + hd * 8 + mt;
                uint2 b0 = KP[kw], b1v = KP[kw + 4];
                mma_bf16(acc[jt], ah, b0.x, b1v.x);
                mma_bf16(acc[jt], ah, b0.y, b1v.y);
                mma_bf16(acc[jt], al, b0.x, b1v.x);
            }
            int iA = hm * 16 + mg, iB = iA + 8;
            int riA = iA >> 3, ciA = iA & 7, riB = iB >> 3, ciB = iB & 7;
            int cntA = Cnt[iA], cntB = Cnt[iB];
            #pragma unroll
            for (int jt = 0; jt < 4; jt++) {
                int c = nh * 32 + jt * 8 + 2 * mt;
                #pragma unroll
                for (int e = 0; e < 2; e++) {
                    int j = c + e;
                    int rj = j >> 3, cj = j & 7;
                    int cntJ = Cnt[j];
                    float bA = Tb[((riA - rj + 7) * 15 + (ciA - cj + 7)) * 6 + hd];
                    float bB = Tb[((riB - rj + 7) * 15 + (ciB - cj + 7)) * 6 + hd];
                    if (SHIFTED) {
                        if (cntA != cntJ) bA -= 100.f;
                        if (cntB != cntJ) bB -= 100.f;
                    }
                    float vA = (e == 0) ? acc[jt].x : acc[jt].y;
                    float vB = (e == 0) ? acc[jt].z : acc[jt].w;
                    Sg[iA * 68 + j] = fmaf(vA, 0.25f, bA);
                    Sg[iB * 68 + j] = fmaf(vB, 0.25f, bB);
                }
            }
        }
        __syncthreads();

        // softmax -> split SP
        {
            int row = tid >> 2, l4 = tid & 3;
            int rg = row >> 6, rr = row & 63;
            float* Sr = S + rg * 4352 + rr * 68;
            float4 v[4];
            float mx = -1e30f;
            #pragma unroll
            for (int q = 0; q < 4; q++) {
                v[q] = *(const float4*)&Sr[l4 * 16 + q * 4];
                mx = fmaxf(mx, fmaxf(fmaxf(v[q].x, v[q].y), fmaxf(v[q].z, v[q].w)));
            }
            mx = fmaxf(mx, __shfl_xor_sync(0xffffffffu, mx, 1));
            mx = fmaxf(mx, __shfl_xor_sync(0xffffffffu, mx, 2));
            float ssum = 0.f;
            #pragma unroll
            for (int q = 0; q < 4; q++) {
                v[q].x = fexp(v[q].x - mx); v[q].y = fexp(v[q].y - mx);
                v[q].z = fexp(v[q].z - mx); v[q].w = fexp(v[q].w - mx);
                ssum += (v[q].x + v[q].y) + (v[q].z + v[q].w);
            }
            ssum += __shfl_xor_sync(0xffffffffu, ssum, 1);
            ssum += __shfl_xor_sync(0xffffffffu, ssum, 2);
            float inv = 1.0f / ssum;
            uint4* SP4 = (uint4*)(SP + rg * (64 * 34) + rr * 34 + l4 * 8);
            #pragma unroll
            for (int q = 0; q < 4; q++) {
                uint32_t hA, lA, hB, lB;
                bfsplit2(v[q].x * inv, v[q].y * inv, hA, lA);
                bfsplit2(v[q].z * inv, v[q].w * inv, hB, lB);
                SP4[q] = make_uint4(hA, lA, hB, lB);
            }
        }
        __syncthreads();

        // AV -> split OP
        {
            int nc0 = hd * 16 + nh * 8;
            float4 acc = make_float4(0.f, 0.f, 0.f, 0.f);
            #pragma unroll
            for (int ks = 0; ks < 4; ks++) {
                int spw = (hm * 16 + mg) * 34 + ks * 8 + mt;
                uint2 a0 = SPg[spw],     a1 = SPg[spw + 272];
                uint2 a2 = SPg[spw + 4], a3 = SPg[spw + 276];
                uint32_t ah[4] = {a0.x, a1.x, a2.x, a3.x};
                uint32_t al[4] = {a0.y, a1.y, a2.y, a3.y};
                int vw = (nc0 + mg) * 36 + ks * 8 + mt;
                uint32_t bh0 = VH[vw], bh1 = VH[vw + 4];
                uint32_t bl0 = VL[vw], bl1 = VL[vw + 4];
                mma_bf16(acc, ah, bh0, bh1);
                mma_bf16(acc, ah, bl0, bl1);
                mma_bf16(acc, al, bh0, bh1);
            }
            int rA = hm * 16 + mg, rB = rA + 8;
            int cw = hd * 8 + nh * 4 + mt;
            uint32_t h, l;
            bfsplit2(acc.x, acc.y, h, l); OP[rA * 50 + cw] = make_uint2(h, l);
            bfsplit2(acc.z, acc.w, h, l); OP[rB * 50 + cw] = make_uint2(h, l);
        }
        __syncthreads();
    }

    // ---- proj + residual -> Y fp32 (overlays S) ----
    float* Y = S;
    {
        float4 acc[3];
        #pragma unroll
        for (int j = 0; j < 3; j++) {
            int c = nch * 24 + j * 8 + 2 * mt;
            float b0 = __ldg(&bproj[c]), b1v = __ldg(&bproj[c + 1]);
            acc[j].x = b0; acc[j].y = b1v; acc[j].z = b0; acc[j].w = b1v;
        }
        mma_gemm_pk<3, 6>(acc, OP, 50, m0, WPF, nch * 3, mg, mt, tx);
        __syncthreads();   // logits reads done; S becomes Y
        #pragma unroll
        for (int j = 0; j < 3; j++) {
            int c = nch * 24 + j * 8 + 2 * mt;
            int cw = c / 2;
            int rA = m0 + mg, rB = rA + 8;
            float xA0, xA1, xB0, xB1;
            bfrec2(XP[rA * 50 + cw], xA0, xA1);
            bfrec2(XP[rB * 50 + cw], xB0, xB1);
            Y[rA * QS + c]     = acc[j].x + xA0;
            Y[rA * QS + c + 1] = acc[j].y + xA1;
            Y[rB * QS + c]     = acc[j].z + xB0;
            Y[rB * QS + c + 1] = acc[j].w + xB1;
        }
    }
    __syncthreads();

    // ---- LayerNorm 1: stats then write LN output as split XP (FFN input) ----
    {
        int row = tid >> 3, l8 = tid & 7;
        float s = 0.f, s2 = 0.f;
        #pragma unroll
        for (int q = 0; q < 3; q++) {
            float4 y = *(const float4*)&Y[row * QS + l8 * 12 + q * 4];
            s += (y.x + y.y) + (y.z + y.w);
            s2 = fmaf(y.x, y.x, fmaf(y.y, y.y, fmaf(y.z, y.z, fmaf(y.w, y.w, s2))));
        }
        #pragma unroll
        for (int o = 4; o > 0; o >>= 1) {
            s  += __shfl_xor_sync(0xffffffffu, s,  o);
            s2 += __shfl_xor_sync(0xffffffffu, s2, o);
        }
        if (l8 == 0) {
            float mean = s * (1.0f / 96.0f);
            float var  = fmaf(-mean, mean, s2 * (1.0f / 96.0f));
            stats[row]      = mean;
            stats[64 + row] = rsqrtf(var + 1e-5f);
        }
    }
    __syncthreads();
    for (int idx = tid; idx < 64 * 48; idx += 512) {
        int t = idx / 48, wd = idx - t * 48;
        float mean = stats[t], rstd = stats[64 + t];
        float y0 = (Y[t * QS + 2 * wd]     - mean) * rstd;
        float y1 = (Y[t * QS + 2 * wd + 1] - mean) * rstd;
        y0 = fmaf(y0, __ldg(&gam1[2 * wd]),     __ldg(&beta1[2 * wd]));
        y1 = fmaf(y1, __ldg(&gam1[2 * wd + 1]), __ldg(&beta1[2 * wd + 1]));
        uint32_t hh, ll;
        bfsplit2(y0, y1, hh, ll);
        XP[t * 50 + wd] = make_uint2(hh, ll);
    }
    __syncthreads();

    // ================= FFN =================
    // GEMM1: 64x192x96 + GELU -> HP (overlays QP/KP; dead after heads)
    {
        float4 acc[6];
        #pragma unroll
        for (int j = 0; j < 6; j++) {
            int c = nch * 48 + j * 8 + 2 * mt;
            float v0 = __ldg(&b1[c]), v1 = __ldg(&b1[c + 1]);
            acc[j].x = v0; acc[j].y = v1; acc[j].z = v0; acc[j].w = v1;
        }
        mma_gemm_pk<6, 6>(acc, XP, 50, m0, W1F, nch * 6, mg, mt, tx);
        #pragma unroll
        for (int j = 0; j < 6; j++) {
            int cw = nch * 24 + j * 4 + mt;
            int rA = m0 + mg, rB = rA + 8;
            float g0 = 0.5f * acc[j].x * (1.0f + erff(acc[j].x * 0.70710678118654752f));
            float g1 = 0.5f * acc[j].y * (1.0f + erff(acc[j].y * 0.70710678118654752f));
            float g2 = 0.5f * acc[j].z * (1.0f + erff(acc[j].z * 0.70710678118654752f));
            float g3 = 0.5f * acc[j].w * (1.0f + erff(acc[j].w * 0.70710678118654752f));
            uint32_t h, l;
            bfsplit2(g0, g1, h, l); HP[rA * 98 + cw] = make_uint2(h, l);
            bfsplit2(g2, g3, h, l); HP[rB * 98 + cw] = make_uint2(h, l);
        }
    }
    __syncthreads();

    // GEMM2: 64x96x192 + residual (rec XP) -> Y
    {
        float4 acc[3];
        #pragma unroll
        for (int j = 0; j < 3; j++) {
            int c = nch * 24 + j * 8 + 2 * mt;
            float v0 = __ldg(&b2[c]), v1 = __ldg(&b2[c + 1]);
            acc[j].x = v0; acc[j].y = v1; acc[j].z = v0; acc[j].w = v1;
        }
        mma_gemm_pk<3, 12>(acc, HP, 98, m0, W2F, nch * 3, mg, mt, tx);
        #pragma unroll
        for (int j = 0; j < 3; j++) {
            int c = nch * 24 + j * 8 + 2 * mt;
            int cw = c / 2;
            int rA = m0 + mg, rB = rA + 8;
            float xA0, xA1, xB0, xB1;
            bfrec2(XP[rA * 50 + cw], xA0, xA1);
            bfrec2(XP[rB * 50 + cw], xB0, xB1);
            Y[rA * QS + c]     = acc[j].x + xA0;
            Y[rA * QS + c + 1] = acc[j].y + xA1;
            Y[rB * QS + c]     = acc[j].z + xB0;
            Y[rB * QS + c + 1] = acc[j].w + xB1;
        }
    }
    __syncthreads();

    // ---- LayerNorm 2 + scatter ----
    {
        int row = tid >> 3, l8 = tid & 7;
        float s = 0.f, s2 = 0.f;
        #pragma unroll
        for (int q = 0; q < 3; q++) {
            float4 y = *(const float4*)&Y[row * QS + l8 * 12 + q * 4];
            s += (y.x + y.y) + (y.z + y.w);
            s2 = fmaf(y.x, y.x, fmaf(y.y, y.y, fmaf(y.z, y.z, fmaf(y.w, y.w, s2))));
        }
        #pragma unroll
        for (int o = 4; o > 0; o >>= 1) {
            s  += __shfl_xor_sync(0xffffffffu, s,  o);
            s2 += __shfl_xor_sync(0xffffffffu, s2, o);
        }
        if (l8 == 0) {
            float mean = s * (1.0f / 96.0f);
            float var  = fmaf(-mean, mean, s2 * (1.0f / 96.0f));
            stats[row]      = mean;
            stats[64 + row] = rsqrtf(var + 1e-5f);
        }
    }
    __syncthreads();

    for (int idx = tid; idx < NTOK * CH; idx += 512) {
        int t = idx / CH, c = idx - t * CH;
        int r = t >> 3, cl = t & 7;
        int h = wr * 8 + r, w = wc * 8 + cl;
        if (SHIFTED) { h += 4; if (h >= HH) h -= HH; w += 4; if (w >= WWI) w -= WWI; }
        float yv = (Y[t * QS + c] - stats[t]) * stats[64 + t];
        dst[(h * WWI + w) * CH + c] = fmaf(yv, gam2[c], beta2[c]);
    }
}

// ---------------------------------------------------------------------------
// Input order (setup_inputs dict order):
//   0: x | 1..7: sa1 | 8..14: sa2 | 15..20: ff1 | 21..26: ff2
// ---------------------------------------------------------------------------
extern "C" void kernel_launch(void* const* d_in, const int* in_sizes, int n_in,
                              void* d_out, int out_size) {
    const float* x = (const float*)d_in[0];
    float *imgA, *imgB;
    uint4* wf;
    cudaGetSymbolAddress((void**)&imgA, g_imgA);
    cudaGetSymbolAddress((void**)&imgB, g_imgB);
    cudaGetSymbolAddress((void**)&wf,   g_wfrag);

    cudaFuncSetAttribute(block_kernel<0>, cudaFuncAttributeMaxDynamicSharedMemorySize, BLK_SMEM);
    cudaFuncSetAttribute(block_kernel<1>, cudaFuncAttributeMaxDynamicSharedMemorySize, BLK_SMEM);

    split_all_weights<<<dim3(27, 8), 256>>>(
        (const float*)d_in[1],  (const float*)d_in[4],
        (const float*)d_in[8],  (const float*)d_in[11],
        (const float*)d_in[15], (const float*)d_in[21],
        (const float*)d_in[17], (const float*)d_in[23]);

    dim3 tb(32, 8);
    dim3 tg(HW / 32, CH / 32, BATCH);

    transpose_in_kernel<<<tg, tb>>>(x, imgA);

    block_kernel<0><<<NWIN, 512, BLK_SMEM>>>(
        imgA, imgB, wf + WF_SA1_QKV,
        (const float*)d_in[2], (const float*)d_in[3],
        wf + WF_SA1_PROJ, (const float*)d_in[5],
        (const float*)d_in[6], (const float*)d_in[7],
        wf + WF_FF1_W1, (const float*)d_in[16],
        wf + WF_FF1_W2, (const float*)d_in[18],
        (const float*)d_in[19], (const float*)d_in[20]);

    block_kernel<1><<<NWIN, 512, BLK_SMEM>>>(
        imgB, imgA, wf + WF_SA2_QKV,
        (const float*)d_in[9], (const float*)d_in[10],
        wf + WF_SA2_PROJ, (const float*)d_in[12],
        (const float*)d_in[13], (const float*)d_in[14],
        wf + WF_FF2_W1, (const float*)d_in[22],
        wf + WF_FF2_W2, (const float*)d_in[24],
        (const float*)d_in[25], (const float*)d_in[26]);

    transpose_out_kernel<<<tg, tb>>>(imgA, (float*)d_out);
}